// round 6
// baseline (speedup 1.0000x reference)
#include <cuda_runtime.h>
#include <cuda_bf16.h>
#include <cstdint>

#define BB 32
#define NN 64
#define FF 128
#define KK 4
#define EE 4032

// ---------------- static device scratch (no allocations) ----------------
__device__ __align__(16) unsigned char g_w1img[KK * 2 * 256 * 272];  // 557,056 B
__device__ __align__(16) unsigned char g_w2img[KK * 2 * 256 * 528];  // 1,081,344 B
__device__ __align__(16) uint32_t g_ximg_hi[BB * NN * 64];           // bf16 pairs
__device__ __align__(16) uint32_t g_ximg_lo[BB * NN * 64];
__device__ float g_hbase[KK * BB * NN * 256];                        // 8 MB
__device__ float g_agg[BB * NN * 256];                               // 2 MB

// ---------------- helpers ----------------
__device__ __forceinline__ uint32_t smem_u32(const void* p) {
    uint32_t a;
    asm("{ .reg .u64 t; cvta.to.shared.u64 t, %1; cvt.u32.u64 %0, t; }" : "=r"(a) : "l"(p));
    return a;
}
__device__ __forceinline__ void split2(float2 v, uint32_t& hi, uint32_t& lo) {
    __nv_bfloat162 h2 = __float22bfloat162_rn(v);
    float2 r = make_float2(v.x - __bfloat162float(h2.x), v.y - __bfloat162float(h2.y));
    __nv_bfloat162 l2 = __float22bfloat162_rn(r);
    hi = reinterpret_cast<uint32_t&>(h2);
    lo = reinterpret_cast<uint32_t&>(l2);
}
__device__ __forceinline__ void ldm4(uint32_t addr, uint32_t r[4]) {
    asm volatile("ldmatrix.sync.aligned.m8n8.x4.shared.b16 {%0,%1,%2,%3}, [%4];"
                 : "=r"(r[0]), "=r"(r[1]), "=r"(r[2]), "=r"(r[3]) : "r"(addr));
}
__device__ __forceinline__ void mma_bf16(float* c, const uint32_t* a, uint32_t b0, uint32_t b1) {
    asm volatile(
        "mma.sync.aligned.m16n8k16.row.col.f32.bf16.bf16.f32 "
        "{%0,%1,%2,%3}, {%4,%5,%6,%7}, {%8,%9}, {%0,%1,%2,%3};"
        : "+f"(c[0]), "+f"(c[1]), "+f"(c[2]), "+f"(c[3])
        : "r"(a[0]), "r"(a[1]), "r"(a[2]), "r"(a[3]), "r"(b0), "r"(b1));
}
__device__ __forceinline__ void cpa16(uint32_t dst, const void* src) {
    asm volatile("cp.async.cg.shared.global [%0], [%1], 16;" :: "r"(dst), "l"(src));
}
#define CP_COMMIT() asm volatile("cp.async.commit_group;" ::: "memory")
#define CP_WAIT0()  asm volatile("cp.async.wait_group 0;" ::: "memory")
#define CP_WAIT1()  asm volatile("cp.async.wait_group 1;" ::: "memory")

// ---------------- SMEM map (bytes) for edge kernel ----------------
// X stride 272 (68 words, %32==4 -> conflict-free ldmatrix). W2 stride 528.
#define SM_XHI   0        // 128*272 = 34816
#define SM_XLO   34816    // 34816
#define SM_W1    69632    // 2 bufs x (hi 8704 + lo 8704) = 34816
#define SM_W2    104448   // 2 bufs x (hi 16896 + lo 16896) = 67584
#define SM_HBS   172032   // 2 nodes * 256 f32 = 2048
#define SM_B2S   174080   // 256 f32 = 1024
#define SM_RTS   175104   // 128 rows * 4 f32 = 2048
#define SM_AGG   177152   // 8 * 256 f32 = 8192
#define SM_TOTAL 185344

// =====================================================================
// Prep: weight images [n][f] bf16 hi/lo with padded rows.
// src element (kt, n, f) = W[kt*65536 + (koff+f)*256 + n]
// =====================================================================
__global__ void __launch_bounds__(256)
prep_w_kernel(const float* __restrict__ W, int koff, unsigned char* __restrict__ img, int rstride)
{
    __shared__ float ts[32][33];
    const int f0 = blockIdx.x * 32, nn0 = blockIdx.y * 32, kt = blockIdx.z;
    const int tid = threadIdx.x;
    const float* Wk = W + (size_t)kt * 65536;
#pragma unroll
    for (int p = 0; p < 4; ++p) {
        int fr = (tid >> 5) + p * 8, nl = tid & 31;
        ts[fr][nl] = Wk[(size_t)(koff + f0 + fr) * 256 + nn0 + nl];
    }
    __syncthreads();
#pragma unroll
    for (int p = 0; p < 2; ++p) {
        int idx = tid + p * 256;
        int nr = idx >> 4, wp = idx & 15;
        uint32_t hi, lo;
        split2(make_float2(ts[2 * wp][nr], ts[2 * wp + 1][nr]), hi, lo);
        size_t rb = (size_t)(nn0 + nr) * rstride + (f0 + 2 * wp) * 2;
        *(uint32_t*)(img + (size_t)(kt * 2 + 0) * 256 * rstride + rb) = hi;
        *(uint32_t*)(img + (size_t)(kt * 2 + 1) * 256 * rstride + rb) = lo;
    }
}

// inputs -> bf16 hi/lo images (plain [B][N][F] layout, as 32-bit pairs)
__global__ void __launch_bounds__(256)
prep_x_kernel(const float* __restrict__ inputs, uint32_t* __restrict__ xhi, uint32_t* __restrict__ xlo)
{
    int idx = blockIdx.x * 256 + threadIdx.x;
    float2 v = ((const float2*)inputs)[idx];
    uint32_t hi, lo;
    split2(v, hi, lo);
    xhi[idx] = hi;
    xlo[idx] = lo;
}

// hbase[k][b][n][:] = b1[k] + inputs[b][n] @ W1[k][0:128]   (fp32)
__global__ void __launch_bounds__(256)
hbase_kernel(const float* __restrict__ inputs, const float* __restrict__ W1,
             const float* __restrict__ b1, float* __restrict__ hbase)
{
    __shared__ float xs[32 * FF];
    int k = blockIdx.x, b = blockIdx.y, half = blockIdx.z;
    for (int i = threadIdx.x; i < 32 * FF / 4; i += 256)
        ((float4*)xs)[i] = ((const float4*)(inputs + ((size_t)b * NN + half * 32) * FF))[i];
    __syncthreads();
    int h = threadIdx.x;
    const float* Wk = W1 + (size_t)k * 65536;
    float bias = b1[k * 256 + h];
#pragma unroll 1
    for (int nt = 0; nt < 2; ++nt) {
        float acc[16];
#pragma unroll
        for (int i = 0; i < 16; ++i) acc[i] = bias;
#pragma unroll 4
        for (int f = 0; f < 128; ++f) {
            float w = Wk[(size_t)f * 256 + h];
            const float* xp = xs + (nt * 16) * 128 + f;
#pragma unroll
            for (int i = 0; i < 16; ++i) acc[i] = fmaf(xp[i * 128], w, acc[i]);
        }
#pragma unroll
        for (int i = 0; i < 16; ++i)
            hbase[(((size_t)k * BB + b) * NN + half * 32 + nt * 16 + i) * 256 + h] = acc[i];
    }
}

// =====================================================================
// Edge kernel: block = (node pair, batch), 256 threads = 8 warps.
// Layer-1 output fragments are kept in REGISTERS (bf16 hi/lo) and fed
// directly as A operands of layer 2; weights double-buffered via cp.async.
// =====================================================================
__global__ void __launch_bounds__(256, 1)
edge_kernel(const float* __restrict__ rel_type,
            const unsigned char* __restrict__ w1img, const unsigned char* __restrict__ w2img,
            const uint32_t* __restrict__ ximg_hi, const uint32_t* __restrict__ ximg_lo,
            const float* __restrict__ b2, const float* __restrict__ hbase,
            float* __restrict__ agg)
{
    extern __shared__ char smem[];
    const uint32_t sb = smem_u32(smem);
    const int tid = threadIdx.x;
    const int lane = tid & 31, w = tid >> 5;
    const int n0 = blockIdx.x * 2, b = blockIdx.y;

    // ---- gather X once (sender features hi/lo bf16, row = edge) ----
    for (int t = tid; t < 2048; t += 256) {
        int r = t >> 4, sgi = t & 15;
        int node = n0 + (r >> 6), le = r & 63;
        uint32_t d = r * 272 + sgi * 16;
        if (le < 63) {
            int j = le + (le >= node);
            size_t so = (size_t)(b * 64 + j) * 64 + sgi * 4;
            cpa16(sb + SM_XHI + d, ximg_hi + so);
            cpa16(sb + SM_XLO + d, ximg_lo + so);
        } else {
            float4 z = make_float4(0.f, 0.f, 0.f, 0.f);
            *(float4*)(smem + SM_XHI + d) = z;
            *(float4*)(smem + SM_XLO + d) = z;
        }
    }
    CP_COMMIT();

    if (tid < 128) {   // rel_type tile [128 rows][4]
        int node = n0 + (tid >> 6), le = tid & 63;
        float4 v = make_float4(0.f, 0.f, 0.f, 0.f);
        if (le < 63) v = *(const float4*)(rel_type + ((size_t)b * EE + node * 63 + le) * KK);
        *(float4*)(smem + SM_RTS + tid * 16) = v;
    }
    for (int i = tid; i < 2048; i += 256) ((float*)(smem + SM_AGG))[i] = 0.f;

    // lane geometry
    const int g = lane >> 2, tg = lane & 3;
    const int arow = lane & 15;
    const uint32_t aoff = (uint32_t)((lane >> 4) << 4);
    const int brow = (lane & 7) + ((lane >> 4) << 3);
    const uint32_t boff = (uint32_t)((lane & 8) << 1);
    const int m0 = w * 16;
    const float* hbp = (const float*)(smem + SM_HBS) + (w >> 2) * 256;
    const float* rts = (const float*)(smem + SM_RTS);
    const float* b2s = (const float*)(smem + SM_B2S);
    float* aggS = (float*)(smem + SM_AGG);

    uint32_t Hhi[64], Hlo[64];   // 16 rows x 256 h per warp, bf16x2 fragments

#pragma unroll 1
    for (int k = 0; k < KK; ++k) {
        // stage hbase rows (2 nodes) + b2 for this k
        if (tid < 128)
            ((float4*)(smem + SM_HBS))[tid] =
                ((const float4*)(hbase + (((size_t)k * BB + b) * NN + n0) * 256))[tid];
        else if (tid < 192)
            ((float4*)(smem + SM_B2S))[tid - 128] = ((const float4*)(b2 + k * 256))[tid - 128];

        // ================= layer 1: 8 slabs of 32 h-cols =================
        for (int t = tid; t < 1088; t += 256) {        // prefetch slab 0
            int im = t >= 544;
            uint32_t off = (uint32_t)(t - im * 544) * 16;
            cpa16(sb + SM_W1 + (im ? 8704 : 0) + off,
                  w1img + (size_t)((k * 2 + im) * 256) * 272 + off);
        }
        CP_COMMIT();
#pragma unroll
        for (int s = 0; s < 8; ++s) {
            if (s < 7) {
                uint32_t wb = SM_W1 + (uint32_t)(((s + 1) & 1) * 17408);
                for (int t = tid; t < 1088; t += 256) {
                    int im = t >= 544;
                    uint32_t off = (uint32_t)(t - im * 544) * 16;
                    cpa16(sb + wb + (im ? 8704 : 0) + off,
                          w1img + (size_t)((k * 2 + im) * 256 + (s + 1) * 32) * 272 + off);
                }
                CP_COMMIT();
                CP_WAIT1();
            } else {
                CP_WAIT0();
            }
            __syncthreads();
            const uint32_t wb = sb + SM_W1 + (uint32_t)((s & 1) * 17408);
            float c[4][4] = {};
#pragma unroll
            for (int sp = 0; sp < 3; ++sp) {
                uint32_t Ab = sb + (sp == 2 ? SM_XLO : SM_XHI) + (m0 + arow) * 272 + aoff;
                uint32_t Bb = wb + (sp == 1 ? 8704u : 0u) + brow * 272 + boff;
#pragma unroll
                for (int ks = 0; ks < 8; ++ks) {
                    uint32_t a[4], b0[4], b1[4];
                    ldm4(Ab + ks * 32, a);
                    ldm4(Bb + ks * 32, b0);
                    ldm4(Bb + 16 * 272 + ks * 32, b1);
                    mma_bf16(c[0], a, b0[0], b0[1]);
                    mma_bf16(c[1], a, b0[2], b0[3]);
                    mma_bf16(c[2], a, b1[0], b1[1]);
                    mma_bf16(c[3], a, b1[2], b1[3]);
                }
            }
            // epilogue: relu(D + hbase) -> H fragments in registers
#pragma unroll
            for (int t = 0; t < 4; ++t) {
                int col = s * 32 + t * 8 + 2 * tg;
                float v00 = fmaxf(c[t][0] + hbp[col], 0.f);
                float v01 = fmaxf(c[t][1] + hbp[col + 1], 0.f);
                float v10 = fmaxf(c[t][2] + hbp[col], 0.f);
                float v11 = fmaxf(c[t][3] + hbp[col + 1], 0.f);
                split2(make_float2(v00, v01), Hhi[s * 8 + 2 * t], Hlo[s * 8 + 2 * t]);
                split2(make_float2(v10, v11), Hhi[s * 8 + 2 * t + 1], Hlo[s * 8 + 2 * t + 1]);
            }
            __syncthreads();
        }

        // ================= layer 2: 8 slabs of 32 m-cols =================
        for (int t = tid; t < 2112; t += 256) {        // prefetch slab 0
            int im = t >= 1056;
            uint32_t off = (uint32_t)(t - im * 1056) * 16;
            cpa16(sb + SM_W2 + (im ? 16896 : 0) + off,
                  w2img + (size_t)((k * 2 + im) * 256) * 528 + off);
        }
        CP_COMMIT();
        const float wr0 = rts[(m0 + g) * 4 + k], wr1 = rts[(m0 + g + 8) * 4 + k];
#pragma unroll
        for (int s = 0; s < 8; ++s) {
            if (s < 7) {
                uint32_t wb = SM_W2 + (uint32_t)(((s + 1) & 1) * 33792);
                for (int t = tid; t < 2112; t += 256) {
                    int im = t >= 1056;
                    uint32_t off = (uint32_t)(t - im * 1056) * 16;
                    cpa16(sb + wb + (im ? 16896 : 0) + off,
                          w2img + (size_t)((k * 2 + im) * 256 + (s + 1) * 32) * 528 + off);
                }
                CP_COMMIT();
                CP_WAIT1();
            } else {
                CP_WAIT0();
            }
            __syncthreads();
            const uint32_t wb = sb + SM_W2 + (uint32_t)((s & 1) * 33792);
            float c2[4][4] = {};
#pragma unroll
            for (int sp = 0; sp < 3; ++sp) {
                uint32_t Bb = wb + (sp == 1 ? 16896u : 0u) + brow * 528 + boff;
#pragma unroll
                for (int ks = 0; ks < 16; ++ks) {
                    uint32_t a[4];
                    if (sp == 2) {
                        a[0] = Hlo[ks * 4]; a[1] = Hlo[ks * 4 + 1];
                        a[2] = Hlo[ks * 4 + 2]; a[3] = Hlo[ks * 4 + 3];
                    } else {
                        a[0] = Hhi[ks * 4]; a[1] = Hhi[ks * 4 + 1];
                        a[2] = Hhi[ks * 4 + 2]; a[3] = Hhi[ks * 4 + 3];
                    }
                    uint32_t b0[4], b1[4];
                    ldm4(Bb + ks * 32, b0);
                    ldm4(Bb + 16 * 528 + ks * 32, b1);
                    mma_bf16(c2[0], a, b0[0], b0[1]);
                    mma_bf16(c2[1], a, b0[2], b0[3]);
                    mma_bf16(c2[2], a, b1[0], b1[1]);
                    mma_bf16(c2[3], a, b1[2], b1[3]);
                }
            }
            // epilogue: relu(D+b2) * rel_type, reduce over this warp's 16 rows
            float p0[4], p1[4];
#pragma unroll
            for (int t = 0; t < 4; ++t) {
                int col = s * 32 + t * 8 + 2 * tg;
                p0[t] = wr0 * fmaxf(c2[t][0] + b2s[col], 0.f)
                      + wr1 * fmaxf(c2[t][2] + b2s[col], 0.f);
                p1[t] = wr0 * fmaxf(c2[t][1] + b2s[col + 1], 0.f)
                      + wr1 * fmaxf(c2[t][3] + b2s[col + 1], 0.f);
            }
#pragma unroll
            for (int off = 4; off <= 16; off <<= 1)
#pragma unroll
                for (int t = 0; t < 4; ++t) {
                    p0[t] += __shfl_xor_sync(0xffffffff, p0[t], off);
                    p1[t] += __shfl_xor_sync(0xffffffff, p1[t], off);
                }
            if (g == 0) {
#pragma unroll
                for (int t = 0; t < 4; ++t) {
                    int col = s * 32 + t * 8 + 2 * tg;
                    aggS[w * 256 + col]     += p0[t];
                    aggS[w * 256 + col + 1] += p1[t];
                }
            }
            __syncthreads();
        }
    }

    // final reduce: node0 = warps 0-3, node1 = warps 4-7
    {
        for (int t = tid; t < 512; t += 256) {
            int ni = t >> 8, m = t & 255;
            float sum = aggS[(ni * 4 + 0) * 256 + m] + aggS[(ni * 4 + 1) * 256 + m]
                      + aggS[(ni * 4 + 2) * 256 + m] + aggS[(ni * 4 + 3) * 256 + m];
            agg[((size_t)b * NN + n0 + ni) * 256 + m] = sum;
        }
    }
}

// =====================================================================
// Output MLP 384->256->256->128 + residual (fp32 f32x2), 16 rows/block.
// =====================================================================
#define AUGSTR 388
#define P1STR 260
__device__ __forceinline__ unsigned long long pack2(float x) {
    unsigned long long r; asm("mov.b64 %0, {%1, %1};" : "=l"(r) : "f"(x)); return r;
}
__device__ __forceinline__ unsigned long long packab(float a, float b) {
    unsigned long long r; asm("mov.b64 %0, {%1, %2};" : "=l"(r) : "f"(a), "f"(b)); return r;
}
__device__ __forceinline__ void unpack2(unsigned long long v, float& a, float& b) {
    asm("mov.b64 {%0, %1}, %2;" : "=f"(a), "=f"(b) : "l"(v));
}
__device__ __forceinline__ unsigned long long fma2(unsigned long long a,
                                                   unsigned long long b,
                                                   unsigned long long c) {
    unsigned long long d;
    asm("fma.rn.f32x2 %0, %1, %2, %3;" : "=l"(d) : "l"(a), "l"(b), "l"(c));
    return d;
}

__global__ void __launch_bounds__(128)
out_mlp_kernel(const float* __restrict__ inputs, const float* __restrict__ agg,
               const float* __restrict__ Wo1, const float* __restrict__ bo1,
               const float* __restrict__ Wo2, const float* __restrict__ bo2,
               const float* __restrict__ Wo3, const float* __restrict__ bo3,
               float* __restrict__ out)
{
    extern __shared__ float sm[];
    float* augS = sm;
    float* p1S  = augS + 16 * AUGSTR;
    float* Wc   = p1S + 16 * P1STR;

    const int qtr = blockIdx.x, b = blockIdx.y;
    const int r0 = qtr * 16, tid = threadIdx.x;
    const int cg = tid & 31, er = tid >> 5, col0 = cg << 3;

    for (int idx = tid; idx < 16 * 96; idx += 128) {
        int r = idx / 96, c4 = idx % 96;
        float4 v;
        if (c4 < 32) v = *(const float4*)(inputs + ((size_t)(b * NN) + r0 + r) * FF + (c4 << 2));
        else         v = *(const float4*)(agg + ((size_t)(b * NN) + r0 + r) * 256 + ((c4 - 32) << 2));
        *(float4*)(augS + r * AUGSTR + (c4 << 2)) = v;
    }

    unsigned long long acc[4][4];
    {
        float4 t0 = *(const float4*)(bo1 + col0);
        float4 t1 = *(const float4*)(bo1 + col0 + 4);
        unsigned long long c0 = packab(t0.x, t0.y), c1 = packab(t0.z, t0.w);
        unsigned long long c2 = packab(t1.x, t1.y), c3 = packab(t1.z, t1.w);
#pragma unroll
        for (int i = 0; i < 4; ++i) { acc[i][0]=c0; acc[i][1]=c1; acc[i][2]=c2; acc[i][3]=c3; }
    }
#pragma unroll 1
    for (int fc = 0; fc < 12; ++fc) {
        __syncthreads();
        const float* wsrc = Wo1 + fc * 32 * 256;
        for (int idx = tid; idx < 32 * 64; idx += 128)
            *(float4*)(Wc + ((idx >> 6) << 8) + ((idx & 63) << 2)) =
                *(const float4*)(wsrc + ((idx >> 6) << 8) + ((idx & 63) << 2));
        __syncthreads();
#pragma unroll 8
        for (int f = 0; f < 32; ++f) {
            const float* wrow = Wc + (f << 8) + col0;
            ulonglong2 wA = *(const ulonglong2*)(wrow);
            ulonglong2 wB = *(const ulonglong2*)(wrow + 4);
#pragma unroll
            for (int i = 0; i < 4; ++i) {
                unsigned long long xp = pack2(augS[(er * 4 + i) * AUGSTR + fc * 32 + f]);
                acc[i][0] = fma2(xp, wA.x, acc[i][0]); acc[i][1] = fma2(xp, wA.y, acc[i][1]);
                acc[i][2] = fma2(xp, wB.x, acc[i][2]); acc[i][3] = fma2(xp, wB.y, acc[i][3]);
            }
        }
    }
#pragma unroll
    for (int i = 0; i < 4; ++i) {
        float4 v0, v1;
        unpack2(acc[i][0], v0.x, v0.y); unpack2(acc[i][1], v0.z, v0.w);
        unpack2(acc[i][2], v1.x, v1.y); unpack2(acc[i][3], v1.z, v1.w);
        v0.x=fmaxf(v0.x,0.f); v0.y=fmaxf(v0.y,0.f); v0.z=fmaxf(v0.z,0.f); v0.w=fmaxf(v0.w,0.f);
        v1.x=fmaxf(v1.x,0.f); v1.y=fmaxf(v1.y,0.f); v1.z=fmaxf(v1.z,0.f); v1.w=fmaxf(v1.w,0.f);
        *(float4*)(p1S + (er * 4 + i) * P1STR + col0)     = v0;
        *(float4*)(p1S + (er * 4 + i) * P1STR + col0 + 4) = v1;
    }

    {
        float4 t0 = *(const float4*)(bo2 + col0);
        float4 t1 = *(const float4*)(bo2 + col0 + 4);
        unsigned long long c0 = packab(t0.x, t0.y), c1 = packab(t0.z, t0.w);
        unsigned long long c2 = packab(t1.x, t1.y), c3 = packab(t1.z, t1.w);
#pragma unroll
        for (int i = 0; i < 4; ++i) { acc[i][0]=c0; acc[i][1]=c1; acc[i][2]=c2; acc[i][3]=c3; }
    }
#pragma unroll 1
    for (int fc = 0; fc < 8; ++fc) {
        __syncthreads();
        const float* wsrc = Wo2 + fc * 32 * 256;
        for (int idx = tid; idx < 32 * 64; idx += 128)
            *(float4*)(Wc + ((idx >> 6) << 8) + ((idx & 63) << 2)) =
                *(const float4*)(wsrc + ((idx >> 6) << 8) + ((idx & 63) << 2));
        __syncthreads();
#pragma unroll 8
        for (int f = 0; f < 32; ++f) {
            const float* wrow = Wc + (f << 8) + col0;
            ulonglong2 wA = *(const ulonglong2*)(wrow);
            ulonglong2 wB = *(const ulonglong2*)(wrow + 4);
#pragma unroll
            for (int i = 0; i < 4; ++i) {
                unsigned long long xp = pack2(p1S[(er * 4 + i) * P1STR + fc * 32 + f]);
                acc[i][0] = fma2(xp, wA.x, acc[i][0]); acc[i][1] = fma2(xp, wA.y, acc[i][1]);
                acc[i][2] = fma2(xp, wB.x, acc[i][2]); acc[i][3] = fma2(xp, wB.y, acc[i][3]);
            }
        }
    }
    __syncthreads();
#pragma unroll
    for (int i = 0; i < 4; ++i) {
        float4 v0, v1;
        unpack2(acc[i][0], v0.x, v0.y); unpack2(acc[i][1], v0.z, v0.w);
        unpack2(acc[i][2], v1.x, v1.y); unpack2(acc[i][3], v1.z, v1.w);
        v0.x=fmaxf(v0.x,0.f); v0.y=fmaxf(v0.y,0.f); v0.z=fmaxf(v0.z,0.f); v0.w=fmaxf(v0.w,0.f);
        v1.x=fmaxf(v1.x,0.f); v1.y=fmaxf(v1.y,0.f); v1.z=fmaxf(v1.z,0.f); v1.w=fmaxf(v1.w,0.f);
        *(float4*)(augS + (er * 4 + i) * AUGSTR + col0)     = v0;
        *(float4*)(augS + (er * 4 + i) * AUGSTR + col0 + 4) = v1;
    }

    unsigned long long a3[4][2];
    {
        float4 tb4 = *(const float4*)(bo3 + (cg << 2));
        unsigned long long c0 = packab(tb4.x, tb4.y), c1 = packab(tb4.z, tb4.w);
#pragma unroll
        for (int i = 0; i < 4; ++i) { a3[i][0] = c0; a3[i][1] = c1; }
    }
#pragma unroll 1
    for (int fc = 0; fc < 8; ++fc) {
        __syncthreads();
        const float* wsrc = Wo3 + fc * 32 * 128;
        for (int idx = tid; idx < 32 * 32; idx += 128)
            *(float4*)(Wc + ((idx >> 5) << 7) + ((idx & 31) << 2)) =
                *(const float4*)(wsrc + ((idx >> 5) << 7) + ((idx & 31) << 2));
        __syncthreads();
#pragma unroll 8
        for (int f = 0; f < 32; ++f) {
            const float* wrow = Wc + (f << 7) + (cg << 2);
            ulonglong2 wA = *(const ulonglong2*)(wrow);
#pragma unroll
            for (int i = 0; i < 4; ++i) {
                unsigned long long xp = pack2(augS[(er * 4 + i) * AUGSTR + fc * 32 + f]);
                a3[i][0] = fma2(xp, wA.x, a3[i][0]); a3[i][1] = fma2(xp, wA.y, a3[i][1]);
            }
        }
    }
#pragma unroll
    for (int i = 0; i < 4; ++i) {
        int r = r0 + er * 4 + i;
        float4 res = *(const float4*)(inputs + ((size_t)(b * NN) + r) * FF + (cg << 2));
        float x0, x1;
        unpack2(a3[i][0], x0, x1); res.x += x0; res.y += x1;
        unpack2(a3[i][1], x0, x1); res.z += x0; res.w += x1;
        *(float4*)(out + ((size_t)(b * NN) + r) * FF + (cg << 2)) = res;
    }
}

// =====================================================================
extern "C" void kernel_launch(void* const* d_in, const int* in_sizes, int n_in,
                              void* d_out, int out_size)
{
    const float* inputs   = (const float*)d_in[0];
    const float* rel_type = (const float*)d_in[1];
    const float* W1  = (const float*)d_in[4];
    const float* b1  = (const float*)d_in[5];
    const float* W2  = (const float*)d_in[6];
    const float* b2  = (const float*)d_in[7];
    const float* Wo1 = (const float*)d_in[8];
    const float* bo1 = (const float*)d_in[9];
    const float* Wo2 = (const float*)d_in[10];
    const float* bo2 = (const float*)d_in[11];
    const float* Wo3 = (const float*)d_in[12];
    const float* bo3 = (const float*)d_in[13];
    float* out = (float*)d_out;

    float *agg, *hb;
    unsigned char *w1i, *w2i;
    uint32_t *xhi, *xlo;
    cudaGetSymbolAddress((void**)&agg, g_agg);
    cudaGetSymbolAddress((void**)&hb, g_hbase);
    cudaGetSymbolAddress((void**)&w1i, g_w1img);
    cudaGetSymbolAddress((void**)&w2i, g_w2img);
    cudaGetSymbolAddress((void**)&xhi, g_ximg_hi);
    cudaGetSymbolAddress((void**)&xlo, g_ximg_lo);

    const int smemB = (16 * AUGSTR + 16 * P1STR + 32 * 256) * 4;  // 74240
    cudaFuncSetAttribute(edge_kernel, cudaFuncAttributeMaxDynamicSharedMemorySize, SM_TOTAL);
    cudaFuncSetAttribute(out_mlp_kernel, cudaFuncAttributeMaxDynamicSharedMemorySize, smemB);

    prep_x_kernel<<<BB * NN * 64 / 256, 256>>>(inputs, xhi, xlo);
    prep_w_kernel<<<dim3(4, 8, 4), 256>>>(W1, 128, w1i, 272);   // sender half of W1
    prep_w_kernel<<<dim3(8, 8, 4), 256>>>(W2, 0, w2i, 528);
    hbase_kernel<<<dim3(KK, BB, 2), 256>>>(inputs, W1, b1, hb);
    edge_kernel<<<dim3(NN / 2, BB), 256, SM_TOTAL>>>(rel_type, w1i, w2i, xhi, xlo, b2, hb, agg);
    out_mlp_kernel<<<dim3(4, BB), 128, smemB>>>(inputs, agg, Wo1, bo1, Wo2, bo2, Wo3, bo3, out);
}

// round 7
// speedup vs baseline: 1.3649x; 1.3649x over previous
#include <cuda_runtime.h>
#include <cuda_bf16.h>
#include <cstdint>

#define BB 32
#define NN 64
#define FF 128
#define KK 4
#define EE 4032

// ---------------- static device scratch (no allocations) ----------------
__device__ __align__(16) unsigned char g_w1r[KK * 2 * 256 * 272];   // W1 recv half image
__device__ __align__(16) unsigned char g_w1s[KK * 2 * 256 * 272];   // W1 send half image
__device__ __align__(16) unsigned char g_w2img[KK * 2 * 256 * 528]; // W2 image
__device__ __align__(16) uint32_t g_ximg_hi[BB * NN * 64];          // node feats bf16 pairs
__device__ __align__(16) uint32_t g_ximg_lo[BB * NN * 64];
__device__ __align__(16) float g_ns[KK * BB * NN * 512];            // [k][b][node][512]: hbase|S (16 MB)
__device__ float g_agg[BB * NN * 256];                              // 2 MB

// ---------------- helpers ----------------
__device__ __forceinline__ uint32_t smem_u32(const void* p) {
    uint32_t a;
    asm("{ .reg .u64 t; cvta.to.shared.u64 t, %1; cvt.u32.u64 %0, t; }" : "=r"(a) : "l"(p));
    return a;
}
__device__ __forceinline__ void split2(float2 v, uint32_t& hi, uint32_t& lo) {
    __nv_bfloat162 h2 = __float22bfloat162_rn(v);
    float2 r = make_float2(v.x - __bfloat162float(h2.x), v.y - __bfloat162float(h2.y));
    __nv_bfloat162 l2 = __float22bfloat162_rn(r);
    hi = reinterpret_cast<uint32_t&>(h2);
    lo = reinterpret_cast<uint32_t&>(l2);
}
__device__ __forceinline__ void ldm4(uint32_t addr, uint32_t r[4]) {
    asm volatile("ldmatrix.sync.aligned.m8n8.x4.shared.b16 {%0,%1,%2,%3}, [%4];"
                 : "=r"(r[0]), "=r"(r[1]), "=r"(r[2]), "=r"(r[3]) : "r"(addr));
}
__device__ __forceinline__ void mma_bf16(float* c, const uint32_t* a, uint32_t b0, uint32_t b1) {
    asm volatile(
        "mma.sync.aligned.m16n8k16.row.col.f32.bf16.bf16.f32 "
        "{%0,%1,%2,%3}, {%4,%5,%6,%7}, {%8,%9}, {%0,%1,%2,%3};"
        : "+f"(c[0]), "+f"(c[1]), "+f"(c[2]), "+f"(c[3])
        : "r"(a[0]), "r"(a[1]), "r"(a[2]), "r"(a[3]), "r"(b0), "r"(b1));
}
__device__ __forceinline__ void cpa16(uint32_t dst, const void* src) {
    asm volatile("cp.async.cg.shared.global [%0], [%1], 16;" :: "r"(dst), "l"(src));
}
#define CP_COMMIT() asm volatile("cp.async.commit_group;" ::: "memory")
#define CP_WAIT0()  asm volatile("cp.async.wait_group 0;" ::: "memory")
#define CP_WAIT1()  asm volatile("cp.async.wait_group 1;" ::: "memory")

// =====================================================================
// Prep: weight images [n][f] bf16 hi/lo with padded rows.
// src element (kt, n, f) = W[kt*65536 + (koff+f)*256 + n]
// =====================================================================
__global__ void __launch_bounds__(256)
prep_w_kernel(const float* __restrict__ W, int koff, unsigned char* __restrict__ img, int rstride)
{
    __shared__ float ts[32][33];
    const int f0 = blockIdx.x * 32, nn0 = blockIdx.y * 32, kt = blockIdx.z;
    const int tid = threadIdx.x;
    const float* Wk = W + (size_t)kt * 65536;
#pragma unroll
    for (int p = 0; p < 4; ++p) {
        int fr = (tid >> 5) + p * 8, nl = tid & 31;
        ts[fr][nl] = Wk[(size_t)(koff + f0 + fr) * 256 + nn0 + nl];
    }
    __syncthreads();
#pragma unroll
    for (int p = 0; p < 2; ++p) {
        int idx = tid + p * 256;
        int nr = idx >> 4, wp = idx & 15;
        uint32_t hi, lo;
        split2(make_float2(ts[2 * wp][nr], ts[2 * wp + 1][nr]), hi, lo);
        size_t rb = (size_t)(nn0 + nr) * rstride + (f0 + 2 * wp) * 2;
        *(uint32_t*)(img + (size_t)(kt * 2 + 0) * 256 * rstride + rb) = hi;
        *(uint32_t*)(img + (size_t)(kt * 2 + 1) * 256 * rstride + rb) = lo;
    }
}

// inputs -> bf16 hi/lo images
__global__ void __launch_bounds__(256)
prep_x_kernel(const float* __restrict__ inputs, uint32_t* __restrict__ xhi, uint32_t* __restrict__ xlo)
{
    int idx = blockIdx.x * 256 + threadIdx.x;
    float2 v = ((const float2*)inputs)[idx];
    uint32_t hi, lo;
    split2(v, hi, lo);
    xhi[idx] = hi;
    xlo[idx] = lo;
}

// =====================================================================
// ns_kernel: per (k,b) node GEMM [64x128]@[128x512] (3-split bf16 mma).
// out cols 0:256 = x@W1_recv + b1 (hbase); cols 256:512 = x@W1_send (S).
// =====================================================================
#define NS_XHI 0
#define NS_XLO 17408
#define NS_W   34816      // single buffer: hi 17408 + lo 17408
#define NS_B1  69632      // 256 f32
#define NS_TOTAL 70656

__global__ void __launch_bounds__(256)
ns_kernel(const uint32_t* __restrict__ xhi, const uint32_t* __restrict__ xlo,
          const unsigned char* __restrict__ w1r, const unsigned char* __restrict__ w1s,
          const float* __restrict__ b1, float* __restrict__ ns)
{
    extern __shared__ char smem[];
    const uint32_t sb = smem_u32(smem);
    const int tid = threadIdx.x, lane = tid & 31, w = tid >> 5;
    const int k = blockIdx.x, b = blockIdx.y;

    // load node features (64 rows, hi/lo)
    for (int t = tid; t < 1024; t += 256) {
        int row = t >> 4, sgi = t & 15;
        size_t so = (size_t)(b * 64 + row) * 64 + sgi * 4;
        cpa16(sb + NS_XHI + row * 272 + sgi * 16, xhi + so);
        cpa16(sb + NS_XLO + row * 272 + sgi * 16, xlo + so);
    }
    CP_COMMIT();
    if (tid < 64) ((float4*)(smem + NS_B1))[tid] = ((const float4*)(b1 + k * 256))[tid];

    const int g = lane >> 2, tg = lane & 3;
    const int arow = lane & 15;
    const uint32_t aoff = (uint32_t)((lane >> 4) << 4);
    const int brow = (lane & 7) + ((lane >> 4) << 3);
    const uint32_t boff = (uint32_t)((lane & 8) << 1);
    const int wm = w & 3, wn = w >> 2;
    const int m0 = wm * 16;
    const float* b1s = (const float*)(smem + NS_B1);
    float* outk = ns + ((size_t)k * BB + b) * 64 * 512;

#pragma unroll 1
    for (int half = 0; half < 2; ++half) {
        const unsigned char* img = half ? w1s : w1r;
#pragma unroll 1
        for (int s = 0; s < 4; ++s) {
            for (int t = tid; t < 2176; t += 256) {
                int im = t >= 1088;
                uint32_t off = (uint32_t)(t - im * 1088) * 16;
                cpa16(sb + NS_W + (im ? 17408 : 0) + off,
                      img + (size_t)((k * 2 + im) * 256 + s * 64) * 272 + off);
            }
            CP_COMMIT(); CP_WAIT0();
            __syncthreads();
            float c[4][4] = {};
#pragma unroll
            for (int sp = 0; sp < 3; ++sp) {
                uint32_t Ab = sb + (sp == 2 ? NS_XLO : NS_XHI) + (m0 + arow) * 272 + aoff;
                uint32_t Bb = sb + NS_W + (sp == 1 ? 17408u : 0u) + (wn * 32 + brow) * 272 + boff;
#pragma unroll
                for (int ks = 0; ks < 8; ++ks) {
                    uint32_t a[4], b0[4], b1f[4];
                    ldm4(Ab + ks * 32, a);
                    ldm4(Bb + ks * 32, b0);
                    ldm4(Bb + 16 * 272 + ks * 32, b1f);
                    mma_bf16(c[0], a, b0[0], b0[1]);
                    mma_bf16(c[1], a, b0[2], b0[3]);
                    mma_bf16(c[2], a, b1f[0], b1f[1]);
                    mma_bf16(c[3], a, b1f[2], b1f[3]);
                }
            }
            int r0 = m0 + g, r1 = r0 + 8;
            int cn = s * 64 + wn * 32;
#pragma unroll
            for (int t = 0; t < 4; ++t) {
                int col = cn + t * 8 + 2 * tg;
                float a0 = half ? 0.f : b1s[col], a1 = half ? 0.f : b1s[col + 1];
                outk[(size_t)r0 * 512 + half * 256 + col]     = c[t][0] + a0;
                outk[(size_t)r0 * 512 + half * 256 + col + 1] = c[t][1] + a1;
                outk[(size_t)r1 * 512 + half * 256 + col]     = c[t][2] + a0;
                outk[(size_t)r1 * 512 + half * 256 + col + 1] = c[t][3] + a1;
            }
            __syncthreads();   // retire W reads before next slab overwrites
        }
    }
}

// ---------------- SMEM map (bytes) for edge kernel ----------------
#define SE_S    0         // 64 rows x 1040 B (260 f32) = 66560
#define SE_W2   66560     // 2 bufs x (hi 16896 + lo 16896) = 67584
#define SE_HBS  134144    // 2 nodes x 256 f32 = 2048
#define SE_B2S  136192    // 1024
#define SE_RTS  137216    // 128 x 4 f32 = 2048
#define SE_AGG  139264    // 8 x 256 f32 = 8192
#define SE_TOTAL 147456

// =====================================================================
// Edge kernel: block = (node pair, batch), 256 threads = 8 warps.
// Layer 1 = elementwise relu(hbase[recv] + S[send]) -> register A fragments.
// Layer 2 = 3-split bf16 mma, double-buffered W2 slabs.
// =====================================================================
__global__ void __launch_bounds__(256, 1)
edge_kernel(const float* __restrict__ rel_type,
            const unsigned char* __restrict__ w2img,
            const float* __restrict__ ns,
            const float* __restrict__ b2,
            float* __restrict__ agg)
{
    extern __shared__ char smem[];
    const uint32_t sb = smem_u32(smem);
    const int tid = threadIdx.x;
    const int lane = tid & 31, w = tid >> 5;
    const int n0 = blockIdx.x * 2, b = blockIdx.y;

    if (tid < 128) {   // rel_type tile [128 rows][4]
        int node = n0 + (tid >> 6), le = tid & 63;
        float4 v = make_float4(0.f, 0.f, 0.f, 0.f);
        if (le < 63) v = *(const float4*)(rel_type + ((size_t)b * EE + node * 63 + le) * KK);
        *(float4*)(smem + SE_RTS + tid * 16) = v;
    }
    for (int i = tid; i < 2048; i += 256) ((float*)(smem + SE_AGG))[i] = 0.f;

    // lane geometry
    const int g = lane >> 2, tg = lane & 3;
    const int brow = (lane & 7) + ((lane >> 4) << 3);
    const uint32_t boff = (uint32_t)((lane & 8) << 1);
    const int m0 = w * 16;
    const int nodeg = n0 + (w >> 2);       // this warp's receiver node
    const float* rts = (const float*)(smem + SE_RTS);
    const float* b2s = (const float*)(smem + SE_B2S);
    float* aggS = (float*)(smem + SE_AGG);

    // per-lane edge-row indices (fixed across k)
    const int r0 = m0 + g, r1 = r0 + 8;
    const int le0 = r0 & 63, le1 = r1 & 63;
    const float msk0 = (le0 != 63) ? 1.f : 0.f;
    const float msk1 = (le1 != 63) ? 1.f : 0.f;
    const int j0 = (le0 != 63) ? (le0 + (le0 >= nodeg)) : 0;
    const int j1 = (le1 != 63) ? (le1 + (le1 >= nodeg)) : 0;

    uint32_t Hhi[64], Hlo[64];

#pragma unroll 1
    for (int k = 0; k < KK; ++k) {
        __syncthreads();   // prior k: W2/aggS/S consumers done

        const float* nsk = ns + ((size_t)k * BB + b) * 64 * 512;
        // S rows (all 64 senders, cols 256:512) via cp.async
        for (int t = tid; t < 4096; t += 256) {
            int row = t >> 6, ch = t & 63;
            cpa16(sb + SE_S + row * 1040 + ch * 16, nsk + (size_t)row * 512 + 256 + ch * 4);
        }
        CP_COMMIT();
        // prefetch W2 slab 0
        for (int t = tid; t < 2112; t += 256) {
            int im = t >= 1056;
            uint32_t off = (uint32_t)(t - im * 1056) * 16;
            cpa16(sb + SE_W2 + (im ? 16896 : 0) + off,
                  w2img + (size_t)((k * 2 + im) * 256) * 272 * 0 + (size_t)((k * 2 + im) * 256) * 528 + off);
        }
        CP_COMMIT();
        // hbase rows for the 2 receiver nodes + b2
        if (tid < 128) {
            int row = n0 + (tid >> 6), c4 = (tid & 63) * 4;
            *(float4*)(smem + SE_HBS + tid * 16) = *(const float4*)(nsk + (size_t)row * 512 + c4);
        } else if (tid < 192) {
            ((float4*)(smem + SE_B2S))[tid - 128] = ((const float4*)(b2 + k * 256))[tid - 128];
        }
        CP_WAIT1();        // S complete (W2 slab0 may still be in flight)
        __syncthreads();

        // ---- build H fragments: relu(hbase + S) ----
        {
            const float* S0 = (const float*)(smem + SE_S) + j0 * 260;
            const float* S1 = (const float*)(smem + SE_S) + j1 * 260;
            const float* hb = (const float*)(smem + SE_HBS) + (w >> 2) * 256;
#pragma unroll
            for (int ks = 0; ks < 16; ++ks) {
                int c = ks * 16 + 2 * tg;
                float2 h0 = *(const float2*)(hb + c);
                float2 h8 = *(const float2*)(hb + c + 8);
                float2 s00 = *(const float2*)(S0 + c);
                float2 s08 = *(const float2*)(S0 + c + 8);
                float2 s10 = *(const float2*)(S1 + c);
                float2 s18 = *(const float2*)(S1 + c + 8);
                split2(make_float2(msk0 * fmaxf(h0.x + s00.x, 0.f),
                                   msk0 * fmaxf(h0.y + s00.y, 0.f)), Hhi[ks*4+0], Hlo[ks*4+0]);
                split2(make_float2(msk1 * fmaxf(h0.x + s10.x, 0.f),
                                   msk1 * fmaxf(h0.y + s10.y, 0.f)), Hhi[ks*4+1], Hlo[ks*4+1]);
                split2(make_float2(msk0 * fmaxf(h8.x + s08.x, 0.f),
                                   msk0 * fmaxf(h8.y + s08.y, 0.f)), Hhi[ks*4+2], Hlo[ks*4+2]);
                split2(make_float2(msk1 * fmaxf(h8.x + s18.x, 0.f),
                                   msk1 * fmaxf(h8.y + s18.y, 0.f)), Hhi[ks*4+3], Hlo[ks*4+3]);
            }
        }

        // ---- layer 2: 8 slabs of 32 m-cols, double-buffered ----
        const float wr0 = rts[r0 * 4 + k], wr1 = rts[r1 * 4 + k];
#pragma unroll
        for (int s = 0; s < 8; ++s) {
            if (s < 7) {
                uint32_t wb = SE_W2 + (uint32_t)(((s + 1) & 1) * 33792);
                for (int t = tid; t < 2112; t += 256) {
                    int im = t >= 1056;
                    uint32_t off = (uint32_t)(t - im * 1056) * 16;
                    cpa16(sb + wb + (im ? 16896 : 0) + off,
                          w2img + (size_t)((k * 2 + im) * 256 + (s + 1) * 32) * 528 + off);
                }
                CP_COMMIT();
                CP_WAIT1();
            } else {
                CP_WAIT0();
            }
            __syncthreads();
            const uint32_t wb = sb + SE_W2 + (uint32_t)((s & 1) * 33792);
            float c2[4][4] = {};
#pragma unroll
            for (int sp = 0; sp < 3; ++sp) {
                uint32_t Bb = wb + (sp == 1 ? 16896u : 0u) + brow * 528 + boff;
#pragma unroll
                for (int ks = 0; ks < 16; ++ks) {
                    uint32_t a[4];
                    if (sp == 2) {
                        a[0] = Hlo[ks*4]; a[1] = Hlo[ks*4+1]; a[2] = Hlo[ks*4+2]; a[3] = Hlo[ks*4+3];
                    } else {
                        a[0] = Hhi[ks*4]; a[1] = Hhi[ks*4+1]; a[2] = Hhi[ks*4+2]; a[3] = Hhi[ks*4+3];
                    }
                    uint32_t b0[4], b1f[4];
                    ldm4(Bb + ks * 32, b0);
                    ldm4(Bb + 16 * 528 + ks * 32, b1f);
                    mma_bf16(c2[0], a, b0[0], b0[1]);
                    mma_bf16(c2[1], a, b0[2], b0[3]);
                    mma_bf16(c2[2], a, b1f[0], b1f[1]);
                    mma_bf16(c2[3], a, b1f[2], b1f[3]);
                }
            }
            // epilogue: relu(D+b2) * rel_type, reduce over this warp's 16 rows
            float p0[4], p1[4];
#pragma unroll
            for (int t = 0; t < 4; ++t) {
                int col = s * 32 + t * 8 + 2 * tg;
                p0[t] = wr0 * fmaxf(c2[t][0] + b2s[col], 0.f)
                      + wr1 * fmaxf(c2[t][2] + b2s[col], 0.f);
                p1[t] = wr0 * fmaxf(c2[t][1] + b2s[col + 1], 0.f)
                      + wr1 * fmaxf(c2[t][3] + b2s[col + 1], 0.f);
            }
#pragma unroll
            for (int off = 4; off <= 16; off <<= 1)
#pragma unroll
                for (int t = 0; t < 4; ++t) {
                    p0[t] += __shfl_xor_sync(0xffffffff, p0[t], off);
                    p1[t] += __shfl_xor_sync(0xffffffff, p1[t], off);
                }
            if (g == 0) {
#pragma unroll
                for (int t = 0; t < 4; ++t) {
                    int col = s * 32 + t * 8 + 2 * tg;
                    aggS[w * 256 + col]     += p0[t];
                    aggS[w * 256 + col + 1] += p1[t];
                }
            }
            __syncthreads();
        }
    }

    // final reduce: node0 = warps 0-3, node1 = warps 4-7
    for (int t = tid; t < 512; t += 256) {
        int ni = t >> 8, m = t & 255;
        float sum = aggS[(ni * 4 + 0) * 256 + m] + aggS[(ni * 4 + 1) * 256 + m]
                  + aggS[(ni * 4 + 2) * 256 + m] + aggS[(ni * 4 + 3) * 256 + m];
        agg[((size_t)b * NN + n0 + ni) * 256 + m] = sum;
    }
}

// =====================================================================
// Output MLP 384->256->256->128 + residual (fp32 f32x2), 16 rows/block.
// =====================================================================
#define AUGSTR 388
#define P1STR 260
__device__ __forceinline__ unsigned long long pack2(float x) {
    unsigned long long r; asm("mov.b64 %0, {%1, %1};" : "=l"(r) : "f"(x)); return r;
}
__device__ __forceinline__ unsigned long long packab(float a, float b) {
    unsigned long long r; asm("mov.b64 %0, {%1, %2};" : "=l"(r) : "f"(a), "f"(b)); return r;
}
__device__ __forceinline__ void unpack2(unsigned long long v, float& a, float& b) {
    asm("mov.b64 {%0, %1}, %2;" : "=f"(a), "=f"(b) : "l"(v));
}
__device__ __forceinline__ unsigned long long fma2(unsigned long long a,
                                                   unsigned long long b,
                                                   unsigned long long c) {
    unsigned long long d;
    asm("fma.rn.f32x2 %0, %1, %2, %3;" : "=l"(d) : "l"(a), "l"(b), "l"(c));
    return d;
}

__global__ void __launch_bounds__(128)
out_mlp_kernel(const float* __restrict__ inputs, const float* __restrict__ agg,
               const float* __restrict__ Wo1, const float* __restrict__ bo1,
               const float* __restrict__ Wo2, const float* __restrict__ bo2,
               const float* __restrict__ Wo3, const float* __restrict__ bo3,
               float* __restrict__ out)
{
    extern __shared__ float sm[];
    float* augS = sm;
    float* p1S  = augS + 16 * AUGSTR;
    float* Wc   = p1S + 16 * P1STR;

    const int qtr = blockIdx.x, b = blockIdx.y;
    const int r0 = qtr * 16, tid = threadIdx.x;
    const int cg = tid & 31, er = tid >> 5, col0 = cg << 3;

    for (int idx = tid; idx < 16 * 96; idx += 128) {
        int r = idx / 96, c4 = idx % 96;
        float4 v;
        if (c4 < 32) v = *(const float4*)(inputs + ((size_t)(b * NN) + r0 + r) * FF + (c4 << 2));
        else         v = *(const float4*)(agg + ((size_t)(b * NN) + r0 + r) * 256 + ((c4 - 32) << 2));
        *(float4*)(augS + r * AUGSTR + (c4 << 2)) = v;
    }

    unsigned long long acc[4][4];
    {
        float4 t0 = *(const float4*)(bo1 + col0);
        float4 t1 = *(const float4*)(bo1 + col0 + 4);
        unsigned long long c0 = packab(t0.x, t0.y), c1 = packab(t0.z, t0.w);
        unsigned long long c2 = packab(t1.x, t1.y), c3 = packab(t1.z, t1.w);
#pragma unroll
        for (int i = 0; i < 4; ++i) { acc[i][0]=c0; acc[i][1]=c1; acc[i][2]=c2; acc[i][3]=c3; }
    }
#pragma unroll 1
    for (int fc = 0; fc < 12; ++fc) {
        __syncthreads();
        const float* wsrc = Wo1 + fc * 32 * 256;
        for (int idx = tid; idx < 32 * 64; idx += 128)
            *(float4*)(Wc + ((idx >> 6) << 8) + ((idx & 63) << 2)) =
                *(const float4*)(wsrc + ((idx >> 6) << 8) + ((idx & 63) << 2));
        __syncthreads();
#pragma unroll 8
        for (int f = 0; f < 32; ++f) {
            const float* wrow = Wc + (f << 8) + col0;
            ulonglong2 wA = *(const ulonglong2*)(wrow);
            ulonglong2 wB = *(const ulonglong2*)(wrow + 4);
#pragma unroll
            for (int i = 0; i < 4; ++i) {
                unsigned long long xp = pack2(augS[(er * 4 + i) * AUGSTR + fc * 32 + f]);
                acc[i][0] = fma2(xp, wA.x, acc[i][0]); acc[i][1] = fma2(xp, wA.y, acc[i][1]);
                acc[i][2] = fma2(xp, wB.x, acc[i][2]); acc[i][3] = fma2(xp, wB.y, acc[i][3]);
            }
        }
    }
#pragma unroll
    for (int i = 0; i < 4; ++i) {
        float4 v0, v1;
        unpack2(acc[i][0], v0.x, v0.y); unpack2(acc[i][1], v0.z, v0.w);
        unpack2(acc[i][2], v1.x, v1.y); unpack2(acc[i][3], v1.z, v1.w);
        v0.x=fmaxf(v0.x,0.f); v0.y=fmaxf(v0.y,0.f); v0.z=fmaxf(v0.z,0.f); v0.w=fmaxf(v0.w,0.f);
        v1.x=fmaxf(v1.x,0.f); v1.y=fmaxf(v1.y,0.f); v1.z=fmaxf(v1.z,0.f); v1.w=fmaxf(v1.w,0.f);
        *(float4*)(p1S + (er * 4 + i) * P1STR + col0)     = v0;
        *(float4*)(p1S + (er * 4 + i) * P1STR + col0 + 4) = v1;
    }

    {
        float4 t0 = *(const float4*)(bo2 + col0);
        float4 t1 = *(const float4*)(bo2 + col0 + 4);
        unsigned long long c0 = packab(t0.x, t0.y), c1 = packab(t0.z, t0.w);
        unsigned long long c2 = packab(t1.x, t1.y), c3 = packab(t1.z, t1.w);
#pragma unroll
        for (int i = 0; i < 4; ++i) { acc[i][0]=c0; acc[i][1]=c1; acc[i][2]=c2; acc[i][3]=c3; }
    }
#pragma unroll 1
    for (int fc = 0; fc < 8; ++fc) {
        __syncthreads();
        const float* wsrc = Wo2 + fc * 32 * 256;
        for (int idx = tid; idx < 32 * 64; idx += 128)
            *(float4*)(Wc + ((idx >> 6) << 8) + ((idx & 63) << 2)) =
                *(const float4*)(wsrc + ((idx >> 6) << 8) + ((idx & 63) << 2));
        __syncthreads();
#pragma unroll 8
        for (int f = 0; f < 32; ++f) {
            const float* wrow = Wc + (f << 8) + col0;
            ulonglong2 wA = *(const ulonglong2*)(wrow);
            ulonglong2 wB = *(const ulonglong2*)(wrow + 4);
#pragma unroll
            for (int i = 0; i < 4; ++i) {
                unsigned long long xp = pack2(p1S[(er * 4 + i) * P1STR + fc * 32 + f]);
                acc[i][0] = fma2(xp, wA.x, acc[i][0]); acc[i][1] = fma2(xp, wA.y, acc[i][1]);
                acc[i][2] = fma2(xp, wB.x, acc[i][2]); acc[i][3] = fma2(xp, wB.y, acc[i][3]);
            }
        }
    }
    __syncthreads();
#pragma unroll
    for (int i = 0; i < 4; ++i) {
        float4 v0, v1;
        unpack2(acc[i][0], v0.x, v0.y); unpack2(acc[i][1], v0.z, v0.w);
        unpack2(acc[i][2], v1.x, v1.y); unpack2(acc[i][3], v1.z, v1.w);
        v0.x=fmaxf(v0.x,0.f); v0.y=fmaxf(v0.y,0.f); v0.z=fmaxf(v0.z,0.f); v0.w=fmaxf(v0.w,0.f);
        v1.x=fmaxf(v1.x,0.f); v1.y=fmaxf(v1.y,0.f); v1.z=fmaxf(v1.z,0.f); v1.w=fmaxf(v1.w,0.f);
        *(float4*)(augS + (er * 4 + i) * AUGSTR + col0)     = v0;
        *(float4*)(augS + (er * 4 + i) * AUGSTR + col0 + 4) = v1;
    }

    unsigned long long a3[4][2];
    {
        float4 tb4 = *(const float4*)(bo3 + (cg << 2));
        unsigned long long c0 = packab(tb4.x, tb4.y), c1 = packab(tb4.z, tb4.w);
#pragma unroll
        for (int i = 0; i < 4; ++i) { a3[i][0] = c0; a3[i][1] = c1; }
    }
#pragma unroll 1
    for (int fc = 0; fc < 8; ++fc) {
        __syncthreads();
        const float* wsrc = Wo3 + fc * 32 * 128;
        for (int idx = tid; idx < 32 * 32; idx += 128)
            *(float4*)(Wc + ((idx >> 5) << 7) + ((idx & 31) << 2)) =
                *(const float4*)(wsrc + ((idx >> 5) << 7) + ((idx & 31) << 2));
        __syncthreads();
#pragma unroll 8
        for (int f = 0; f < 32; ++f) {
            const float* wrow = Wc + (f << 7) + (cg << 2);
            ulonglong2 wA = *(const ulonglong2*)(wrow);
#pragma unroll
            for (int i = 0; i < 4; ++i) {
                unsigned long long xp = pack2(augS[(er * 4 + i) * AUGSTR + fc * 32 + f]);
                a3[i][0] = fma2(xp, wA.x, a3[i][0]); a3[i][1] = fma2(xp, wA.y, a3[i][1]);
            }
        }
    }
#pragma unroll
    for (int i = 0; i < 4; ++i) {
        int r = r0 + er * 4 + i;
        float4 res = *(const float4*)(inputs + ((size_t)(b * NN) + r) * FF + (cg << 2));
        float x0, x1;
        unpack2(a3[i][0], x0, x1); res.x += x0; res.y += x1;
        unpack2(a3[i][1], x0, x1); res.z += x0; res.w += x1;
        *(float4*)(out + ((size_t)(b * NN) + r) * FF + (cg << 2)) = res;
    }
}

// =====================================================================
extern "C" void kernel_launch(void* const* d_in, const int* in_sizes, int n_in,
                              void* d_out, int out_size)
{
    const float* inputs   = (const float*)d_in[0];
    const float* rel_type = (const float*)d_in[1];
    const float* W1  = (const float*)d_in[4];
    const float* b1  = (const float*)d_in[5];
    const float* W2  = (const float*)d_in[6];
    const float* b2  = (const float*)d_in[7];
    const float* Wo1 = (const float*)d_in[8];
    const float* bo1 = (const float*)d_in[9];
    const float* Wo2 = (const float*)d_in[10];
    const float* bo2 = (const float*)d_in[11];
    const float* Wo3 = (const float*)d_in[12];
    const float* bo3 = (const float*)d_in[13];
    float* out = (float*)d_out;

    float *agg, *ns;
    unsigned char *w1r, *w1s, *w2i;
    uint32_t *xhi, *xlo;
    cudaGetSymbolAddress((void**)&agg, g_agg);
    cudaGetSymbolAddress((void**)&ns, g_ns);
    cudaGetSymbolAddress((void**)&w1r, g_w1r);
    cudaGetSymbolAddress((void**)&w1s, g_w1s);
    cudaGetSymbolAddress((void**)&w2i, g_w2img);
    cudaGetSymbolAddress((void**)&xhi, g_ximg_hi);
    cudaGetSymbolAddress((void**)&xlo, g_ximg_lo);

    const int smemB = (16 * AUGSTR + 16 * P1STR + 32 * 256) * 4;  // 74240
    cudaFuncSetAttribute(edge_kernel, cudaFuncAttributeMaxDynamicSharedMemorySize, SE_TOTAL);
    cudaFuncSetAttribute(ns_kernel, cudaFuncAttributeMaxDynamicSharedMemorySize, NS_TOTAL);
    cudaFuncSetAttribute(out_mlp_kernel, cudaFuncAttributeMaxDynamicSharedMemorySize, smemB);

    prep_x_kernel<<<BB * NN * 64 / 256, 256>>>(inputs, xhi, xlo);
    prep_w_kernel<<<dim3(4, 8, 4), 256>>>(W1, 0,   w1r, 272);   // recv half of W1
    prep_w_kernel<<<dim3(4, 8, 4), 256>>>(W1, 128, w1s, 272);   // send half of W1
    prep_w_kernel<<<dim3(8, 8, 4), 256>>>(W2, 0, w2i, 528);
    ns_kernel<<<dim3(KK, BB), 256, NS_TOTAL>>>(xhi, xlo, w1r, w1s, b1, ns);
    edge_kernel<<<dim3(NN / 2, BB), 256, SE_TOTAL>>>(rel_type, w2i, ns, b2, agg);
    out_mlp_kernel<<<dim3(4, BB), 128, smemB>>>(inputs, agg, Wo1, bo1, Wo2, bo2, Wo3, bo3, out);
}

// round 8
// speedup vs baseline: 2.1322x; 1.5621x over previous
#include <cuda_runtime.h>
#include <cuda_bf16.h>
#include <cuda_fp16.h>
#include <cstdint>

#define BB 32
#define NN 64
#define FF 128
#define KK 4
#define EE 4032

// ---------------- static device scratch (no allocations) ----------------
__device__ __align__(16) unsigned char g_w1r[KK * 2 * 256 * 272];   // W1 recv half (bf16 hi/lo)
__device__ __align__(16) unsigned char g_w1s[KK * 2 * 256 * 272];   // W1 send half (bf16 hi/lo)
__device__ __align__(16) unsigned char g_w2img[KK * 256 * 528];     // W2 fp16 HI only
__device__ __align__(16) uint32_t g_ximg_hi[BB * NN * 64];          // node feats bf16 pairs
__device__ __align__(16) uint32_t g_ximg_lo[BB * NN * 64];
__device__ __align__(16) float g_ns[KK * BB * NN * 512];            // [k][b][node][512]: hbase|S
__device__ float g_agg[BB * NN * 256];                              // 2 MB

// ---------------- helpers ----------------
__device__ __forceinline__ uint32_t smem_u32(const void* p) {
    uint32_t a;
    asm("{ .reg .u64 t; cvta.to.shared.u64 t, %1; cvt.u32.u64 %0, t; }" : "=r"(a) : "l"(p));
    return a;
}
__device__ __forceinline__ void split2(float2 v, uint32_t& hi, uint32_t& lo) {  // bf16
    __nv_bfloat162 h2 = __float22bfloat162_rn(v);
    float2 r = make_float2(v.x - __bfloat162float(h2.x), v.y - __bfloat162float(h2.y));
    __nv_bfloat162 l2 = __float22bfloat162_rn(r);
    hi = reinterpret_cast<uint32_t&>(h2);
    lo = reinterpret_cast<uint32_t&>(l2);
}
__device__ __forceinline__ void split2h(float2 v, uint32_t& hi, uint32_t& lo) { // fp16
    __half2 h2 = __float22half2_rn(v);
    float2 r = make_float2(v.x - __low2float(h2), v.y - __high2float(h2));
    __half2 l2 = __float22half2_rn(r);
    hi = reinterpret_cast<uint32_t&>(h2);
    lo = reinterpret_cast<uint32_t&>(l2);
}
__device__ __forceinline__ void ldm4(uint32_t addr, uint32_t r[4]) {
    asm volatile("ldmatrix.sync.aligned.m8n8.x4.shared.b16 {%0,%1,%2,%3}, [%4];"
                 : "=r"(r[0]), "=r"(r[1]), "=r"(r[2]), "=r"(r[3]) : "r"(addr));
}
__device__ __forceinline__ void mma_bf16(float* c, const uint32_t* a, uint32_t b0, uint32_t b1) {
    asm volatile(
        "mma.sync.aligned.m16n8k16.row.col.f32.bf16.bf16.f32 "
        "{%0,%1,%2,%3}, {%4,%5,%6,%7}, {%8,%9}, {%0,%1,%2,%3};"
        : "+f"(c[0]), "+f"(c[1]), "+f"(c[2]), "+f"(c[3])
        : "r"(a[0]), "r"(a[1]), "r"(a[2]), "r"(a[3]), "r"(b0), "r"(b1));
}
__device__ __forceinline__ void mma_f16(float* c, const uint32_t* a, uint32_t b0, uint32_t b1) {
    asm volatile(
        "mma.sync.aligned.m16n8k16.row.col.f32.f16.f16.f32 "
        "{%0,%1,%2,%3}, {%4,%5,%6,%7}, {%8,%9}, {%0,%1,%2,%3};"
        : "+f"(c[0]), "+f"(c[1]), "+f"(c[2]), "+f"(c[3])
        : "r"(a[0]), "r"(a[1]), "r"(a[2]), "r"(a[3]), "r"(b0), "r"(b1));
}
__device__ __forceinline__ void cpa16(uint32_t dst, const void* src) {
    asm volatile("cp.async.cg.shared.global [%0], [%1], 16;" :: "r"(dst), "l"(src));
}
#define CP_COMMIT() asm volatile("cp.async.commit_group;" ::: "memory")
#define CP_WAIT0()  asm volatile("cp.async.wait_group 0;" ::: "memory")
#define CP_WAIT1()  asm volatile("cp.async.wait_group 1;" ::: "memory")

// =====================================================================
// Prep: W1 bf16 hi/lo images [n][f], padded rows (stride 272).
// src element (kt, n, f) = W[kt*65536 + (koff+f)*256 + n]
// =====================================================================
__global__ void __launch_bounds__(256)
prep_w_kernel(const float* __restrict__ W, int koff, unsigned char* __restrict__ img, int rstride)
{
    __shared__ float ts[32][33];
    const int f0 = blockIdx.x * 32, nn0 = blockIdx.y * 32, kt = blockIdx.z;
    const int tid = threadIdx.x;
    const float* Wk = W + (size_t)kt * 65536;
#pragma unroll
    for (int p = 0; p < 4; ++p) {
        int fr = (tid >> 5) + p * 8, nl = tid & 31;
        ts[fr][nl] = Wk[(size_t)(koff + f0 + fr) * 256 + nn0 + nl];
    }
    __syncthreads();
#pragma unroll
    for (int p = 0; p < 2; ++p) {
        int idx = tid + p * 256;
        int nr = idx >> 4, wp = idx & 15;
        uint32_t hi, lo;
        split2(make_float2(ts[2 * wp][nr], ts[2 * wp + 1][nr]), hi, lo);
        size_t rb = (size_t)(nn0 + nr) * rstride + (f0 + 2 * wp) * 2;
        *(uint32_t*)(img + (size_t)(kt * 2 + 0) * 256 * rstride + rb) = hi;
        *(uint32_t*)(img + (size_t)(kt * 2 + 1) * 256 * rstride + rb) = lo;
    }
}

// Prep: W2 fp16 HI-only image [n][f], stride 528.
__global__ void __launch_bounds__(256)
prep_w2h_kernel(const float* __restrict__ W, unsigned char* __restrict__ img)
{
    __shared__ float ts[32][33];
    const int f0 = blockIdx.x * 32, nn0 = blockIdx.y * 32, kt = blockIdx.z;
    const int tid = threadIdx.x;
    const float* Wk = W + (size_t)kt * 65536;
#pragma unroll
    for (int p = 0; p < 4; ++p) {
        int fr = (tid >> 5) + p * 8, nl = tid & 31;
        ts[fr][nl] = Wk[(size_t)(f0 + fr) * 256 + nn0 + nl];
    }
    __syncthreads();
#pragma unroll
    for (int p = 0; p < 2; ++p) {
        int idx = tid + p * 256;
        int nr = idx >> 4, wp = idx & 15;
        __half2 h2 = __float22half2_rn(make_float2(ts[2 * wp][nr], ts[2 * wp + 1][nr]));
        *(uint32_t*)(img + (size_t)(kt * 256 + nn0 + nr) * 528 + (f0 + 2 * wp) * 2) =
            reinterpret_cast<uint32_t&>(h2);
    }
}

// inputs -> bf16 hi/lo images
__global__ void __launch_bounds__(256)
prep_x_kernel(const float* __restrict__ inputs, uint32_t* __restrict__ xhi, uint32_t* __restrict__ xlo)
{
    int idx = blockIdx.x * 256 + threadIdx.x;
    float2 v = ((const float2*)inputs)[idx];
    uint32_t hi, lo;
    split2(v, hi, lo);
    xhi[idx] = hi;
    xlo[idx] = lo;
}

// =====================================================================
// ns_kernel: per (k,b) node GEMM [64x128]@[128x512] (3-split bf16 mma).
// out cols 0:256 = x@W1_recv + b1 (hbase); cols 256:512 = x@W1_send (S).
// =====================================================================
#define NS_XHI 0
#define NS_XLO 17408
#define NS_W   34816
#define NS_B1  69632
#define NS_TOTAL 70656

__global__ void __launch_bounds__(256)
ns_kernel(const uint32_t* __restrict__ xhi, const uint32_t* __restrict__ xlo,
          const unsigned char* __restrict__ w1r, const unsigned char* __restrict__ w1s,
          const float* __restrict__ b1, float* __restrict__ ns)
{
    extern __shared__ char smem[];
    const uint32_t sb = smem_u32(smem);
    const int tid = threadIdx.x, lane = tid & 31, w = tid >> 5;
    const int k = blockIdx.x, b = blockIdx.y;

    for (int t = tid; t < 1024; t += 256) {
        int row = t >> 4, sgi = t & 15;
        size_t so = (size_t)(b * 64 + row) * 64 + sgi * 4;
        cpa16(sb + NS_XHI + row * 272 + sgi * 16, xhi + so);
        cpa16(sb + NS_XLO + row * 272 + sgi * 16, xlo + so);
    }
    CP_COMMIT();
    if (tid < 64) ((float4*)(smem + NS_B1))[tid] = ((const float4*)(b1 + k * 256))[tid];

    const int g = lane >> 2, tg = lane & 3;
    const int arow = lane & 15;
    const uint32_t aoff = (uint32_t)((lane >> 4) << 4);
    const int brow = (lane & 7) + ((lane >> 4) << 3);
    const uint32_t boff = (uint32_t)((lane & 8) << 1);
    const int wm = w & 3, wn = w >> 2;
    const int m0 = wm * 16;
    const float* b1s = (const float*)(smem + NS_B1);
    float* outk = ns + ((size_t)k * BB + b) * 64 * 512;

#pragma unroll 1
    for (int half = 0; half < 2; ++half) {
        const unsigned char* img = half ? w1s : w1r;
#pragma unroll 1
        for (int s = 0; s < 4; ++s) {
            for (int t = tid; t < 2176; t += 256) {
                int im = t >= 1088;
                uint32_t off = (uint32_t)(t - im * 1088) * 16;
                cpa16(sb + NS_W + (im ? 17408 : 0) + off,
                      img + (size_t)((k * 2 + im) * 256 + s * 64) * 272 + off);
            }
            CP_COMMIT(); CP_WAIT0();
            __syncthreads();
            float c[4][4] = {};
#pragma unroll
            for (int sp = 0; sp < 3; ++sp) {
                uint32_t Ab = sb + (sp == 2 ? NS_XLO : NS_XHI) + (m0 + arow) * 272 + aoff;
                uint32_t Bb = sb + NS_W + (sp == 1 ? 17408u : 0u) + (wn * 32 + brow) * 272 + boff;
#pragma unroll
                for (int ks = 0; ks < 8; ++ks) {
                    uint32_t a[4], b0[4], b1f[4];
                    ldm4(Ab + ks * 32, a);
                    ldm4(Bb + ks * 32, b0);
                    ldm4(Bb + 16 * 272 + ks * 32, b1f);
                    mma_bf16(c[0], a, b0[0], b0[1]);
                    mma_bf16(c[1], a, b0[2], b0[3]);
                    mma_bf16(c[2], a, b1f[0], b1f[1]);
                    mma_bf16(c[3], a, b1f[2], b1f[3]);
                }
            }
            int r0 = m0 + g, r1 = r0 + 8;
            int cn = s * 64 + wn * 32;
#pragma unroll
            for (int t = 0; t < 4; ++t) {
                int col = cn + t * 8 + 2 * tg;
                float a0 = half ? 0.f : b1s[col], a1 = half ? 0.f : b1s[col + 1];
                outk[(size_t)r0 * 512 + half * 256 + col]     = c[t][0] + a0;
                outk[(size_t)r0 * 512 + half * 256 + col + 1] = c[t][1] + a1;
                outk[(size_t)r1 * 512 + half * 256 + col]     = c[t][2] + a0;
                outk[(size_t)r1 * 512 + half * 256 + col + 1] = c[t][3] + a1;
            }
            __syncthreads();
        }
    }
}

// ---------------- SMEM map (bytes) for edge kernel ----------------
#define SE_S    0         // 64 rows x 1040 B = 66560
#define SE_W2   66560     // 2 bufs x 16896 (fp16 hi only) = 33792
#define SE_HBS  100352    // 2048
#define SE_B2S  102400    // 1024
#define SE_RTS  103424    // 2048
#define SE_AGG  105472    // 8192
#define SE_TOTAL 113664

// =====================================================================
// Edge kernel: block = (node pair, batch), 256 threads = 8 warps.
// Layer 1 = elementwise relu(hbase[recv] + S[send]) -> fp16 A fragments.
// Layer 2 = fp16 2-split (AhiB + AloB), B regs shared across both passes.
// =====================================================================
__global__ void __launch_bounds__(256, 1)
edge_kernel(const float* __restrict__ rel_type,
            const unsigned char* __restrict__ w2img,
            const float* __restrict__ ns,
            const float* __restrict__ b2,
            float* __restrict__ agg)
{
    extern __shared__ char smem[];
    const uint32_t sb = smem_u32(smem);
    const int tid = threadIdx.x;
    const int lane = tid & 31, w = tid >> 5;
    const int n0 = blockIdx.x * 2, b = blockIdx.y;

    if (tid < 128) {
        int node = n0 + (tid >> 6), le = tid & 63;
        float4 v = make_float4(0.f, 0.f, 0.f, 0.f);
        if (le < 63) v = *(const float4*)(rel_type + ((size_t)b * EE + node * 63 + le) * KK);
        *(float4*)(smem + SE_RTS + tid * 16) = v;
    }
    for (int i = tid; i < 2048; i += 256) ((float*)(smem + SE_AGG))[i] = 0.f;

    const int g = lane >> 2, tg = lane & 3;
    const int brow = (lane & 7) + ((lane >> 4) << 3);
    const uint32_t boff = (uint32_t)((lane & 8) << 1);
    const int m0 = w * 16;
    const int nodeg = n0 + (w >> 2);
    const float* rts = (const float*)(smem + SE_RTS);
    const float* b2s = (const float*)(smem + SE_B2S);
    float* aggS = (float*)(smem + SE_AGG);

    const int r0 = m0 + g, r1 = r0 + 8;
    const int le0 = r0 & 63, le1 = r1 & 63;
    const float msk0 = (le0 != 63) ? 1.f : 0.f;
    const float msk1 = (le1 != 63) ? 1.f : 0.f;
    const int j0 = (le0 != 63) ? (le0 + (le0 >= nodeg)) : 0;
    const int j1 = (le1 != 63) ? (le1 + (le1 >= nodeg)) : 0;

    uint32_t Hhi[64], Hlo[64];   // fp16 pairs

#pragma unroll 1
    for (int k = 0; k < KK; ++k) {
        __syncthreads();   // prior k consumers done (S buffer, W2 bufs)

        const float* nsk = ns + ((size_t)k * BB + b) * 64 * 512;
        // S rows (all 64 senders, cols 256:512)
        for (int t = tid; t < 4096; t += 256) {
            int row = t >> 6, ch = t & 63;
            cpa16(sb + SE_S + row * 1040 + ch * 16, nsk + (size_t)row * 512 + 256 + ch * 4);
        }
        CP_COMMIT();
        // prefetch W2 slab 0
        for (int t = tid; t < 1056; t += 256)
            cpa16(sb + SE_W2 + t * 16, w2img + (size_t)(k * 256) * 528 + t * 16);
        CP_COMMIT();
        // hbase rows for the 2 receiver nodes + b2
        if (tid < 128) {
            int row = n0 + (tid >> 6), c4 = (tid & 63) * 4;
            *(float4*)(smem + SE_HBS + tid * 16) = *(const float4*)(nsk + (size_t)row * 512 + c4);
        } else if (tid < 192) {
            ((float4*)(smem + SE_B2S))[tid - 128] = ((const float4*)(b2 + k * 256))[tid - 128];
        }
        CP_WAIT1();        // S complete (W2 slab0 may still be in flight)
        __syncthreads();

        // ---- build H fragments: relu(hbase + S), fp16 hi/lo ----
        {
            const float* S0 = (const float*)(smem + SE_S) + j0 * 260;
            const float* S1 = (const float*)(smem + SE_S) + j1 * 260;
            const float* hb = (const float*)(smem + SE_HBS) + (w >> 2) * 256;
#pragma unroll
            for (int ks = 0; ks < 16; ++ks) {
                int c = ks * 16 + 2 * tg;
                float2 h0 = *(const float2*)(hb + c);
                float2 h8 = *(const float2*)(hb + c + 8);
                float2 s00 = *(const float2*)(S0 + c);
                float2 s08 = *(const float2*)(S0 + c + 8);
                float2 s10 = *(const float2*)(S1 + c);
                float2 s18 = *(const float2*)(S1 + c + 8);
                split2h(make_float2(msk0 * fmaxf(h0.x + s00.x, 0.f),
                                    msk0 * fmaxf(h0.y + s00.y, 0.f)), Hhi[ks*4+0], Hlo[ks*4+0]);
                split2h(make_float2(msk1 * fmaxf(h0.x + s10.x, 0.f),
                                    msk1 * fmaxf(h0.y + s10.y, 0.f)), Hhi[ks*4+1], Hlo[ks*4+1]);
                split2h(make_float2(msk0 * fmaxf(h8.x + s08.x, 0.f),
                                    msk0 * fmaxf(h8.y + s08.y, 0.f)), Hhi[ks*4+2], Hlo[ks*4+2]);
                split2h(make_float2(msk1 * fmaxf(h8.x + s18.x, 0.f),
                                    msk1 * fmaxf(h8.y + s18.y, 0.f)), Hhi[ks*4+3], Hlo[ks*4+3]);
            }
        }

        // ---- layer 2: 8 slabs of 32 m-cols, double-buffered, 1 sync/slab ----
        const float wr0 = rts[r0 * 4 + k], wr1 = rts[r1 * 4 + k];
#pragma unroll 1
        for (int s = 0; s < 8; ++s) {
            CP_WAIT0();        // slab s resident
            __syncthreads();   // all warps done reading the other buffer
            if (s < 7) {
                uint32_t wb = SE_W2 + (uint32_t)(((s + 1) & 1) * 16896);
                for (int t = tid; t < 1056; t += 256)
                    cpa16(sb + wb + t * 16,
                          w2img + (size_t)(k * 256 + (s + 1) * 32) * 528 + t * 16);
                CP_COMMIT();
            }
            const uint32_t wbs = sb + SE_W2 + (uint32_t)((s & 1) * 16896) + brow * 528 + boff;
            float c2[4][4] = {};
#pragma unroll
            for (int ks = 0; ks < 16; ++ks) {
                uint32_t b0[4], b1f[4];
                ldm4(wbs + ks * 32, b0);
                ldm4(wbs + 16 * 528 + ks * 32, b1f);
                const uint32_t* ah = Hhi + ks * 4;
                const uint32_t* al = Hlo + ks * 4;
                mma_f16(c2[0], ah, b0[0], b0[1]);
                mma_f16(c2[1], ah, b0[2], b0[3]);
                mma_f16(c2[2], ah, b1f[0], b1f[1]);
                mma_f16(c2[3], ah, b1f[2], b1f[3]);
                mma_f16(c2[0], al, b0[0], b0[1]);
                mma_f16(c2[1], al, b0[2], b0[3]);
                mma_f16(c2[2], al, b1f[0], b1f[1]);
                mma_f16(c2[3], al, b1f[2], b1f[3]);
            }
            // epilogue: relu(D+b2) * rel_type, reduce over this warp's 16 rows
            float p0[4], p1[4];
#pragma unroll
            for (int t = 0; t < 4; ++t) {
                int col = s * 32 + t * 8 + 2 * tg;
                p0[t] = wr0 * fmaxf(c2[t][0] + b2s[col], 0.f)
                      + wr1 * fmaxf(c2[t][2] + b2s[col], 0.f);
                p1[t] = wr0 * fmaxf(c2[t][1] + b2s[col + 1], 0.f)
                      + wr1 * fmaxf(c2[t][3] + b2s[col + 1], 0.f);
            }
#pragma unroll
            for (int off = 4; off <= 16; off <<= 1)
#pragma unroll
                for (int t = 0; t < 4; ++t) {
                    p0[t] += __shfl_xor_sync(0xffffffff, p0[t], off);
                    p1[t] += __shfl_xor_sync(0xffffffff, p1[t], off);
                }
            if (g == 0) {
#pragma unroll
                for (int t = 0; t < 4; ++t) {
                    int col = s * 32 + t * 8 + 2 * tg;
                    aggS[w * 256 + col]     += p0[t];
                    aggS[w * 256 + col + 1] += p1[t];
                }
            }
        }
    }

    __syncthreads();
    for (int t = tid; t < 512; t += 256) {
        int ni = t >> 8, m = t & 255;
        float sum = aggS[(ni * 4 + 0) * 256 + m] + aggS[(ni * 4 + 1) * 256 + m]
                  + aggS[(ni * 4 + 2) * 256 + m] + aggS[(ni * 4 + 3) * 256 + m];
        agg[((size_t)b * NN + n0 + ni) * 256 + m] = sum;
    }
}

// =====================================================================
// Output MLP 384->256->256->128 + residual (fp32 f32x2), 16 rows/block.
// =====================================================================
#define AUGSTR 388
#define P1STR 260
__device__ __forceinline__ unsigned long long pack2(float x) {
    unsigned long long r; asm("mov.b64 %0, {%1, %1};" : "=l"(r) : "f"(x)); return r;
}
__device__ __forceinline__ unsigned long long packab(float a, float b) {
    unsigned long long r; asm("mov.b64 %0, {%1, %2};" : "=l"(r) : "f"(a), "f"(b)); return r;
}
__device__ __forceinline__ void unpack2(unsigned long long v, float& a, float& b) {
    asm("mov.b64 {%0, %1}, %2;" : "=f"(a), "=f"(b) : "l"(v));
}
__device__ __forceinline__ unsigned long long fma2(unsigned long long a,
                                                   unsigned long long b,
                                                   unsigned long long c) {
    unsigned long long d;
    asm("fma.rn.f32x2 %0, %1, %2, %3;" : "=l"(d) : "l"(a), "l"(b), "l"(c));
    return d;
}

__global__ void __launch_bounds__(128)
out_mlp_kernel(const float* __restrict__ inputs, const float* __restrict__ agg,
               const float* __restrict__ Wo1, const float* __restrict__ bo1,
               const float* __restrict__ Wo2, const float* __restrict__ bo2,
               const float* __restrict__ Wo3, const float* __restrict__ bo3,
               float* __restrict__ out)
{
    extern __shared__ float sm[];
    float* augS = sm;
    float* p1S  = augS + 16 * AUGSTR;
    float* Wc   = p1S + 16 * P1STR;

    const int qtr = blockIdx.x, b = blockIdx.y;
    const int r0 = qtr * 16, tid = threadIdx.x;
    const int cg = tid & 31, er = tid >> 5, col0 = cg << 3;

    for (int idx = tid; idx < 16 * 96; idx += 128) {
        int r = idx / 96, c4 = idx % 96;
        float4 v;
        if (c4 < 32) v = *(const float4*)(inputs + ((size_t)(b * NN) + r0 + r) * FF + (c4 << 2));
        else         v = *(const float4*)(agg + ((size_t)(b * NN) + r0 + r) * 256 + ((c4 - 32) << 2));
        *(float4*)(augS + r * AUGSTR + (c4 << 2)) = v;
    }

    unsigned long long acc[4][4];
    {
        float4 t0 = *(const float4*)(bo1 + col0);
        float4 t1 = *(const float4*)(bo1 + col0 + 4);
        unsigned long long c0 = packab(t0.x, t0.y), c1 = packab(t0.z, t0.w);
        unsigned long long c2 = packab(t1.x, t1.y), c3 = packab(t1.z, t1.w);
#pragma unroll
        for (int i = 0; i < 4; ++i) { acc[i][0]=c0; acc[i][1]=c1; acc[i][2]=c2; acc[i][3]=c3; }
    }
#pragma unroll 1
    for (int fc = 0; fc < 12; ++fc) {
        __syncthreads();
        const float* wsrc = Wo1 + fc * 32 * 256;
        for (int idx = tid; idx < 32 * 64; idx += 128)
            *(float4*)(Wc + ((idx >> 6) << 8) + ((idx & 63) << 2)) =
                *(const float4*)(wsrc + ((idx >> 6) << 8) + ((idx & 63) << 2));
        __syncthreads();
#pragma unroll 8
        for (int f = 0; f < 32; ++f) {
            const float* wrow = Wc + (f << 8) + col0;
            ulonglong2 wA = *(const ulonglong2*)(wrow);
            ulonglong2 wB = *(const ulonglong2*)(wrow + 4);
#pragma unroll
            for (int i = 0; i < 4; ++i) {
                unsigned long long xp = pack2(augS[(er * 4 + i) * AUGSTR + fc * 32 + f]);
                acc[i][0] = fma2(xp, wA.x, acc[i][0]); acc[i][1] = fma2(xp, wA.y, acc[i][1]);
                acc[i][2] = fma2(xp, wB.x, acc[i][2]); acc[i][3] = fma2(xp, wB.y, acc[i][3]);
            }
        }
    }
#pragma unroll
    for (int i = 0; i < 4; ++i) {
        float4 v0, v1;
        unpack2(acc[i][0], v0.x, v0.y); unpack2(acc[i][1], v0.z, v0.w);
        unpack2(acc[i][2], v1.x, v1.y); unpack2(acc[i][3], v1.z, v1.w);
        v0.x=fmaxf(v0.x,0.f); v0.y=fmaxf(v0.y,0.f); v0.z=fmaxf(v0.z,0.f); v0.w=fmaxf(v0.w,0.f);
        v1.x=fmaxf(v1.x,0.f); v1.y=fmaxf(v1.y,0.f); v1.z=fmaxf(v1.z,0.f); v1.w=fmaxf(v1.w,0.f);
        *(float4*)(p1S + (er * 4 + i) * P1STR + col0)     = v0;
        *(float4*)(p1S + (er * 4 + i) * P1STR + col0 + 4) = v1;
    }

    {
        float4 t0 = *(const float4*)(bo2 + col0);
        float4 t1 = *(const float4*)(bo2 + col0 + 4);
        unsigned long long c0 = packab(t0.x, t0.y), c1 = packab(t0.z, t0.w);
        unsigned long long c2 = packab(t1.x, t1.y), c3 = packab(t1.z, t1.w);
#pragma unroll
        for (int i = 0; i < 4; ++i) { acc[i][0]=c0; acc[i][1]=c1; acc[i][2]=c2; acc[i][3]=c3; }
    }
#pragma unroll 1
    for (int fc = 0; fc < 8; ++fc) {
        __syncthreads();
        const float* wsrc = Wo2 + fc * 32 * 256;
        for (int idx = tid; idx < 32 * 64; idx += 128)
            *(float4*)(Wc + ((idx >> 6) << 8) + ((idx & 63) << 2)) =
                *(const float4*)(wsrc + ((idx >> 6) << 8) + ((idx & 63) << 2));
        __syncthreads();
#pragma unroll 8
        for (int f = 0; f < 32; ++f) {
            const float* wrow = Wc + (f << 8) + col0;
            ulonglong2 wA = *(const ulonglong2*)(wrow);
            ulonglong2 wB = *(const ulonglong2*)(wrow + 4);
#pragma unroll
            for (int i = 0; i < 4; ++i) {
                unsigned long long xp = pack2(p1S[(er * 4 + i) * P1STR + fc * 32 + f]);
                acc[i][0] = fma2(xp, wA.x, acc[i][0]); acc[i][1] = fma2(xp, wA.y, acc[i][1]);
                acc[i][2] = fma2(xp, wB.x, acc[i][2]); acc[i][3] = fma2(xp, wB.y, acc[i][3]);
            }
        }
    }
    __syncthreads();
#pragma unroll
    for (int i = 0; i < 4; ++i) {
        float4 v0, v1;
        unpack2(acc[i][0], v0.x, v0.y); unpack2(acc[i][1], v0.z, v0.w);
        unpack2(acc[i][2], v1.x, v1.y); unpack2(acc[i][3], v1.z, v1.w);
        v0.x=fmaxf(v0.x,0.f); v0.y=fmaxf(v0.y,0.f); v0.z=fmaxf(v0.z,0.f); v0.w=fmaxf(v0.w,0.f);
        v1.x=fmaxf(v1.x,0.f); v1.y=fmaxf(v1.y,0.f); v1.z=fmaxf(v1.z,0.f); v1.w=fmaxf(v1.w,0.f);
        *(float4*)(augS + (er * 4 + i) * AUGSTR + col0)     = v0;
        *(float4*)(augS + (er * 4 + i) * AUGSTR + col0 + 4) = v1;
    }

    unsigned long long a3[4][2];
    {
        float4 tb4 = *(const float4*)(bo3 + (cg << 2));
        unsigned long long c0 = packab(tb4.x, tb4.y), c1 = packab(tb4.z, tb4.w);
#pragma unroll
        for (int i = 0; i < 4; ++i) { a3[i][0] = c0; a3[i][1] = c1; }
    }
#pragma unroll 1
    for (int fc = 0; fc < 8; ++fc) {
        __syncthreads();
        const float* wsrc = Wo3 + fc * 32 * 128;
        for (int idx = tid; idx < 32 * 32; idx += 128)
            *(float4*)(Wc + ((idx >> 5) << 7) + ((idx & 31) << 2)) =
                *(const float4*)(wsrc + ((idx >> 5) << 7) + ((idx & 31) << 2));
        __syncthreads();
#pragma unroll 8
        for (int f = 0; f < 32; ++f) {
            const float* wrow = Wc + (f << 7) + (cg << 2);
            ulonglong2 wA = *(const ulonglong2*)(wrow);
#pragma unroll
            for (int i = 0; i < 4; ++i) {
                unsigned long long xp = pack2(augS[(er * 4 + i) * AUGSTR + fc * 32 + f]);
                a3[i][0] = fma2(xp, wA.x, a3[i][0]); a3[i][1] = fma2(xp, wA.y, a3[i][1]);
            }
        }
    }
#pragma unroll
    for (int i = 0; i < 4; ++i) {
        int r = r0 + er * 4 + i;
        float4 res = *(const float4*)(inputs + ((size_t)(b * NN) + r) * FF + (cg << 2));
        float x0, x1;
        unpack2(a3[i][0], x0, x1); res.x += x0; res.y += x1;
        unpack2(a3[i][1], x0, x1); res.z += x0; res.w += x1;
        *(float4*)(out + ((size_t)(b * NN) + r) * FF + (cg << 2)) = res;
    }
}

// =====================================================================
extern "C" void kernel_launch(void* const* d_in, const int* in_sizes, int n_in,
                              void* d_out, int out_size)
{
    const float* inputs   = (const float*)d_in[0];
    const float* rel_type = (const float*)d_in[1];
    const float* W1  = (const float*)d_in[4];
    const float* b1  = (const float*)d_in[5];
    const float* W2  = (const float*)d_in[6];
    const float* b2  = (const float*)d_in[7];
    const float* Wo1 = (const float*)d_in[8];
    const float* bo1 = (const float*)d_in[9];
    const float* Wo2 = (const float*)d_in[10];
    const float* bo2 = (const float*)d_in[11];
    const float* Wo3 = (const float*)d_in[12];
    const float* bo3 = (const float*)d_in[13];
    float* out = (float*)d_out;

    float *agg, *ns;
    unsigned char *w1r, *w1s, *w2i;
    uint32_t *xhi, *xlo;
    cudaGetSymbolAddress((void**)&agg, g_agg);
    cudaGetSymbolAddress((void**)&ns, g_ns);
    cudaGetSymbolAddress((void**)&w1r, g_w1r);
    cudaGetSymbolAddress((void**)&w1s, g_w1s);
    cudaGetSymbolAddress((void**)&w2i, g_w2img);
    cudaGetSymbolAddress((void**)&xhi, g_ximg_hi);
    cudaGetSymbolAddress((void**)&xlo, g_ximg_lo);

    const int smemB = (16 * AUGSTR + 16 * P1STR + 32 * 256) * 4;  // 74240
    cudaFuncSetAttribute(edge_kernel, cudaFuncAttributeMaxDynamicSharedMemorySize, SE_TOTAL);
    cudaFuncSetAttribute(ns_kernel, cudaFuncAttributeMaxDynamicSharedMemorySize, NS_TOTAL);
    cudaFuncSetAttribute(out_mlp_kernel, cudaFuncAttributeMaxDynamicSharedMemorySize, smemB);

    prep_x_kernel<<<BB * NN * 64 / 256, 256>>>(inputs, xhi, xlo);
    prep_w_kernel<<<dim3(4, 8, 4), 256>>>(W1, 0,   w1r, 272);   // recv half of W1 (bf16)
    prep_w_kernel<<<dim3(4, 8, 4), 256>>>(W1, 128, w1s, 272);   // send half of W1 (bf16)
    prep_w2h_kernel<<<dim3(8, 8, 4), 256>>>(W2, w2i);           // W2 fp16 hi
    ns_kernel<<<dim3(KK, BB), 256, NS_TOTAL>>>(xhi, xlo, w1r, w1s, b1, ns);
    edge_kernel<<<dim3(NN / 2, BB), 256, SE_TOTAL>>>(rel_type, w2i, ns, b2, agg);
    out_mlp_kernel<<<dim3(4, BB), 128, smemB>>>(inputs, agg, Wo1, bo1, Wo2, bo2, Wo3, bo3, out);
}

// round 9
// speedup vs baseline: 2.8437x; 1.3337x over previous
#include <cuda_runtime.h>
#include <cuda_bf16.h>
#include <cuda_fp16.h>
#include <cstdint>

#define BB 32
#define NN 64
#define FF 128
#define KK 4
#define EE 4032

// ---------------- static device scratch (no allocations) ----------------
__device__ __align__(16) unsigned char g_w1r[KK * 2 * 256 * 272];   // W1 recv half (bf16 hi/lo)
__device__ __align__(16) unsigned char g_w1s[KK * 2 * 256 * 272];   // W1 send half (bf16 hi/lo)
__device__ __align__(16) unsigned char g_w2img[KK * 256 * 528];     // W2 fp16 HI only
__device__ __align__(16) uint32_t g_ximg_hi[BB * NN * 64];          // node feats bf16 pairs
__device__ __align__(16) uint32_t g_ximg_lo[BB * NN * 64];
__device__ __align__(16) float g_ns[KK * BB * NN * 512];            // [k][b][node][512]: hbase|S
__device__ float g_agg[BB * NN * 256];                              // 2 MB

// ---------------- helpers ----------------
__device__ __forceinline__ uint32_t smem_u32(const void* p) {
    uint32_t a;
    asm("{ .reg .u64 t; cvta.to.shared.u64 t, %1; cvt.u32.u64 %0, t; }" : "=r"(a) : "l"(p));
    return a;
}
__device__ __forceinline__ void split2(float2 v, uint32_t& hi, uint32_t& lo) {  // bf16
    __nv_bfloat162 h2 = __float22bfloat162_rn(v);
    float2 r = make_float2(v.x - __bfloat162float(h2.x), v.y - __bfloat162float(h2.y));
    __nv_bfloat162 l2 = __float22bfloat162_rn(r);
    hi = reinterpret_cast<uint32_t&>(h2);
    lo = reinterpret_cast<uint32_t&>(l2);
}
__device__ __forceinline__ uint32_t h2pack(float a, float b) {
    __half2 h = __float22half2_rn(make_float2(a, b));
    return reinterpret_cast<uint32_t&>(h);
}
__device__ __forceinline__ void ldm4(uint32_t addr, uint32_t r[4]) {
    asm volatile("ldmatrix.sync.aligned.m8n8.x4.shared.b16 {%0,%1,%2,%3}, [%4];"
                 : "=r"(r[0]), "=r"(r[1]), "=r"(r[2]), "=r"(r[3]) : "r"(addr));
}
__device__ __forceinline__ void mma_bf16(float* c, const uint32_t* a, uint32_t b0, uint32_t b1) {
    asm volatile(
        "mma.sync.aligned.m16n8k16.row.col.f32.bf16.bf16.f32 "
        "{%0,%1,%2,%3}, {%4,%5,%6,%7}, {%8,%9}, {%0,%1,%2,%3};"
        : "+f"(c[0]), "+f"(c[1]), "+f"(c[2]), "+f"(c[3])
        : "r"(a[0]), "r"(a[1]), "r"(a[2]), "r"(a[3]), "r"(b0), "r"(b1));
}
__device__ __forceinline__ void mma_f16(float* c, const uint32_t* a, uint32_t b0, uint32_t b1) {
    asm volatile(
        "mma.sync.aligned.m16n8k16.row.col.f32.f16.f16.f32 "
        "{%0,%1,%2,%3}, {%4,%5,%6,%7}, {%8,%9}, {%0,%1,%2,%3};"
        : "+f"(c[0]), "+f"(c[1]), "+f"(c[2]), "+f"(c[3])
        : "r"(a[0]), "r"(a[1]), "r"(a[2]), "r"(a[3]), "r"(b0), "r"(b1));
}
__device__ __forceinline__ void cpa16(uint32_t dst, const void* src) {
    asm volatile("cp.async.cg.shared.global [%0], [%1], 16;" :: "r"(dst), "l"(src));
}
#define CP_COMMIT() asm volatile("cp.async.commit_group;" ::: "memory")
#define CP_WAIT0()  asm volatile("cp.async.wait_group 0;" ::: "memory")
#define CP_WAIT1()  asm volatile("cp.async.wait_group 1;" ::: "memory")

// =====================================================================
// Prep kernels
// =====================================================================
__global__ void __launch_bounds__(256)
prep_w_kernel(const float* __restrict__ W, int koff, unsigned char* __restrict__ img, int rstride)
{
    __shared__ float ts[32][33];
    const int f0 = blockIdx.x * 32, nn0 = blockIdx.y * 32, kt = blockIdx.z;
    const int tid = threadIdx.x;
    const float* Wk = W + (size_t)kt * 65536;
#pragma unroll
    for (int p = 0; p < 4; ++p) {
        int fr = (tid >> 5) + p * 8, nl = tid & 31;
        ts[fr][nl] = Wk[(size_t)(koff + f0 + fr) * 256 + nn0 + nl];
    }
    __syncthreads();
#pragma unroll
    for (int p = 0; p < 2; ++p) {
        int idx = tid + p * 256;
        int nr = idx >> 4, wp = idx & 15;
        uint32_t hi, lo;
        split2(make_float2(ts[2 * wp][nr], ts[2 * wp + 1][nr]), hi, lo);
        size_t rb = (size_t)(nn0 + nr) * rstride + (f0 + 2 * wp) * 2;
        *(uint32_t*)(img + (size_t)(kt * 2 + 0) * 256 * rstride + rb) = hi;
        *(uint32_t*)(img + (size_t)(kt * 2 + 1) * 256 * rstride + rb) = lo;
    }
}

__global__ void __launch_bounds__(256)
prep_w2h_kernel(const float* __restrict__ W, unsigned char* __restrict__ img)
{
    __shared__ float ts[32][33];
    const int f0 = blockIdx.x * 32, nn0 = blockIdx.y * 32, kt = blockIdx.z;
    const int tid = threadIdx.x;
    const float* Wk = W + (size_t)kt * 65536;
#pragma unroll
    for (int p = 0; p < 4; ++p) {
        int fr = (tid >> 5) + p * 8, nl = tid & 31;
        ts[fr][nl] = Wk[(size_t)(f0 + fr) * 256 + nn0 + nl];
    }
    __syncthreads();
#pragma unroll
    for (int p = 0; p < 2; ++p) {
        int idx = tid + p * 256;
        int nr = idx >> 4, wp = idx & 15;
        *(uint32_t*)(img + (size_t)(kt * 256 + nn0 + nr) * 528 + (f0 + 2 * wp) * 2) =
            h2pack(ts[2 * wp][nr], ts[2 * wp + 1][nr]);
    }
}

__global__ void __launch_bounds__(256)
prep_x_kernel(const float* __restrict__ inputs, uint32_t* __restrict__ xhi, uint32_t* __restrict__ xlo)
{
    int idx = blockIdx.x * 256 + threadIdx.x;
    float2 v = ((const float2*)inputs)[idx];
    uint32_t hi, lo;
    split2(v, hi, lo);
    xhi[idx] = hi;
    xlo[idx] = lo;
}

// =====================================================================
// ns_kernel: per (k,b) node GEMM [64x128]@[128x512] (3-split bf16 mma).
// out cols 0:256 = x@W1_recv + b1 (hbase); cols 256:512 = x@W1_send (S).
// =====================================================================
#define NS_XHI 0
#define NS_XLO 17408
#define NS_W   34816
#define NS_B1  69632
#define NS_TOTAL 70656

__global__ void __launch_bounds__(256)
ns_kernel(const uint32_t* __restrict__ xhi, const uint32_t* __restrict__ xlo,
          const unsigned char* __restrict__ w1r, const unsigned char* __restrict__ w1s,
          const float* __restrict__ b1, float* __restrict__ ns)
{
    extern __shared__ char smem[];
    const uint32_t sb = smem_u32(smem);
    const int tid = threadIdx.x, lane = tid & 31, w = tid >> 5;
    const int k = blockIdx.x, b = blockIdx.y;

    for (int t = tid; t < 1024; t += 256) {
        int row = t >> 4, sgi = t & 15;
        size_t so = (size_t)(b * 64 + row) * 64 + sgi * 4;
        cpa16(sb + NS_XHI + row * 272 + sgi * 16, xhi + so);
        cpa16(sb + NS_XLO + row * 272 + sgi * 16, xlo + so);
    }
    CP_COMMIT();
    if (tid < 64) ((float4*)(smem + NS_B1))[tid] = ((const float4*)(b1 + k * 256))[tid];

    const int g = lane >> 2, tg = lane & 3;
    const int arow = lane & 15;
    const uint32_t aoff = (uint32_t)((lane >> 4) << 4);
    const int brow = (lane & 7) + ((lane >> 4) << 3);
    const uint32_t boff = (uint32_t)((lane & 8) << 1);
    const int wm = w & 3, wn = w >> 2;
    const int m0 = wm * 16;
    const float* b1s = (const float*)(smem + NS_B1);
    float* outk = ns + ((size_t)k * BB + b) * 64 * 512;

#pragma unroll 1
    for (int half = 0; half < 2; ++half) {
        const unsigned char* img = half ? w1s : w1r;
#pragma unroll 1
        for (int s = 0; s < 4; ++s) {
            for (int t = tid; t < 2176; t += 256) {
                int im = t >= 1088;
                uint32_t off = (uint32_t)(t - im * 1088) * 16;
                cpa16(sb + NS_W + (im ? 17408 : 0) + off,
                      img + (size_t)((k * 2 + im) * 256 + s * 64) * 272 + off);
            }
            CP_COMMIT(); CP_WAIT0();
            __syncthreads();
            float c[4][4] = {};
#pragma unroll
            for (int sp = 0; sp < 3; ++sp) {
                uint32_t Ab = sb + (sp == 2 ? NS_XLO : NS_XHI) + (m0 + arow) * 272 + aoff;
                uint32_t Bb = sb + NS_W + (sp == 1 ? 17408u : 0u) + (wn * 32 + brow) * 272 + boff;
#pragma unroll
                for (int ks = 0; ks < 8; ++ks) {
                    uint32_t a[4], b0[4], b1f[4];
                    ldm4(Ab + ks * 32, a);
                    ldm4(Bb + ks * 32, b0);
                    ldm4(Bb + 16 * 272 + ks * 32, b1f);
                    mma_bf16(c[0], a, b0[0], b0[1]);
                    mma_bf16(c[1], a, b0[2], b0[3]);
                    mma_bf16(c[2], a, b1f[0], b1f[1]);
                    mma_bf16(c[3], a, b1f[2], b1f[3]);
                }
            }
            int r0 = m0 + g, r1 = r0 + 8;
            int cn = s * 64 + wn * 32;
#pragma unroll
            for (int t = 0; t < 4; ++t) {
                int col = cn + t * 8 + 2 * tg;
                float a0 = half ? 0.f : b1s[col], a1 = half ? 0.f : b1s[col + 1];
                outk[(size_t)r0 * 512 + half * 256 + col]     = c[t][0] + a0;
                outk[(size_t)r0 * 512 + half * 256 + col + 1] = c[t][1] + a1;
                outk[(size_t)r1 * 512 + half * 256 + col]     = c[t][2] + a0;
                outk[(size_t)r1 * 512 + half * 256 + col + 1] = c[t][3] + a1;
            }
            __syncthreads();
        }
    }
}

// ---------------- SMEM map (bytes) for edge kernel ----------------
#define SE_S    0         // 64 rows x 1040 B = 66560
#define SE_W2   66560     // 2 bufs x 16896 (fp16 hi only) = 33792 -> 100352
#define SE_HBS  100352    // 4 nodes x 256 f32 = 4096 -> 104448
#define SE_B2S  104448    // 1024 -> 105472
#define SE_RTS  105472    // 256 rows x 4 f32 = 4096 -> 109568
#define SE_AGG  109568    // 8 x 256 f32 = 8192 -> 117760
#define SE_TOTAL 117760

// =====================================================================
// Edge kernel: block = (4 nodes, batch), 256 threads = 8 warps.
// M = 256 edge rows, 32 rows/warp (2 A fragments).
// Layer 1 = elementwise relu(hbase[recv] + S[send]) -> fp16 A fragments.
// Layer 2 = single fp16 mma (A fp16-rounded, B fp16 hi), B regs shared.
// =====================================================================
__global__ void __launch_bounds__(256, 1)
edge_kernel(const float* __restrict__ rel_type,
            const unsigned char* __restrict__ w2img,
            const float* __restrict__ ns,
            const float* __restrict__ b2,
            float* __restrict__ agg)
{
    extern __shared__ char smem[];
    const uint32_t sb = smem_u32(smem);
    const int tid = threadIdx.x;
    const int lane = tid & 31, w = tid >> 5;
    const int n0 = blockIdx.x * 4, b = blockIdx.y;

    {   // rel_type tile [256 rows][4]
        int node = n0 + (tid >> 6), le = tid & 63;
        float4 v = make_float4(0.f, 0.f, 0.f, 0.f);
        if (le < 63) v = *(const float4*)(rel_type + ((size_t)b * EE + node * 63 + le) * KK);
        *(float4*)(smem + SE_RTS + tid * 16) = v;
    }
    for (int i = tid; i < 2048; i += 256) ((float*)(smem + SE_AGG))[i] = 0.f;

    const int g = lane >> 2, tg = lane & 3;
    const int brow = (lane & 7) + ((lane >> 4) << 3);
    const uint32_t boff = (uint32_t)((lane & 8) << 1);
    const int m0 = w * 32;
    const int nodeg = n0 + (w >> 1);       // this warp's receiver node
    const float* rts = (const float*)(smem + SE_RTS);
    const float* b2s = (const float*)(smem + SE_B2S);
    float* aggS = (float*)(smem + SE_AGG);

    // this warp's 4 row-slots (2 fragments x 2 rows each)
    const int rw[4] = { m0 + g, m0 + g + 8, m0 + g + 16, m0 + g + 24 };
    float msk[4];
    int js[4];
#pragma unroll
    for (int i = 0; i < 4; ++i) {
        int le = rw[i] & 63;
        msk[i] = (le != 63) ? 1.f : 0.f;
        js[i] = (le != 63) ? (le + (le >= nodeg)) : 0;
    }

    uint32_t Ha[64], Hb[64];   // fp16 pairs: frag A rows rw[0],rw[1]; frag B rows rw[2],rw[3]

#pragma unroll 1
    for (int k = 0; k < KK; ++k) {
        __syncthreads();   // prior k consumers done (S buffer, W2 bufs)

        const float* nsk = ns + ((size_t)k * BB + b) * 64 * 512;
        // S rows (all 64 senders, cols 256:512)
        for (int t = tid; t < 4096; t += 256) {
            int row = t >> 6, ch = t & 63;
            cpa16(sb + SE_S + row * 1040 + ch * 16, nsk + (size_t)row * 512 + 256 + ch * 4);
        }
        CP_COMMIT();
        // prefetch W2 slab 0
        for (int t = tid; t < 1056; t += 256)
            cpa16(sb + SE_W2 + t * 16, w2img + (size_t)(k * 256) * 528 + t * 16);
        CP_COMMIT();
        // hbase rows for the 4 receiver nodes + b2
        {
            int row = n0 + (tid >> 6), c4 = (tid & 63) * 4;
            *(float4*)(smem + SE_HBS + tid * 16) = *(const float4*)(nsk + (size_t)row * 512 + c4);
            if (tid < 64)
                ((float4*)(smem + SE_B2S))[tid] = ((const float4*)(b2 + k * 256))[tid];
        }
        CP_WAIT1();        // S complete (W2 slab0 may still be in flight)
        __syncthreads();

        // ---- build H fragments: relu(hbase + S), fp16 ----
        {
            const float* S0 = (const float*)(smem + SE_S) + js[0] * 260;
            const float* S1 = (const float*)(smem + SE_S) + js[1] * 260;
            const float* S2 = (const float*)(smem + SE_S) + js[2] * 260;
            const float* S3 = (const float*)(smem + SE_S) + js[3] * 260;
            const float* hb = (const float*)(smem + SE_HBS) + (w >> 1) * 256;
#pragma unroll
            for (int ks = 0; ks < 16; ++ks) {
                int c = ks * 16 + 2 * tg;
                float2 h0 = *(const float2*)(hb + c);
                float2 h8 = *(const float2*)(hb + c + 8);
                float2 sA0 = *(const float2*)(S0 + c), sA8 = *(const float2*)(S0 + c + 8);
                float2 sB0 = *(const float2*)(S1 + c), sB8 = *(const float2*)(S1 + c + 8);
                float2 sC0 = *(const float2*)(S2 + c), sC8 = *(const float2*)(S2 + c + 8);
                float2 sD0 = *(const float2*)(S3 + c), sD8 = *(const float2*)(S3 + c + 8);
                Ha[ks*4+0] = h2pack(msk[0]*fmaxf(h0.x + sA0.x, 0.f), msk[0]*fmaxf(h0.y + sA0.y, 0.f));
                Ha[ks*4+1] = h2pack(msk[1]*fmaxf(h0.x + sB0.x, 0.f), msk[1]*fmaxf(h0.y + sB0.y, 0.f));
                Ha[ks*4+2] = h2pack(msk[0]*fmaxf(h8.x + sA8.x, 0.f), msk[0]*fmaxf(h8.y + sA8.y, 0.f));
                Ha[ks*4+3] = h2pack(msk[1]*fmaxf(h8.x + sB8.x, 0.f), msk[1]*fmaxf(h8.y + sB8.y, 0.f));
                Hb[ks*4+0] = h2pack(msk[2]*fmaxf(h0.x + sC0.x, 0.f), msk[2]*fmaxf(h0.y + sC0.y, 0.f));
                Hb[ks*4+1] = h2pack(msk[3]*fmaxf(h0.x + sD0.x, 0.f), msk[3]*fmaxf(h0.y + sD0.y, 0.f));
                Hb[ks*4+2] = h2pack(msk[2]*fmaxf(h8.x + sC8.x, 0.f), msk[2]*fmaxf(h8.y + sC8.y, 0.f));
                Hb[ks*4+3] = h2pack(msk[3]*fmaxf(h8.x + sD8.x, 0.f), msk[3]*fmaxf(h8.y + sD8.y, 0.f));
            }
        }

        // ---- layer 2: 8 slabs of 32 m-cols, double-buffered ----
        const float wr0 = rts[rw[0] * 4 + k], wr1 = rts[rw[1] * 4 + k];
        const float wr2 = rts[rw[2] * 4 + k], wr3 = rts[rw[3] * 4 + k];
#pragma unroll 1
        for (int s = 0; s < 8; ++s) {
            CP_WAIT0();        // slab s resident
            __syncthreads();   // all warps done reading the other buffer
            if (s < 7) {
                uint32_t wb = SE_W2 + (uint32_t)(((s + 1) & 1) * 16896);
                for (int t = tid; t < 1056; t += 256)
                    cpa16(sb + wb + t * 16,
                          w2img + (size_t)(k * 256 + (s + 1) * 32) * 528 + t * 16);
                CP_COMMIT();
            }
            const uint32_t wbs = sb + SE_W2 + (uint32_t)((s & 1) * 16896) + brow * 528 + boff;
            float cA[4][4] = {}, cB[4][4] = {};
#pragma unroll
            for (int ks = 0; ks < 16; ++ks) {
                uint32_t b0[4], b1f[4];
                ldm4(wbs + ks * 32, b0);
                ldm4(wbs + 16 * 528 + ks * 32, b1f);
                const uint32_t* aA = Ha + ks * 4;
                const uint32_t* aB = Hb + ks * 4;
                mma_f16(cA[0], aA, b0[0], b0[1]);
                mma_f16(cA[1], aA, b0[2], b0[3]);
                mma_f16(cA[2], aA, b1f[0], b1f[1]);
                mma_f16(cA[3], aA, b1f[2], b1f[3]);
                mma_f16(cB[0], aB, b0[0], b0[1]);
                mma_f16(cB[1], aB, b0[2], b0[3]);
                mma_f16(cB[2], aB, b1f[0], b1f[1]);
                mma_f16(cB[3], aB, b1f[2], b1f[3]);
            }
            // epilogue: relu(D+b2) * rel_type, reduce over this warp's 32 rows
            float p0[4], p1[4];
#pragma unroll
            for (int t = 0; t < 4; ++t) {
                int col = s * 32 + t * 8 + 2 * tg;
                float bc0 = b2s[col], bc1 = b2s[col + 1];
                p0[t] = wr0 * fmaxf(cA[t][0] + bc0, 0.f)
                      + wr1 * fmaxf(cA[t][2] + bc0, 0.f)
                      + wr2 * fmaxf(cB[t][0] + bc0, 0.f)
                      + wr3 * fmaxf(cB[t][2] + bc0, 0.f);
                p1[t] = wr0 * fmaxf(cA[t][1] + bc1, 0.f)
                      + wr1 * fmaxf(cA[t][3] + bc1, 0.f)
                      + wr2 * fmaxf(cB[t][1] + bc1, 0.f)
                      + wr3 * fmaxf(cB[t][3] + bc1, 0.f);
            }
#pragma unroll
            for (int off = 4; off <= 16; off <<= 1)
#pragma unroll
                for (int t = 0; t < 4; ++t) {
                    p0[t] += __shfl_xor_sync(0xffffffff, p0[t], off);
                    p1[t] += __shfl_xor_sync(0xffffffff, p1[t], off);
                }
            if (g == 0) {
#pragma unroll
                for (int t = 0; t < 4; ++t) {
                    int col = s * 32 + t * 8 + 2 * tg;
                    aggS[w * 256 + col]     += p0[t];
                    aggS[w * 256 + col + 1] += p1[t];
                }
            }
        }
    }

    __syncthreads();
    // final reduce: node ni (0..3) = warps 2ni, 2ni+1
    for (int t = tid; t < 1024; t += 256) {
        int ni = t >> 8, m = t & 255;
        agg[((size_t)b * NN + n0 + ni) * 256 + m] =
            aggS[(2 * ni) * 256 + m] + aggS[(2 * ni + 1) * 256 + m];
    }
}

// =====================================================================
// Output MLP 384->256->256->128 + residual (fp32 f32x2), 8 rows/block.
// =====================================================================
#define AUGSTR 388
#define P1STR 260
__device__ __forceinline__ unsigned long long pack2(float x) {
    unsigned long long r; asm("mov.b64 %0, {%1, %1};" : "=l"(r) : "f"(x)); return r;
}
__device__ __forceinline__ unsigned long long packab(float a, float b) {
    unsigned long long r; asm("mov.b64 %0, {%1, %2};" : "=l"(r) : "f"(a), "f"(b)); return r;
}
__device__ __forceinline__ void unpack2(unsigned long long v, float& a, float& b) {
    asm("mov.b64 {%0, %1}, %2;" : "=f"(a), "=f"(b) : "l"(v));
}
__device__ __forceinline__ unsigned long long fma2(unsigned long long a,
                                                   unsigned long long b,
                                                   unsigned long long c) {
    unsigned long long d;
    asm("fma.rn.f32x2 %0, %1, %2, %3;" : "=l"(d) : "l"(a), "l"(b), "l"(c));
    return d;
}

__global__ void __launch_bounds__(128)
out_mlp_kernel(const float* __restrict__ inputs, const float* __restrict__ agg,
               const float* __restrict__ Wo1, const float* __restrict__ bo1,
               const float* __restrict__ Wo2, const float* __restrict__ bo2,
               const float* __restrict__ Wo3, const float* __restrict__ bo3,
               float* __restrict__ out)
{
    extern __shared__ float sm[];
    float* augS = sm;                    // [8][AUGSTR], reused for p2
    float* p1S  = augS + 8 * AUGSTR;     // [8][P1STR]
    float* Wc   = p1S + 8 * P1STR;       // [32][256]

    const int oct = blockIdx.x, b = blockIdx.y;
    const int r0 = oct * 8, tid = threadIdx.x;
    const int cg = tid & 31, er = tid >> 5, col0 = cg << 3;

    for (int idx = tid; idx < 8 * 96; idx += 128) {
        int r = idx / 96, c4 = idx % 96;
        float4 v;
        if (c4 < 32) v = *(const float4*)(inputs + ((size_t)(b * NN) + r0 + r) * FF + (c4 << 2));
        else         v = *(const float4*)(agg + ((size_t)(b * NN) + r0 + r) * 256 + ((c4 - 32) << 2));
        *(float4*)(augS + r * AUGSTR + (c4 << 2)) = v;
    }

    unsigned long long acc[2][4];
    {
        float4 t0 = *(const float4*)(bo1 + col0);
        float4 t1 = *(const float4*)(bo1 + col0 + 4);
        unsigned long long c0 = packab(t0.x, t0.y), c1 = packab(t0.z, t0.w);
        unsigned long long c2 = packab(t1.x, t1.y), c3 = packab(t1.z, t1.w);
#pragma unroll
        for (int i = 0; i < 2; ++i) { acc[i][0]=c0; acc[i][1]=c1; acc[i][2]=c2; acc[i][3]=c3; }
    }
#pragma unroll 1
    for (int fc = 0; fc < 12; ++fc) {
        __syncthreads();
        const float* wsrc = Wo1 + fc * 32 * 256;
        for (int idx = tid; idx < 32 * 64; idx += 128)
            *(float4*)(Wc + ((idx >> 6) << 8) + ((idx & 63) << 2)) =
                *(const float4*)(wsrc + ((idx >> 6) << 8) + ((idx & 63) << 2));
        __syncthreads();
#pragma unroll 8
        for (int f = 0; f < 32; ++f) {
            const float* wrow = Wc + (f << 8) + col0;
            ulonglong2 wA = *(const ulonglong2*)(wrow);
            ulonglong2 wB = *(const ulonglong2*)(wrow + 4);
#pragma unroll
            for (int i = 0; i < 2; ++i) {
                unsigned long long xp = pack2(augS[(er * 2 + i) * AUGSTR + fc * 32 + f]);
                acc[i][0] = fma2(xp, wA.x, acc[i][0]); acc[i][1] = fma2(xp, wA.y, acc[i][1]);
                acc[i][2] = fma2(xp, wB.x, acc[i][2]); acc[i][3] = fma2(xp, wB.y, acc[i][3]);
            }
        }
    }
#pragma unroll
    for (int i = 0; i < 2; ++i) {
        float4 v0, v1;
        unpack2(acc[i][0], v0.x, v0.y); unpack2(acc[i][1], v0.z, v0.w);
        unpack2(acc[i][2], v1.x, v1.y); unpack2(acc[i][3], v1.z, v1.w);
        v0.x=fmaxf(v0.x,0.f); v0.y=fmaxf(v0.y,0.f); v0.z=fmaxf(v0.z,0.f); v0.w=fmaxf(v0.w,0.f);
        v1.x=fmaxf(v1.x,0.f); v1.y=fmaxf(v1.y,0.f); v1.z=fmaxf(v1.z,0.f); v1.w=fmaxf(v1.w,0.f);
        *(float4*)(p1S + (er * 2 + i) * P1STR + col0)     = v0;
        *(float4*)(p1S + (er * 2 + i) * P1STR + col0 + 4) = v1;
    }

    {
        float4 t0 = *(const float4*)(bo2 + col0);
        float4 t1 = *(const float4*)(bo2 + col0 + 4);
        unsigned long long c0 = packab(t0.x, t0.y), c1 = packab(t0.z, t0.w);
        unsigned long long c2 = packab(t1.x, t1.y), c3 = packab(t1.z, t1.w);
#pragma unroll
        for (int i = 0; i < 2; ++i) { acc[i][0]=c0; acc[i][1]=c1; acc[i][2]=c2; acc[i][3]=c3; }
    }
#pragma unroll 1
    for (int fc = 0; fc < 8; ++fc) {
        __syncthreads();
        const float* wsrc = Wo2 + fc * 32 * 256;
        for (int idx = tid; idx < 32 * 64; idx += 128)
            *(float4*)(Wc + ((idx >> 6) << 8) + ((idx & 63) << 2)) =
                *(const float4*)(wsrc + ((idx >> 6) << 8) + ((idx & 63) << 2));
        __syncthreads();
#pragma unroll 8
        for (int f = 0; f < 32; ++f) {
            const float* wrow = Wc + (f << 8) + col0;
            ulonglong2 wA = *(const ulonglong2*)(wrow);
            ulonglong2 wB = *(const ulonglong2*)(wrow + 4);
#pragma unroll
            for (int i = 0; i < 2; ++i) {
                unsigned long long xp = pack2(p1S[(er * 2 + i) * P1STR + fc * 32 + f]);
                acc[i][0] = fma2(xp, wA.x, acc[i][0]); acc[i][1] = fma2(xp, wA.y, acc[i][1]);
                acc[i][2] = fma2(xp, wB.x, acc[i][2]); acc[i][3] = fma2(xp, wB.y, acc[i][3]);
            }
        }
    }
    __syncthreads();
#pragma unroll
    for (int i = 0; i < 2; ++i) {
        float4 v0, v1;
        unpack2(acc[i][0], v0.x, v0.y); unpack2(acc[i][1], v0.z, v0.w);
        unpack2(acc[i][2], v1.x, v1.y); unpack2(acc[i][3], v1.z, v1.w);
        v0.x=fmaxf(v0.x,0.f); v0.y=fmaxf(v0.y,0.f); v0.z=fmaxf(v0.z,0.f); v0.w=fmaxf(v0.w,0.f);
        v1.x=fmaxf(v1.x,0.f); v1.y=fmaxf(v1.y,0.f); v1.z=fmaxf(v1.z,0.f); v1.w=fmaxf(v1.w,0.f);
        *(float4*)(augS + (er * 2 + i) * AUGSTR + col0)     = v0;
        *(float4*)(augS + (er * 2 + i) * AUGSTR + col0 + 4) = v1;
    }

    unsigned long long a3[2][2];
    {
        float4 tb4 = *(const float4*)(bo3 + (cg << 2));
        unsigned long long c0 = packab(tb4.x, tb4.y), c1 = packab(tb4.z, tb4.w);
#pragma unroll
        for (int i = 0; i < 2; ++i) { a3[i][0] = c0; a3[i][1] = c1; }
    }
#pragma unroll 1
    for (int fc = 0; fc < 8; ++fc) {
        __syncthreads();
        const float* wsrc = Wo3 + fc * 32 * 128;
        for (int idx = tid; idx < 32 * 32; idx += 128)
            *(float4*)(Wc + ((idx >> 5) << 7) + ((idx & 31) << 2)) =
                *(const float4*)(wsrc + ((idx >> 5) << 7) + ((idx & 31) << 2));
        __syncthreads();
#pragma unroll 8
        for (int f = 0; f < 32; ++f) {
            const float* wrow = Wc + (f << 7) + (cg << 2);
            ulonglong2 wA = *(const ulonglong2*)(wrow);
#pragma unroll
            for (int i = 0; i < 2; ++i) {
                unsigned long long xp = pack2(augS[(er * 2 + i) * AUGSTR + fc * 32 + f]);
                a3[i][0] = fma2(xp, wA.x, a3[i][0]); a3[i][1] = fma2(xp, wA.y, a3[i][1]);
            }
        }
    }
#pragma unroll
    for (int i = 0; i < 2; ++i) {
        int r = r0 + er * 2 + i;
        float4 res = *(const float4*)(inputs + ((size_t)(b * NN) + r) * FF + (cg << 2));
        float x0, x1;
        unpack2(a3[i][0], x0, x1); res.x += x0; res.y += x1;
        unpack2(a3[i][1], x0, x1); res.z += x0; res.w += x1;
        *(float4*)(out + ((size_t)(b * NN) + r) * FF + (cg << 2)) = res;
    }
}

// =====================================================================
extern "C" void kernel_launch(void* const* d_in, const int* in_sizes, int n_in,
                              void* d_out, int out_size)
{
    const float* inputs   = (const float*)d_in[0];
    const float* rel_type = (const float*)d_in[1];
    const float* W1  = (const float*)d_in[4];
    const float* b1  = (const float*)d_in[5];
    const float* W2  = (const float*)d_in[6];
    const float* b2  = (const float*)d_in[7];
    const float* Wo1 = (const float*)d_in[8];
    const float* bo1 = (const float*)d_in[9];
    const float* Wo2 = (const float*)d_in[10];
    const float* bo2 = (const float*)d_in[11];
    const float* Wo3 = (const float*)d_in[12];
    const float* bo3 = (const float*)d_in[13];
    float* out = (float*)d_out;

    float *agg, *ns;
    unsigned char *w1r, *w1s, *w2i;
    uint32_t *xhi, *xlo;
    cudaGetSymbolAddress((void**)&agg, g_agg);
    cudaGetSymbolAddress((void**)&ns, g_ns);
    cudaGetSymbolAddress((void**)&w1r, g_w1r);
    cudaGetSymbolAddress((void**)&w1s, g_w1s);
    cudaGetSymbolAddress((void**)&w2i, g_w2img);
    cudaGetSymbolAddress((void**)&xhi, g_ximg_hi);
    cudaGetSymbolAddress((void**)&xlo, g_ximg_lo);

    const int smemB = (8 * AUGSTR + 8 * P1STR + 32 * 256) * 4;  // 53504
    cudaFuncSetAttribute(edge_kernel, cudaFuncAttributeMaxDynamicSharedMemorySize, SE_TOTAL);
    cudaFuncSetAttribute(ns_kernel, cudaFuncAttributeMaxDynamicSharedMemorySize, NS_TOTAL);
    cudaFuncSetAttribute(out_mlp_kernel, cudaFuncAttributeMaxDynamicSharedMemorySize, smemB);

    prep_x_kernel<<<BB * NN * 64 / 256, 256>>>(inputs, xhi, xlo);
    prep_w_kernel<<<dim3(4, 8, 4), 256>>>(W1, 0,   w1r, 272);   // recv half of W1 (bf16)
    prep_w_kernel<<<dim3(4, 8, 4), 256>>>(W1, 128, w1s, 272);   // send half of W1 (bf16)
    prep_w2h_kernel<<<dim3(8, 8, 4), 256>>>(W2, w2i);           // W2 fp16 hi
    ns_kernel<<<dim3(KK, BB), 256, NS_TOTAL>>>(xhi, xlo, w1r, w1s, b1, ns);
    edge_kernel<<<dim3(NN / 4, BB), 256, SE_TOTAL>>>(rel_type, w2i, ns, b2, agg);
    out_mlp_kernel<<<dim3(8, BB), 128, smemB>>>(inputs, agg, Wo1, bo1, Wo2, bo2, Wo3, bo3, out);
}

// round 10
// speedup vs baseline: 3.3158x; 1.1660x over previous
#include <cuda_runtime.h>
#include <cuda_bf16.h>
#include <cuda_fp16.h>
#include <cstdint>

#define BB 32
#define NN 64
#define FF 128
#define KK 4
#define EE 4032

// ---------------- static device scratch (no allocations) ----------------
__device__ __align__(16) unsigned char g_w1r[KK * 2 * 256 * 272];   // W1 recv half (bf16 hi/lo)
__device__ __align__(16) unsigned char g_w1s[KK * 2 * 256 * 272];   // W1 send half (bf16 hi/lo)
__device__ __align__(16) unsigned char g_w2img[KK * 256 * 528];     // W2 fp16 HI only
__device__ __align__(16) unsigned char g_wo1[256 * 784];            // Wo1 fp16 image
__device__ __align__(16) unsigned char g_wo2[256 * 528];            // Wo2 fp16 image
__device__ __align__(16) unsigned char g_wo3[128 * 528];            // Wo3 fp16 image
__device__ __align__(16) uint32_t g_ximg_hi[BB * NN * 64];          // node feats bf16 pairs
__device__ __align__(16) uint32_t g_ximg_lo[BB * NN * 64];
__device__ __align__(16) float g_ns[KK * BB * NN * 512];            // [k][b][node][512]: hbase|S
__device__ float g_agg[BB * NN * 256];                              // 2 MB

// ---------------- helpers ----------------
__device__ __forceinline__ uint32_t smem_u32(const void* p) {
    uint32_t a;
    asm("{ .reg .u64 t; cvta.to.shared.u64 t, %1; cvt.u32.u64 %0, t; }" : "=r"(a) : "l"(p));
    return a;
}
__device__ __forceinline__ void split2(float2 v, uint32_t& hi, uint32_t& lo) {  // bf16
    __nv_bfloat162 h2 = __float22bfloat162_rn(v);
    float2 r = make_float2(v.x - __bfloat162float(h2.x), v.y - __bfloat162float(h2.y));
    __nv_bfloat162 l2 = __float22bfloat162_rn(r);
    hi = reinterpret_cast<uint32_t&>(h2);
    lo = reinterpret_cast<uint32_t&>(l2);
}
__device__ __forceinline__ uint32_t h2pack(float a, float b) {
    __half2 h = __float22half2_rn(make_float2(a, b));
    return reinterpret_cast<uint32_t&>(h);
}
__device__ __forceinline__ void ldm4(uint32_t addr, uint32_t r[4]) {
    asm volatile("ldmatrix.sync.aligned.m8n8.x4.shared.b16 {%0,%1,%2,%3}, [%4];"
                 : "=r"(r[0]), "=r"(r[1]), "=r"(r[2]), "=r"(r[3]) : "r"(addr));
}
__device__ __forceinline__ void mma_bf16(float* c, const uint32_t* a, uint32_t b0, uint32_t b1) {
    asm volatile(
        "mma.sync.aligned.m16n8k16.row.col.f32.bf16.bf16.f32 "
        "{%0,%1,%2,%3}, {%4,%5,%6,%7}, {%8,%9}, {%0,%1,%2,%3};"
        : "+f"(c[0]), "+f"(c[1]), "+f"(c[2]), "+f"(c[3])
        : "r"(a[0]), "r"(a[1]), "r"(a[2]), "r"(a[3]), "r"(b0), "r"(b1));
}
__device__ __forceinline__ void mma_f16(float* c, const uint32_t* a, uint32_t b0, uint32_t b1) {
    asm volatile(
        "mma.sync.aligned.m16n8k16.row.col.f32.f16.f16.f32 "
        "{%0,%1,%2,%3}, {%4,%5,%6,%7}, {%8,%9}, {%0,%1,%2,%3};"
        : "+f"(c[0]), "+f"(c[1]), "+f"(c[2]), "+f"(c[3])
        : "r"(a[0]), "r"(a[1]), "r"(a[2]), "r"(a[3]), "r"(b0), "r"(b1));
}
__device__ __forceinline__ void cpa16(uint32_t dst, const void* src) {
    asm volatile("cp.async.cg.shared.global [%0], [%1], 16;" :: "r"(dst), "l"(src));
}
#define CP_COMMIT() asm volatile("cp.async.commit_group;" ::: "memory")
#define CP_WAIT0()  asm volatile("cp.async.wait_group 0;" ::: "memory")
#define CP_WAIT1()  asm volatile("cp.async.wait_group 1;" ::: "memory")

// =====================================================================
// Prep kernels
// =====================================================================
__global__ void __launch_bounds__(256)
prep_w_kernel(const float* __restrict__ W, int koff, unsigned char* __restrict__ img, int rstride)
{
    __shared__ float ts[32][33];
    const int f0 = blockIdx.x * 32, nn0 = blockIdx.y * 32, kt = blockIdx.z;
    const int tid = threadIdx.x;
    const float* Wk = W + (size_t)kt * 65536;
#pragma unroll
    for (int p = 0; p < 4; ++p) {
        int fr = (tid >> 5) + p * 8, nl = tid & 31;
        ts[fr][nl] = Wk[(size_t)(koff + f0 + fr) * 256 + nn0 + nl];
    }
    __syncthreads();
#pragma unroll
    for (int p = 0; p < 2; ++p) {
        int idx = tid + p * 256;
        int nr = idx >> 4, wp = idx & 15;
        uint32_t hi, lo;
        split2(make_float2(ts[2 * wp][nr], ts[2 * wp + 1][nr]), hi, lo);
        size_t rb = (size_t)(nn0 + nr) * rstride + (f0 + 2 * wp) * 2;
        *(uint32_t*)(img + (size_t)(kt * 2 + 0) * 256 * rstride + rb) = hi;
        *(uint32_t*)(img + (size_t)(kt * 2 + 1) * 256 * rstride + rb) = lo;
    }
}

__global__ void __launch_bounds__(256)
prep_w2h_kernel(const float* __restrict__ W, unsigned char* __restrict__ img)
{
    __shared__ float ts[32][33];
    const int f0 = blockIdx.x * 32, nn0 = blockIdx.y * 32, kt = blockIdx.z;
    const int tid = threadIdx.x;
    const float* Wk = W + (size_t)kt * 65536;
#pragma unroll
    for (int p = 0; p < 4; ++p) {
        int fr = (tid >> 5) + p * 8, nl = tid & 31;
        ts[fr][nl] = Wk[(size_t)(f0 + fr) * 256 + nn0 + nl];
    }
    __syncthreads();
#pragma unroll
    for (int p = 0; p < 2; ++p) {
        int idx = tid + p * 256;
        int nr = idx >> 4, wp = idx & 15;
        *(uint32_t*)(img + (size_t)(kt * 256 + nn0 + nr) * 528 + (f0 + 2 * wp) * 2) =
            h2pack(ts[2 * wp][nr], ts[2 * wp + 1][nr]);
    }
}

// generic Wo prep: W[f][n] (row-major, Ncols) -> img[n][f] fp16, row stride bytes
__global__ void __launch_bounds__(256)
prep_wo_kernel(const float* __restrict__ W, unsigned char* __restrict__ img, int Ncols, int rstride)
{
    __shared__ float ts[32][33];
    const int f0 = blockIdx.x * 32, nn0 = blockIdx.y * 32;
    const int tid = threadIdx.x;
#pragma unroll
    for (int p = 0; p < 4; ++p) {
        int fr = (tid >> 5) + p * 8, nl = tid & 31;
        ts[fr][nl] = W[(size_t)(f0 + fr) * Ncols + nn0 + nl];
    }
    __syncthreads();
#pragma unroll
    for (int p = 0; p < 2; ++p) {
        int idx = tid + p * 256;
        int nr = idx >> 4, wp = idx & 15;
        *(uint32_t*)(img + (size_t)(nn0 + nr) * rstride + (f0 + 2 * wp) * 2) =
            h2pack(ts[2 * wp][nr], ts[2 * wp + 1][nr]);
    }
}

__global__ void __launch_bounds__(256)
prep_x_kernel(const float* __restrict__ inputs, uint32_t* __restrict__ xhi, uint32_t* __restrict__ xlo)
{
    int idx = blockIdx.x * 256 + threadIdx.x;
    float2 v = ((const float2*)inputs)[idx];
    uint32_t hi, lo;
    split2(v, hi, lo);
    xhi[idx] = hi;
    xlo[idx] = lo;
}

// =====================================================================
// ns_kernel: per (k,b,half) node GEMM [64x128]@[128x256] (3-split bf16).
// half 0 -> cols 0:256 = x@W1_recv + b1 (hbase); half 1 -> 256:512 = x@W1_send.
// =====================================================================
#define NS_XHI 0
#define NS_XLO 17408
#define NS_W   34816
#define NS_B1  69632
#define NS_TOTAL 70656

__global__ void __launch_bounds__(256)
ns_kernel(const uint32_t* __restrict__ xhi, const uint32_t* __restrict__ xlo,
          const unsigned char* __restrict__ w1r, const unsigned char* __restrict__ w1s,
          const float* __restrict__ b1, float* __restrict__ ns)
{
    extern __shared__ char smem[];
    const uint32_t sb = smem_u32(smem);
    const int tid = threadIdx.x, lane = tid & 31, w = tid >> 5;
    const int k = blockIdx.x, b = blockIdx.y, half = blockIdx.z;

    for (int t = tid; t < 1024; t += 256) {
        int row = t >> 4, sgi = t & 15;
        size_t so = (size_t)(b * 64 + row) * 64 + sgi * 4;
        cpa16(sb + NS_XHI + row * 272 + sgi * 16, xhi + so);
        cpa16(sb + NS_XLO + row * 272 + sgi * 16, xlo + so);
    }
    CP_COMMIT();
    if (tid < 64) ((float4*)(smem + NS_B1))[tid] = ((const float4*)(b1 + k * 256))[tid];

    const int g = lane >> 2, tg = lane & 3;
    const int arow = lane & 15;
    const uint32_t aoff = (uint32_t)((lane >> 4) << 4);
    const int brow = (lane & 7) + ((lane >> 4) << 3);
    const uint32_t boff = (uint32_t)((lane & 8) << 1);
    const int wm = w & 3, wn = w >> 2;
    const int m0 = wm * 16;
    const float* b1s = (const float*)(smem + NS_B1);
    float* outk = ns + ((size_t)k * BB + b) * 64 * 512;
    const unsigned char* img = half ? w1s : w1r;

#pragma unroll 1
    for (int s = 0; s < 4; ++s) {
        for (int t = tid; t < 2176; t += 256) {
            int im = t >= 1088;
            uint32_t off = (uint32_t)(t - im * 1088) * 16;
            cpa16(sb + NS_W + (im ? 17408 : 0) + off,
                  img + (size_t)((k * 2 + im) * 256 + s * 64) * 272 + off);
        }
        CP_COMMIT(); CP_WAIT0();
        __syncthreads();
        float c[4][4] = {};
#pragma unroll
        for (int sp = 0; sp < 3; ++sp) {
            uint32_t Ab = sb + (sp == 2 ? NS_XLO : NS_XHI) + (m0 + arow) * 272 + aoff;
            uint32_t Bb = sb + NS_W + (sp == 1 ? 17408u : 0u) + (wn * 32 + brow) * 272 + boff;
#pragma unroll
            for (int ks = 0; ks < 8; ++ks) {
                uint32_t a[4], b0[4], b1f[4];
                ldm4(Ab + ks * 32, a);
                ldm4(Bb + ks * 32, b0);
                ldm4(Bb + 16 * 272 + ks * 32, b1f);
                mma_bf16(c[0], a, b0[0], b0[1]);
                mma_bf16(c[1], a, b0[2], b0[3]);
                mma_bf16(c[2], a, b1f[0], b1f[1]);
                mma_bf16(c[3], a, b1f[2], b1f[3]);
            }
        }
        int r0 = m0 + g, r1 = r0 + 8;
        int cn = s * 64 + wn * 32;
#pragma unroll
        for (int t = 0; t < 4; ++t) {
            int col = cn + t * 8 + 2 * tg;
            float a0 = half ? 0.f : b1s[col], a1 = half ? 0.f : b1s[col + 1];
            outk[(size_t)r0 * 512 + half * 256 + col]     = c[t][0] + a0;
            outk[(size_t)r0 * 512 + half * 256 + col + 1] = c[t][1] + a1;
            outk[(size_t)r1 * 512 + half * 256 + col]     = c[t][2] + a0;
            outk[(size_t)r1 * 512 + half * 256 + col + 1] = c[t][3] + a1;
        }
        __syncthreads();
    }
}

// ---------------- SMEM map (bytes) for edge kernel ----------------
#define SE_S    0         // 64 rows x 1040 B = 66560
#define SE_W2   66560     // 2 bufs x 16896 = 33792 -> 100352
#define SE_HBS  100352    // 4096 -> 104448
#define SE_B2S  104448    // 1024 -> 105472
#define SE_RTS  105472    // 4096 -> 109568
#define SE_AGG  109568    // 8192 -> 117760
#define SE_TOTAL 117760

// =====================================================================
// Edge kernel (unchanged from R9 — at mma.sync roofline).
// =====================================================================
__global__ void __launch_bounds__(256, 1)
edge_kernel(const float* __restrict__ rel_type,
            const unsigned char* __restrict__ w2img,
            const float* __restrict__ ns,
            const float* __restrict__ b2,
            float* __restrict__ agg)
{
    extern __shared__ char smem[];
    const uint32_t sb = smem_u32(smem);
    const int tid = threadIdx.x;
    const int lane = tid & 31, w = tid >> 5;
    const int n0 = blockIdx.x * 4, b = blockIdx.y;

    {
        int node = n0 + (tid >> 6), le = tid & 63;
        float4 v = make_float4(0.f, 0.f, 0.f, 0.f);
        if (le < 63) v = *(const float4*)(rel_type + ((size_t)b * EE + node * 63 + le) * KK);
        *(float4*)(smem + SE_RTS + tid * 16) = v;
    }
    for (int i = tid; i < 2048; i += 256) ((float*)(smem + SE_AGG))[i] = 0.f;

    const int g = lane >> 2, tg = lane & 3;
    const int brow = (lane & 7) + ((lane >> 4) << 3);
    const uint32_t boff = (uint32_t)((lane & 8) << 1);
    const int m0 = w * 32;
    const int nodeg = n0 + (w >> 1);
    const float* rts = (const float*)(smem + SE_RTS);
    const float* b2s = (const float*)(smem + SE_B2S);
    float* aggS = (float*)(smem + SE_AGG);

    const int rw[4] = { m0 + g, m0 + g + 8, m0 + g + 16, m0 + g + 24 };
    float msk[4];
    int js[4];
#pragma unroll
    for (int i = 0; i < 4; ++i) {
        int le = rw[i] & 63;
        msk[i] = (le != 63) ? 1.f : 0.f;
        js[i] = (le != 63) ? (le + (le >= nodeg)) : 0;
    }

    uint32_t Ha[64], Hb[64];

#pragma unroll 1
    for (int k = 0; k < KK; ++k) {
        __syncthreads();

        const float* nsk = ns + ((size_t)k * BB + b) * 64 * 512;
        for (int t = tid; t < 4096; t += 256) {
            int row = t >> 6, ch = t & 63;
            cpa16(sb + SE_S + row * 1040 + ch * 16, nsk + (size_t)row * 512 + 256 + ch * 4);
        }
        CP_COMMIT();
        for (int t = tid; t < 1056; t += 256)
            cpa16(sb + SE_W2 + t * 16, w2img + (size_t)(k * 256) * 528 + t * 16);
        CP_COMMIT();
        {
            int row = n0 + (tid >> 6), c4 = (tid & 63) * 4;
            *(float4*)(smem + SE_HBS + tid * 16) = *(const float4*)(nsk + (size_t)row * 512 + c4);
            if (tid < 64)
                ((float4*)(smem + SE_B2S))[tid] = ((const float4*)(b2 + k * 256))[tid];
        }
        CP_WAIT1();
        __syncthreads();

        {
            const float* S0 = (const float*)(smem + SE_S) + js[0] * 260;
            const float* S1 = (const float*)(smem + SE_S) + js[1] * 260;
            const float* S2 = (const float*)(smem + SE_S) + js[2] * 260;
            const float* S3 = (const float*)(smem + SE_S) + js[3] * 260;
            const float* hb = (const float*)(smem + SE_HBS) + (w >> 1) * 256;
#pragma unroll
            for (int ks = 0; ks < 16; ++ks) {
                int c = ks * 16 + 2 * tg;
                float2 h0 = *(const float2*)(hb + c);
                float2 h8 = *(const float2*)(hb + c + 8);
                float2 sA0 = *(const float2*)(S0 + c), sA8 = *(const float2*)(S0 + c + 8);
                float2 sB0 = *(const float2*)(S1 + c), sB8 = *(const float2*)(S1 + c + 8);
                float2 sC0 = *(const float2*)(S2 + c), sC8 = *(const float2*)(S2 + c + 8);
                float2 sD0 = *(const float2*)(S3 + c), sD8 = *(const float2*)(S3 + c + 8);
                Ha[ks*4+0] = h2pack(msk[0]*fmaxf(h0.x + sA0.x, 0.f), msk[0]*fmaxf(h0.y + sA0.y, 0.f));
                Ha[ks*4+1] = h2pack(msk[1]*fmaxf(h0.x + sB0.x, 0.f), msk[1]*fmaxf(h0.y + sB0.y, 0.f));
                Ha[ks*4+2] = h2pack(msk[0]*fmaxf(h8.x + sA8.x, 0.f), msk[0]*fmaxf(h8.y + sA8.y, 0.f));
                Ha[ks*4+3] = h2pack(msk[1]*fmaxf(h8.x + sB8.x, 0.f), msk[1]*fmaxf(h8.y + sB8.y, 0.f));
                Hb[ks*4+0] = h2pack(msk[2]*fmaxf(h0.x + sC0.x, 0.f), msk[2]*fmaxf(h0.y + sC0.y, 0.f));
                Hb[ks*4+1] = h2pack(msk[3]*fmaxf(h0.x + sD0.x, 0.f), msk[3]*fmaxf(h0.y + sD0.y, 0.f));
                Hb[ks*4+2] = h2pack(msk[2]*fmaxf(h8.x + sC8.x, 0.f), msk[2]*fmaxf(h8.y + sC8.y, 0.f));
                Hb[ks*4+3] = h2pack(msk[3]*fmaxf(h8.x + sD8.x, 0.f), msk[3]*fmaxf(h8.y + sD8.y, 0.f));
            }
        }

        const float wr0 = rts[rw[0] * 4 + k], wr1 = rts[rw[1] * 4 + k];
        const float wr2 = rts[rw[2] * 4 + k], wr3 = rts[rw[3] * 4 + k];
#pragma unroll 1
        for (int s = 0; s < 8; ++s) {
            CP_WAIT0();
            __syncthreads();
            if (s < 7) {
                uint32_t wb = SE_W2 + (uint32_t)(((s + 1) & 1) * 16896);
                for (int t = tid; t < 1056; t += 256)
                    cpa16(sb + wb + t * 16,
                          w2img + (size_t)(k * 256 + (s + 1) * 32) * 528 + t * 16);
                CP_COMMIT();
            }
            const uint32_t wbs = sb + SE_W2 + (uint32_t)((s & 1) * 16896) + brow * 528 + boff;
            float cA[4][4] = {}, cB[4][4] = {};
#pragma unroll
            for (int ks = 0; ks < 16; ++ks) {
                uint32_t b0[4], b1f[4];
                ldm4(wbs + ks * 32, b0);
                ldm4(wbs + 16 * 528 + ks * 32, b1f);
                const uint32_t* aA = Ha + ks * 4;
                const uint32_t* aB = Hb + ks * 4;
                mma_f16(cA[0], aA, b0[0], b0[1]);
                mma_f16(cA[1], aA, b0[2], b0[3]);
                mma_f16(cA[2], aA, b1f[0], b1f[1]);
                mma_f16(cA[3], aA, b1f[2], b1f[3]);
                mma_f16(cB[0], aB, b0[0], b0[1]);
                mma_f16(cB[1], aB, b0[2], b0[3]);
                mma_f16(cB[2], aB, b1f[0], b1f[1]);
                mma_f16(cB[3], aB, b1f[2], b1f[3]);
            }
            float p0[4], p1[4];
#pragma unroll
            for (int t = 0; t < 4; ++t) {
                int col = s * 32 + t * 8 + 2 * tg;
                float bc0 = b2s[col], bc1 = b2s[col + 1];
                p0[t] = wr0 * fmaxf(cA[t][0] + bc0, 0.f)
                      + wr1 * fmaxf(cA[t][2] + bc0, 0.f)
                      + wr2 * fmaxf(cB[t][0] + bc0, 0.f)
                      + wr3 * fmaxf(cB[t][2] + bc0, 0.f);
                p1[t] = wr0 * fmaxf(cA[t][1] + bc1, 0.f)
                      + wr1 * fmaxf(cA[t][3] + bc1, 0.f)
                      + wr2 * fmaxf(cB[t][1] + bc1, 0.f)
                      + wr3 * fmaxf(cB[t][3] + bc1, 0.f);
            }
#pragma unroll
            for (int off = 4; off <= 16; off <<= 1)
#pragma unroll
                for (int t = 0; t < 4; ++t) {
                    p0[t] += __shfl_xor_sync(0xffffffff, p0[t], off);
                    p1[t] += __shfl_xor_sync(0xffffffff, p1[t], off);
                }
            if (g == 0) {
#pragma unroll
                for (int t = 0; t < 4; ++t) {
                    int col = s * 32 + t * 8 + 2 * tg;
                    aggS[w * 256 + col]     += p0[t];
                    aggS[w * 256 + col + 1] += p1[t];
                }
            }
        }
    }

    __syncthreads();
    for (int t = tid; t < 1024; t += 256) {
        int ni = t >> 8, m = t & 255;
        agg[((size_t)b * NN + n0 + ni) * 256 + m] =
            aggS[(2 * ni) * 256 + m] + aggS[(2 * ni + 1) * 256 + m];
    }
}

// =====================================================================
// Output MLP, tensor-core fp16: 64 rows/block, grid 32.
// aug(fp16) @ Wo1 -> p1(fp16) @ Wo2 -> p2(fp16) @ Wo3 + residual.
// =====================================================================
#define OM_A0 0          // 64 x 784 = 50176 (aug, later p2 at stride 528)
#define OM_A1 50176      // 64 x 528 = 33792 -> 83968
#define OM_W  83968      // 2 x 50176 -> 184320
#define OM_TOTAL 184320

__global__ void __launch_bounds__(256, 1)
out_tc_kernel(const float* __restrict__ inputs, const float* __restrict__ agg,
              const unsigned char* __restrict__ wo1, const unsigned char* __restrict__ wo2,
              const unsigned char* __restrict__ wo3,
              const float* __restrict__ bo1, const float* __restrict__ bo2,
              const float* __restrict__ bo3, float* __restrict__ out)
{
    extern __shared__ char smem[];
    const uint32_t sb = smem_u32(smem);
    const int tid = threadIdx.x, lane = tid & 31, w = tid >> 5;
    const int row0 = blockIdx.x * 64;

    const int g = lane >> 2, tg = lane & 3;
    const int arow = lane & 15;
    const uint32_t aoff = (uint32_t)((lane >> 4) << 4);
    const int brow = (lane & 7) + ((lane >> 4) << 3);
    const uint32_t boff = (uint32_t)((lane & 8) << 1);
    const int wm = w & 3, wn = w >> 2;
    const int m0 = wm * 16;
    const int r0 = m0 + g, r1 = r0 + 8;

    // build aug fp16 in A0 (cols 0..127 inputs, 128..383 agg)
    for (int idx = tid; idx < 64 * 192; idx += 256) {
        int r = idx / 192, pc = idx % 192;
        float2 v;
        if (pc < 64) v = *(const float2*)(inputs + (size_t)(row0 + r) * FF + pc * 2);
        else         v = *(const float2*)(agg + (size_t)(row0 + r) * 256 + (pc - 64) * 2);
        *(uint32_t*)(smem + OM_A0 + r * 784 + pc * 4) = h2pack(v.x, v.y);
    }
    // prefetch Wo1 slab 0 (64 n-rows x 784 B)
    for (int t = tid; t < 3136; t += 256)
        cpa16(sb + OM_W + t * 16, wo1 + (size_t)t * 16);
    CP_COMMIT();
    __syncthreads();

    // ---- layer 1: K=384 (24 ks), N=256 (4 slabs), relu -> A1 (stride 528) ----
#pragma unroll 1
    for (int s = 0; s < 4; ++s) {
        CP_WAIT0();
        __syncthreads();
        if (s < 3) {
            uint32_t wb = OM_W + (uint32_t)(((s + 1) & 1) * 50176);
            for (int t = tid; t < 3136; t += 256)
                cpa16(sb + wb + t * 16, wo1 + (size_t)((s + 1) * 64) * 784 + t * 16);
            CP_COMMIT();
        }
        const uint32_t wbs = sb + OM_W + (uint32_t)((s & 1) * 50176) + (wn * 32 + brow) * 784 + boff;
        const uint32_t Ab = sb + OM_A0 + (m0 + arow) * 784 + aoff;
        float c[4][4] = {};
#pragma unroll
        for (int ks = 0; ks < 24; ++ks) {
            uint32_t a[4], b0[4], b1f[4];
            ldm4(Ab + ks * 32, a);
            ldm4(wbs + ks * 32, b0);
            ldm4(wbs + 16 * 784 + ks * 32, b1f);
            mma_f16(c[0], a, b0[0], b0[1]);
            mma_f16(c[1], a, b0[2], b0[3]);
            mma_f16(c[2], a, b1f[0], b1f[1]);
            mma_f16(c[3], a, b1f[2], b1f[3]);
        }
#pragma unroll
        for (int t = 0; t < 4; ++t) {
            int col = s * 64 + wn * 32 + t * 8 + 2 * tg;
            float bc0 = bo1[col], bc1 = bo1[col + 1];
            *(uint32_t*)(smem + OM_A1 + r0 * 528 + col * 2) =
                h2pack(fmaxf(c[t][0] + bc0, 0.f), fmaxf(c[t][1] + bc1, 0.f));
            *(uint32_t*)(smem + OM_A1 + r1 * 528 + col * 2) =
                h2pack(fmaxf(c[t][2] + bc0, 0.f), fmaxf(c[t][3] + bc1, 0.f));
        }
    }
    __syncthreads();
    // prefetch Wo2 slab 0
    for (int t = tid; t < 2112; t += 256)
        cpa16(sb + OM_W + t * 16, wo2 + (size_t)t * 16);
    CP_COMMIT();

    // ---- layer 2: K=256 (16 ks), N=256 (4 slabs), relu -> A0 (stride 528) ----
#pragma unroll 1
    for (int s = 0; s < 4; ++s) {
        CP_WAIT0();
        __syncthreads();
        if (s < 3) {
            uint32_t wb = OM_W + (uint32_t)(((s + 1) & 1) * 50176);
            for (int t = tid; t < 2112; t += 256)
                cpa16(sb + wb + t * 16, wo2 + (size_t)((s + 1) * 64) * 528 + t * 16);
            CP_COMMIT();
        }
        const uint32_t wbs = sb + OM_W + (uint32_t)((s & 1) * 50176) + (wn * 32 + brow) * 528 + boff;
        const uint32_t Ab = sb + OM_A1 + (m0 + arow) * 528 + aoff;
        float c[4][4] = {};
#pragma unroll
        for (int ks = 0; ks < 16; ++ks) {
            uint32_t a[4], b0[4], b1f[4];
            ldm4(Ab + ks * 32, a);
            ldm4(wbs + ks * 32, b0);
            ldm4(wbs + 16 * 528 + ks * 32, b1f);
            mma_f16(c[0], a, b0[0], b0[1]);
            mma_f16(c[1], a, b0[2], b0[3]);
            mma_f16(c[2], a, b1f[0], b1f[1]);
            mma_f16(c[3], a, b1f[2], b1f[3]);
        }
#pragma unroll
        for (int t = 0; t < 4; ++t) {
            int col = s * 64 + wn * 32 + t * 8 + 2 * tg;
            float bc0 = bo2[col], bc1 = bo2[col + 1];
            *(uint32_t*)(smem + OM_A0 + r0 * 528 + col * 2) =
                h2pack(fmaxf(c[t][0] + bc0, 0.f), fmaxf(c[t][1] + bc1, 0.f));
            *(uint32_t*)(smem + OM_A0 + r1 * 528 + col * 2) =
                h2pack(fmaxf(c[t][2] + bc0, 0.f), fmaxf(c[t][3] + bc1, 0.f));
        }
    }
    __syncthreads();
    // prefetch Wo3 slab 0
    for (int t = tid; t < 2112; t += 256)
        cpa16(sb + OM_W + t * 16, wo3 + (size_t)t * 16);
    CP_COMMIT();

    // ---- layer 3: K=256 (16 ks), N=128 (2 slabs), + residual -> out ----
#pragma unroll 1
    for (int s = 0; s < 2; ++s) {
        CP_WAIT0();
        __syncthreads();
        if (s < 1) {
            uint32_t wb = OM_W + 50176u;
            for (int t = tid; t < 2112; t += 256)
                cpa16(sb + wb + t * 16, wo3 + (size_t)64 * 528 + t * 16);
            CP_COMMIT();
        }
        const uint32_t wbs = sb + OM_W + (uint32_t)((s & 1) * 50176) + (wn * 32 + brow) * 528 + boff;
        const uint32_t Ab = sb + OM_A0 + (m0 + arow) * 528 + aoff;
        float c[4][4] = {};
#pragma unroll
        for (int ks = 0; ks < 16; ++ks) {
            uint32_t a[4], b0[4], b1f[4];
            ldm4(Ab + ks * 32, a);
            ldm4(wbs + ks * 32, b0);
            ldm4(wbs + 16 * 528 + ks * 32, b1f);
            mma_f16(c[0], a, b0[0], b0[1]);
            mma_f16(c[1], a, b0[2], b0[3]);
            mma_f16(c[2], a, b1f[0], b1f[1]);
            mma_f16(c[3], a, b1f[2], b1f[3]);
        }
#pragma unroll
        for (int t = 0; t < 4; ++t) {
            int col = s * 64 + wn * 32 + t * 8 + 2 * tg;
            float bc0 = bo3[col], bc1 = bo3[col + 1];
            float2 e0 = *(const float2*)(inputs + (size_t)(row0 + r0) * FF + col);
            float2 e1 = *(const float2*)(inputs + (size_t)(row0 + r1) * FF + col);
            float2 o0 = make_float2(e0.x + c[t][0] + bc0, e0.y + c[t][1] + bc1);
            float2 o1 = make_float2(e1.x + c[t][2] + bc0, e1.y + c[t][3] + bc1);
            *(float2*)(out + (size_t)(row0 + r0) * FF + col) = o0;
            *(float2*)(out + (size_t)(row0 + r1) * FF + col) = o1;
        }
    }
}

// =====================================================================
extern "C" void kernel_launch(void* const* d_in, const int* in_sizes, int n_in,
                              void* d_out, int out_size)
{
    const float* inputs   = (const float*)d_in[0];
    const float* rel_type = (const float*)d_in[1];
    const float* W1  = (const float*)d_in[4];
    const float* b1  = (const float*)d_in[5];
    const float* W2  = (const float*)d_in[6];
    const float* b2  = (const float*)d_in[7];
    const float* Wo1 = (const float*)d_in[8];
    const float* bo1 = (const float*)d_in[9];
    const float* Wo2 = (const float*)d_in[10];
    const float* bo2 = (const float*)d_in[11];
    const float* Wo3 = (const float*)d_in[12];
    const float* bo3 = (const float*)d_in[13];
    float* out = (float*)d_out;

    float *agg, *ns;
    unsigned char *w1r, *w1s, *w2i, *wo1i, *wo2i, *wo3i;
    uint32_t *xhi, *xlo;
    cudaGetSymbolAddress((void**)&agg, g_agg);
    cudaGetSymbolAddress((void**)&ns, g_ns);
    cudaGetSymbolAddress((void**)&w1r, g_w1r);
    cudaGetSymbolAddress((void**)&w1s, g_w1s);
    cudaGetSymbolAddress((void**)&w2i, g_w2img);
    cudaGetSymbolAddress((void**)&wo1i, g_wo1);
    cudaGetSymbolAddress((void**)&wo2i, g_wo2);
    cudaGetSymbolAddress((void**)&wo3i, g_wo3);
    cudaGetSymbolAddress((void**)&xhi, g_ximg_hi);
    cudaGetSymbolAddress((void**)&xlo, g_ximg_lo);

    cudaFuncSetAttribute(edge_kernel, cudaFuncAttributeMaxDynamicSharedMemorySize, SE_TOTAL);
    cudaFuncSetAttribute(ns_kernel, cudaFuncAttributeMaxDynamicSharedMemorySize, NS_TOTAL);
    cudaFuncSetAttribute(out_tc_kernel, cudaFuncAttributeMaxDynamicSharedMemorySize, OM_TOTAL);

    prep_x_kernel<<<BB * NN * 64 / 256, 256>>>(inputs, xhi, xlo);
    prep_w_kernel<<<dim3(4, 8, 4), 256>>>(W1, 0,   w1r, 272);
    prep_w_kernel<<<dim3(4, 8, 4), 256>>>(W1, 128, w1s, 272);
    prep_w2h_kernel<<<dim3(8, 8, 4), 256>>>(W2, w2i);
    prep_wo_kernel<<<dim3(12, 8), 256>>>(Wo1, wo1i, 256, 784);
    prep_wo_kernel<<<dim3(8, 8), 256>>>(Wo2, wo2i, 256, 528);
    prep_wo_kernel<<<dim3(8, 4), 256>>>(Wo3, wo3i, 128, 528);
    ns_kernel<<<dim3(KK, BB, 2), 256, NS_TOTAL>>>(xhi, xlo, w1r, w1s, b1, ns);
    edge_kernel<<<dim3(NN / 4, BB), 256, SE_TOTAL>>>(rel_type, w2i, ns, b2, agg);
    out_tc_kernel<<<BB * NN / 64, 256, OM_TOTAL>>>(inputs, agg, wo1i, wo2i, wo3i,
                                                   bo1, bo2, bo3, out);
}

// round 11
// speedup vs baseline: 3.3772x; 1.0185x over previous
#include <cuda_runtime.h>
#include <cuda_bf16.h>
#include <cuda_fp16.h>
#include <cstdint>

#define BB 32
#define NN 64
#define FF 128
#define KK 4
#define EE 4032

// ---------------- static device scratch (no allocations) ----------------
__device__ __align__(16) unsigned char g_w1r[KK * 2 * 256 * 272];   // W1 recv half (bf16 hi/lo)
__device__ __align__(16) unsigned char g_w1s[KK * 2 * 256 * 272];   // W1 send half (bf16 hi/lo)
__device__ __align__(16) unsigned char g_w2img[KK * 256 * 528];     // W2 fp16 HI only
__device__ __align__(16) unsigned char g_wo1[256 * 784];            // Wo1 fp16 image
__device__ __align__(16) unsigned char g_wo2[256 * 528];            // Wo2 fp16 image
__device__ __align__(16) unsigned char g_wo3[128 * 528];            // Wo3 fp16 image
__device__ __align__(16) uint32_t g_ximg_hi[BB * NN * 64];          // node feats bf16 pairs
__device__ __align__(16) uint32_t g_ximg_lo[BB * NN * 64];
__device__ __align__(16) float g_ns[KK * BB * NN * 512];            // [k][b][node][512]: hbase|S
__device__ float g_agg[BB * NN * 256];                              // 2 MB

// ---------------- helpers ----------------
__device__ __forceinline__ uint32_t smem_u32(const void* p) {
    uint32_t a;
    asm("{ .reg .u64 t; cvta.to.shared.u64 t, %1; cvt.u32.u64 %0, t; }" : "=r"(a) : "l"(p));
    return a;
}
__device__ __forceinline__ void split2(float2 v, uint32_t& hi, uint32_t& lo) {  // bf16
    __nv_bfloat162 h2 = __float22bfloat162_rn(v);
    float2 r = make_float2(v.x - __bfloat162float(h2.x), v.y - __bfloat162float(h2.y));
    __nv_bfloat162 l2 = __float22bfloat162_rn(r);
    hi = reinterpret_cast<uint32_t&>(h2);
    lo = reinterpret_cast<uint32_t&>(l2);
}
__device__ __forceinline__ uint32_t h2pack(float a, float b) {
    __half2 h = __float22half2_rn(make_float2(a, b));
    return reinterpret_cast<uint32_t&>(h);
}
__device__ __forceinline__ void ldm4(uint32_t addr, uint32_t r[4]) {
    asm volatile("ldmatrix.sync.aligned.m8n8.x4.shared.b16 {%0,%1,%2,%3}, [%4];"
                 : "=r"(r[0]), "=r"(r[1]), "=r"(r[2]), "=r"(r[3]) : "r"(addr));
}
__device__ __forceinline__ void mma_bf16(float* c, const uint32_t* a, uint32_t b0, uint32_t b1) {
    asm volatile(
        "mma.sync.aligned.m16n8k16.row.col.f32.bf16.bf16.f32 "
        "{%0,%1,%2,%3}, {%4,%5,%6,%7}, {%8,%9}, {%0,%1,%2,%3};"
        : "+f"(c[0]), "+f"(c[1]), "+f"(c[2]), "+f"(c[3])
        : "r"(a[0]), "r"(a[1]), "r"(a[2]), "r"(a[3]), "r"(b0), "r"(b1));
}
__device__ __forceinline__ void mma_f16(float* c, const uint32_t* a, uint32_t b0, uint32_t b1) {
    asm volatile(
        "mma.sync.aligned.m16n8k16.row.col.f32.f16.f16.f32 "
        "{%0,%1,%2,%3}, {%4,%5,%6,%7}, {%8,%9}, {%0,%1,%2,%3};"
        : "+f"(c[0]), "+f"(c[1]), "+f"(c[2]), "+f"(c[3])
        : "r"(a[0]), "r"(a[1]), "r"(a[2]), "r"(a[3]), "r"(b0), "r"(b1));
}
__device__ __forceinline__ void cpa16(uint32_t dst, const void* src) {
    asm volatile("cp.async.cg.shared.global [%0], [%1], 16;" :: "r"(dst), "l"(src));
}
#define CP_COMMIT() asm volatile("cp.async.commit_group;" ::: "memory")
#define CP_WAIT0()  asm volatile("cp.async.wait_group 0;" ::: "memory")
#define CP_WAIT1()  asm volatile("cp.async.wait_group 1;" ::: "memory")

// =====================================================================
// Prep kernels
// =====================================================================
__global__ void __launch_bounds__(256)
prep_w_kernel(const float* __restrict__ W, int koff, unsigned char* __restrict__ img, int rstride)
{
    __shared__ float ts[32][33];
    const int f0 = blockIdx.x * 32, nn0 = blockIdx.y * 32, kt = blockIdx.z;
    const int tid = threadIdx.x;
    const float* Wk = W + (size_t)kt * 65536;
#pragma unroll
    for (int p = 0; p < 4; ++p) {
        int fr = (tid >> 5) + p * 8, nl = tid & 31;
        ts[fr][nl] = Wk[(size_t)(koff + f0 + fr) * 256 + nn0 + nl];
    }
    __syncthreads();
#pragma unroll
    for (int p = 0; p < 2; ++p) {
        int idx = tid + p * 256;
        int nr = idx >> 4, wp = idx & 15;
        uint32_t hi, lo;
        split2(make_float2(ts[2 * wp][nr], ts[2 * wp + 1][nr]), hi, lo);
        size_t rb = (size_t)(nn0 + nr) * rstride + (f0 + 2 * wp) * 2;
        *(uint32_t*)(img + (size_t)(kt * 2 + 0) * 256 * rstride + rb) = hi;
        *(uint32_t*)(img + (size_t)(kt * 2 + 1) * 256 * rstride + rb) = lo;
    }
}

__global__ void __launch_bounds__(256)
prep_w2h_kernel(const float* __restrict__ W, unsigned char* __restrict__ img)
{
    __shared__ float ts[32][33];
    const int f0 = blockIdx.x * 32, nn0 = blockIdx.y * 32, kt = blockIdx.z;
    const int tid = threadIdx.x;
    const float* Wk = W + (size_t)kt * 65536;
#pragma unroll
    for (int p = 0; p < 4; ++p) {
        int fr = (tid >> 5) + p * 8, nl = tid & 31;
        ts[fr][nl] = Wk[(size_t)(f0 + fr) * 256 + nn0 + nl];
    }
    __syncthreads();
#pragma unroll
    for (int p = 0; p < 2; ++p) {
        int idx = tid + p * 256;
        int nr = idx >> 4, wp = idx & 15;
        *(uint32_t*)(img + (size_t)(kt * 256 + nn0 + nr) * 528 + (f0 + 2 * wp) * 2) =
            h2pack(ts[2 * wp][nr], ts[2 * wp + 1][nr]);
    }
}

__global__ void __launch_bounds__(256)
prep_wo_kernel(const float* __restrict__ W, unsigned char* __restrict__ img, int Ncols, int rstride)
{
    __shared__ float ts[32][33];
    const int f0 = blockIdx.x * 32, nn0 = blockIdx.y * 32;
    const int tid = threadIdx.x;
#pragma unroll
    for (int p = 0; p < 4; ++p) {
        int fr = (tid >> 5) + p * 8, nl = tid & 31;
        ts[fr][nl] = W[(size_t)(f0 + fr) * Ncols + nn0 + nl];
    }
    __syncthreads();
#pragma unroll
    for (int p = 0; p < 2; ++p) {
        int idx = tid + p * 256;
        int nr = idx >> 4, wp = idx & 15;
        *(uint32_t*)(img + (size_t)(nn0 + nr) * rstride + (f0 + 2 * wp) * 2) =
            h2pack(ts[2 * wp][nr], ts[2 * wp + 1][nr]);
    }
}

__global__ void __launch_bounds__(256)
prep_x_kernel(const float* __restrict__ inputs, uint32_t* __restrict__ xhi, uint32_t* __restrict__ xlo)
{
    int idx = blockIdx.x * 256 + threadIdx.x;
    float2 v = ((const float2*)inputs)[idx];
    uint32_t hi, lo;
    split2(v, hi, lo);
    xhi[idx] = hi;
    xlo[idx] = lo;
}

// =====================================================================
// ns_kernel: per (k,b,z) node GEMM [64x128]@[128x128] (3-split bf16).
// z = (half<<1)|scol: half 0 -> hbase (+b1), half 1 -> S; scol = col pair.
// =====================================================================
#define NS_XHI 0
#define NS_XLO 17408
#define NS_W   34816
#define NS_B1  69632
#define NS_TOTAL 70656

__global__ void __launch_bounds__(256)
ns_kernel(const uint32_t* __restrict__ xhi, const uint32_t* __restrict__ xlo,
          const unsigned char* __restrict__ w1r, const unsigned char* __restrict__ w1s,
          const float* __restrict__ b1, float* __restrict__ ns)
{
    extern __shared__ char smem[];
    const uint32_t sb = smem_u32(smem);
    const int tid = threadIdx.x, lane = tid & 31, w = tid >> 5;
    const int k = blockIdx.x, b = blockIdx.y;
    const int half = blockIdx.z >> 1, s0 = (blockIdx.z & 1) * 2;

    for (int t = tid; t < 1024; t += 256) {
        int row = t >> 4, sgi = t & 15;
        size_t so = (size_t)(b * 64 + row) * 64 + sgi * 4;
        cpa16(sb + NS_XHI + row * 272 + sgi * 16, xhi + so);
        cpa16(sb + NS_XLO + row * 272 + sgi * 16, xlo + so);
    }
    CP_COMMIT();
    if (tid < 64) ((float4*)(smem + NS_B1))[tid] = ((const float4*)(b1 + k * 256))[tid];

    const int g = lane >> 2, tg = lane & 3;
    const int arow = lane & 15;
    const uint32_t aoff = (uint32_t)((lane >> 4) << 4);
    const int brow = (lane & 7) + ((lane >> 4) << 3);
    const uint32_t boff = (uint32_t)((lane & 8) << 1);
    const int wm = w & 3, wn = w >> 2;
    const int m0 = wm * 16;
    const float* b1s = (const float*)(smem + NS_B1);
    float* outk = ns + ((size_t)k * BB + b) * 64 * 512;
    const unsigned char* img = half ? w1s : w1r;

#pragma unroll 1
    for (int si = 0; si < 2; ++si) {
        int s = s0 + si;
        for (int t = tid; t < 2176; t += 256) {
            int im = t >= 1088;
            uint32_t off = (uint32_t)(t - im * 1088) * 16;
            cpa16(sb + NS_W + (im ? 17408 : 0) + off,
                  img + (size_t)((k * 2 + im) * 256 + s * 64) * 272 + off);
        }
        CP_COMMIT(); CP_WAIT0();
        __syncthreads();
        float c[4][4] = {};
#pragma unroll
        for (int sp = 0; sp < 3; ++sp) {
            uint32_t Ab = sb + (sp == 2 ? NS_XLO : NS_XHI) + (m0 + arow) * 272 + aoff;
            uint32_t Bb = sb + NS_W + (sp == 1 ? 17408u : 0u) + (wn * 32 + brow) * 272 + boff;
#pragma unroll
            for (int ks = 0; ks < 8; ++ks) {
                uint32_t a[4], b0[4], b1f[4];
                ldm4(Ab + ks * 32, a);
                ldm4(Bb + ks * 32, b0);
                ldm4(Bb + 16 * 272 + ks * 32, b1f);
                mma_bf16(c[0], a, b0[0], b0[1]);
                mma_bf16(c[1], a, b0[2], b0[3]);
                mma_bf16(c[2], a, b1f[0], b1f[1]);
                mma_bf16(c[3], a, b1f[2], b1f[3]);
            }
        }
        int r0 = m0 + g, r1 = r0 + 8;
        int cn = s * 64 + wn * 32;
#pragma unroll
        for (int t = 0; t < 4; ++t) {
            int col = cn + t * 8 + 2 * tg;
            float a0 = half ? 0.f : b1s[col], a1 = half ? 0.f : b1s[col + 1];
            outk[(size_t)r0 * 512 + half * 256 + col]     = c[t][0] + a0;
            outk[(size_t)r0 * 512 + half * 256 + col + 1] = c[t][1] + a1;
            outk[(size_t)r1 * 512 + half * 256 + col]     = c[t][2] + a0;
            outk[(size_t)r1 * 512 + half * 256 + col + 1] = c[t][3] + a1;
        }
        __syncthreads();
    }
}

// ---------------- SMEM map (bytes) for edge kernel ----------------
#define SE_S0   0         // 64 x 1040 = 66560
#define SE_S1   66560     // -> 133120
#define SE_W2   133120    // 2 x 16896 -> 166912
#define SE_HBS  166912    // 4096 -> 171008
#define SE_B2S  171008    // 1024 -> 172032
#define SE_RTS  172032    // 4096 -> 176128
#define SE_AGG  176128    // 8192 -> 184320
#define SE_TOTAL 184320

// =====================================================================
// Edge kernel: block = (4 nodes, batch), 256 threads.
// S double-buffered across k; S(k+1) gather rides in the s==4 commit group.
// =====================================================================
__global__ void __launch_bounds__(256, 1)
edge_kernel(const float* __restrict__ rel_type,
            const unsigned char* __restrict__ w2img,
            const float* __restrict__ ns,
            const float* __restrict__ b2,
            float* __restrict__ agg)
{
    extern __shared__ char smem[];
    const uint32_t sb = smem_u32(smem);
    const int tid = threadIdx.x;
    const int lane = tid & 31, w = tid >> 5;
    const int n0 = blockIdx.x * 4, b = blockIdx.y;

    // prologue group: S(k=0) into S0 + W2(k=0, slab0)
    {
        const float* ns0 = ns + (size_t)b * 64 * 512;
        for (int t = tid; t < 4096; t += 256) {
            int row = t >> 6, ch = t & 63;
            cpa16(sb + SE_S0 + row * 1040 + ch * 16, ns0 + (size_t)row * 512 + 256 + ch * 4);
        }
        for (int t = tid; t < 1056; t += 256)
            cpa16(sb + SE_W2 + t * 16, w2img + (size_t)t * 16);
        CP_COMMIT();
    }

    {   // rel_type tile [256 rows][4]
        int node = n0 + (tid >> 6), le = tid & 63;
        float4 v = make_float4(0.f, 0.f, 0.f, 0.f);
        if (le < 63) v = *(const float4*)(rel_type + ((size_t)b * EE + node * 63 + le) * KK);
        *(float4*)(smem + SE_RTS + tid * 16) = v;
    }
    for (int i = tid; i < 2048; i += 256) ((float*)(smem + SE_AGG))[i] = 0.f;

    const int g = lane >> 2, tg = lane & 3;
    const int brow = (lane & 7) + ((lane >> 4) << 3);
    const uint32_t boff = (uint32_t)((lane & 8) << 1);
    const int m0 = w * 32;
    const int nodeg = n0 + (w >> 1);
    const float* rts = (const float*)(smem + SE_RTS);
    const float* b2s = (const float*)(smem + SE_B2S);
    float* aggS = (float*)(smem + SE_AGG);

    const int rw[4] = { m0 + g, m0 + g + 8, m0 + g + 16, m0 + g + 24 };
    float msk[4];
    int js[4];
#pragma unroll
    for (int i = 0; i < 4; ++i) {
        int le = rw[i] & 63;
        msk[i] = (le != 63) ? 1.f : 0.f;
        js[i] = (le != 63) ? (le + (le >= nodeg)) : 0;
    }

    uint32_t Ha[64], Hb[64];

#pragma unroll 1
    for (int k = 0; k < KK; ++k) {
        const float* nsk = ns + ((size_t)k * BB + b) * 64 * 512;
        {   // hbase rows for the 4 receiver nodes + b2 (plain loads)
            int row = n0 + (tid >> 6), c4 = (tid & 63) * 4;
            *(float4*)(smem + SE_HBS + tid * 16) = *(const float4*)(nsk + (size_t)row * 512 + c4);
            if (tid < 64)
                ((float4*)(smem + SE_B2S))[tid] = ((const float4*)(b2 + k * 256))[tid];
        }
        CP_WAIT0();        // S(k) + W2(k,0) resident
        __syncthreads();

        // ---- build H fragments: relu(hbase + S), fp16 ----
        {
            const float* Sbase = (const float*)(smem + ((k & 1) ? SE_S1 : SE_S0));
            const float* S0 = Sbase + js[0] * 260;
            const float* S1 = Sbase + js[1] * 260;
            const float* S2 = Sbase + js[2] * 260;
            const float* S3 = Sbase + js[3] * 260;
            const float* hb = (const float*)(smem + SE_HBS) + (w >> 1) * 256;
#pragma unroll
            for (int ks = 0; ks < 16; ++ks) {
                int c = ks * 16 + 2 * tg;
                float2 h0 = *(const float2*)(hb + c);
                float2 h8 = *(const float2*)(hb + c + 8);
                float2 sA0 = *(const float2*)(S0 + c), sA8 = *(const float2*)(S0 + c + 8);
                float2 sB0 = *(const float2*)(S1 + c), sB8 = *(const float2*)(S1 + c + 8);
                float2 sC0 = *(const float2*)(S2 + c), sC8 = *(const float2*)(S2 + c + 8);
                float2 sD0 = *(const float2*)(S3 + c), sD8 = *(const float2*)(S3 + c + 8);
                Ha[ks*4+0] = h2pack(msk[0]*fmaxf(h0.x + sA0.x, 0.f), msk[0]*fmaxf(h0.y + sA0.y, 0.f));
                Ha[ks*4+1] = h2pack(msk[1]*fmaxf(h0.x + sB0.x, 0.f), msk[1]*fmaxf(h0.y + sB0.y, 0.f));
                Ha[ks*4+2] = h2pack(msk[0]*fmaxf(h8.x + sA8.x, 0.f), msk[0]*fmaxf(h8.y + sA8.y, 0.f));
                Ha[ks*4+3] = h2pack(msk[1]*fmaxf(h8.x + sB8.x, 0.f), msk[1]*fmaxf(h8.y + sB8.y, 0.f));
                Hb[ks*4+0] = h2pack(msk[2]*fmaxf(h0.x + sC0.x, 0.f), msk[2]*fmaxf(h0.y + sC0.y, 0.f));
                Hb[ks*4+1] = h2pack(msk[3]*fmaxf(h0.x + sD0.x, 0.f), msk[3]*fmaxf(h0.y + sD0.y, 0.f));
                Hb[ks*4+2] = h2pack(msk[2]*fmaxf(h8.x + sC8.x, 0.f), msk[2]*fmaxf(h8.y + sC8.y, 0.f));
                Hb[ks*4+3] = h2pack(msk[3]*fmaxf(h8.x + sD8.x, 0.f), msk[3]*fmaxf(h8.y + sD8.y, 0.f));
            }
        }

        const float wr0 = rts[rw[0] * 4 + k], wr1 = rts[rw[1] * 4 + k];
        const float wr2 = rts[rw[2] * 4 + k], wr3 = rts[rw[3] * 4 + k];
#pragma unroll 1
        for (int s = 0; s < 8; ++s) {
            const int gs = k * 8 + s;
            CP_WAIT0();        // slab gs resident
            __syncthreads();   // all warps done with the other buffer
            if (gs < 31) {
                const int nk = (gs + 1) >> 3, nslab = (gs + 1) & 7;
                uint32_t wb = SE_W2 + (uint32_t)(((gs + 1) & 1) * 16896);
                for (int t = tid; t < 1056; t += 256)
                    cpa16(sb + wb + t * 16,
                          w2img + (size_t)(nk * 256 + nslab * 32) * 528 + t * 16);
                if (s == 4 && k < 3) {   // S(k+1) rides in this group
                    const float* nsn = ns + ((size_t)(k + 1) * BB + b) * 64 * 512;
                    uint32_t sB = ((k + 1) & 1) ? SE_S1 : SE_S0;
                    for (int t = tid; t < 4096; t += 256) {
                        int row = t >> 6, ch = t & 63;
                        cpa16(sb + sB + row * 1040 + ch * 16,
                              nsn + (size_t)row * 512 + 256 + ch * 4);
                    }
                }
                CP_COMMIT();
            }
            const uint32_t wbs = sb + SE_W2 + (uint32_t)((s & 1) * 16896) + brow * 528 + boff;
            float cA[4][4] = {}, cB[4][4] = {};
#pragma unroll
            for (int ks = 0; ks < 16; ++ks) {
                uint32_t b0[4], b1f[4];
                ldm4(wbs + ks * 32, b0);
                ldm4(wbs + 16 * 528 + ks * 32, b1f);
                const uint32_t* aA = Ha + ks * 4;
                const uint32_t* aB = Hb + ks * 4;
                mma_f16(cA[0], aA, b0[0], b0[1]);
                mma_f16(cA[1], aA, b0[2], b0[3]);
                mma_f16(cA[2], aA, b1f[0], b1f[1]);
                mma_f16(cA[3], aA, b1f[2], b1f[3]);
                mma_f16(cB[0], aB, b0[0], b0[1]);
                mma_f16(cB[1], aB, b0[2], b0[3]);
                mma_f16(cB[2], aB, b1f[0], b1f[1]);
                mma_f16(cB[3], aB, b1f[2], b1f[3]);
            }
            float p0[4], p1[4];
#pragma unroll
            for (int t = 0; t < 4; ++t) {
                int col = s * 32 + t * 8 + 2 * tg;
                float bc0 = b2s[col], bc1 = b2s[col + 1];
                p0[t] = wr0 * fmaxf(cA[t][0] + bc0, 0.f)
                      + wr1 * fmaxf(cA[t][2] + bc0, 0.f)
                      + wr2 * fmaxf(cB[t][0] + bc0, 0.f)
                      + wr3 * fmaxf(cB[t][2] + bc0, 0.f);
                p1[t] = wr0 * fmaxf(cA[t][1] + bc1, 0.f)
                      + wr1 * fmaxf(cA[t][3] + bc1, 0.f)
                      + wr2 * fmaxf(cB[t][1] + bc1, 0.f)
                      + wr3 * fmaxf(cB[t][3] + bc1, 0.f);
            }
#pragma unroll
            for (int off = 4; off <= 16; off <<= 1)
#pragma unroll
                for (int t = 0; t < 4; ++t) {
                    p0[t] += __shfl_xor_sync(0xffffffff, p0[t], off);
                    p1[t] += __shfl_xor_sync(0xffffffff, p1[t], off);
                }
            if (g == 0) {
#pragma unroll
                for (int t = 0; t < 4; ++t) {
                    int col = s * 32 + t * 8 + 2 * tg;
                    aggS[w * 256 + col]     += p0[t];
                    aggS[w * 256 + col + 1] += p1[t];
                }
            }
        }
    }

    __syncthreads();
    for (int t = tid; t < 1024; t += 256) {
        int ni = t >> 8, m = t & 255;
        agg[((size_t)b * NN + n0 + ni) * 256 + m] =
            aggS[(2 * ni) * 256 + m] + aggS[(2 * ni + 1) * 256 + m];
    }
}

// =====================================================================
// Output MLP, tensor-core fp16: 16 rows/block, 128 threads, grid 128.
// Warp w handles 16 cols of each 64-col slab.
// =====================================================================
#define OT_A0 0          // 16 x 784 = 12544 (aug, later p2 at stride 528)
#define OT_A1 12544      // 16 x 528 = 8448 -> 20992
#define OT_W  20992      // 2 x 50176 -> 121344
#define OT_TOTAL 121344

__global__ void __launch_bounds__(128, 1)
out_tc_kernel(const float* __restrict__ inputs, const float* __restrict__ agg,
              const unsigned char* __restrict__ wo1, const unsigned char* __restrict__ wo2,
              const unsigned char* __restrict__ wo3,
              const float* __restrict__ bo1, const float* __restrict__ bo2,
              const float* __restrict__ bo3, float* __restrict__ out)
{
    extern __shared__ char smem[];
    const uint32_t sb = smem_u32(smem);
    const int tid = threadIdx.x, lane = tid & 31, w = tid >> 5;   // w = 0..3
    const int row0 = blockIdx.x * 16;

    const int g = lane >> 2, tg = lane & 3;
    const int arow = lane & 15;
    const uint32_t aoff = (uint32_t)((lane >> 4) << 4);
    const int brow = (lane & 7) + ((lane >> 4) << 3);
    const uint32_t boff = (uint32_t)((lane & 8) << 1);
    const int r0 = g, r1 = g + 8;

    // build aug fp16 in A0 (cols 0..127 inputs, 128..383 agg), stride 784
    for (int idx = tid; idx < 16 * 192; idx += 128) {
        int r = idx / 192, pc = idx % 192;
        float2 v;
        if (pc < 64) v = *(const float2*)(inputs + (size_t)(row0 + r) * FF + pc * 2);
        else         v = *(const float2*)(agg + (size_t)(row0 + r) * 256 + (pc - 64) * 2);
        *(uint32_t*)(smem + OT_A0 + r * 784 + pc * 4) = h2pack(v.x, v.y);
    }
    for (int t = tid; t < 3136; t += 128)
        cpa16(sb + OT_W + t * 16, wo1 + (size_t)t * 16);
    CP_COMMIT();
    __syncthreads();

    // ---- layer 1: K=384 (24 ks), N=256 (4 slabs of 64), relu -> A1 ----
#pragma unroll 1
    for (int s = 0; s < 4; ++s) {
        CP_WAIT0();
        __syncthreads();
        if (s < 3) {
            uint32_t wb = OT_W + (uint32_t)(((s + 1) & 1) * 50176);
            for (int t = tid; t < 3136; t += 128)
                cpa16(sb + wb + t * 16, wo1 + (size_t)((s + 1) * 64) * 784 + t * 16);
            CP_COMMIT();
        }
        const uint32_t wbs = sb + OT_W + (uint32_t)((s & 1) * 50176) + (w * 16 + brow) * 784 + boff;
        const uint32_t Ab = sb + OT_A0 + arow * 784 + aoff;
        float c[2][4] = {};
#pragma unroll
        for (int ks = 0; ks < 24; ++ks) {
            uint32_t a[4], bb[4];
            ldm4(Ab + ks * 32, a);
            ldm4(wbs + ks * 32, bb);
            mma_f16(c[0], a, bb[0], bb[1]);
            mma_f16(c[1], a, bb[2], bb[3]);
        }
#pragma unroll
        for (int t = 0; t < 2; ++t) {
            int col = s * 64 + w * 16 + t * 8 + 2 * tg;
            float bc0 = bo1[col], bc1 = bo1[col + 1];
            *(uint32_t*)(smem + OT_A1 + r0 * 528 + col * 2) =
                h2pack(fmaxf(c[t][0] + bc0, 0.f), fmaxf(c[t][1] + bc1, 0.f));
            *(uint32_t*)(smem + OT_A1 + r1 * 528 + col * 2) =
                h2pack(fmaxf(c[t][2] + bc0, 0.f), fmaxf(c[t][3] + bc1, 0.f));
        }
    }
    __syncthreads();
    for (int t = tid; t < 2112; t += 128)
        cpa16(sb + OT_W + t * 16, wo2 + (size_t)t * 16);
    CP_COMMIT();

    // ---- layer 2: K=256 (16 ks), N=256, relu -> A0 (stride 528) ----
#pragma unroll 1
    for (int s = 0; s < 4; ++s) {
        CP_WAIT0();
        __syncthreads();
        if (s < 3) {
            uint32_t wb = OT_W + (uint32_t)(((s + 1) & 1) * 50176);
            for (int t = tid; t < 2112; t += 128)
                cpa16(sb + wb + t * 16, wo2 + (size_t)((s + 1) * 64) * 528 + t * 16);
            CP_COMMIT();
        }
        const uint32_t wbs = sb + OT_W + (uint32_t)((s & 1) * 50176) + (w * 16 + brow) * 528 + boff;
        const uint32_t Ab = sb + OT_A1 + arow * 528 + aoff;
        float c[2][4] = {};
#pragma unroll
        for (int ks = 0; ks < 16; ++ks) {
            uint32_t a[4], bb[4];
            ldm4(Ab + ks * 32, a);
            ldm4(wbs + ks * 32, bb);
            mma_f16(c[0], a, bb[0], bb[1]);
            mma_f16(c[1], a, bb[2], bb[3]);
        }
#pragma unroll
        for (int t = 0; t < 2; ++t) {
            int col = s * 64 + w * 16 + t * 8 + 2 * tg;
            float bc0 = bo2[col], bc1 = bo2[col + 1];
            *(uint32_t*)(smem + OT_A0 + r0 * 528 + col * 2) =
                h2pack(fmaxf(c[t][0] + bc0, 0.f), fmaxf(c[t][1] + bc1, 0.f));
            *(uint32_t*)(smem + OT_A0 + r1 * 528 + col * 2) =
                h2pack(fmaxf(c[t][2] + bc0, 0.f), fmaxf(c[t][3] + bc1, 0.f));
        }
    }
    __syncthreads();
    for (int t = tid; t < 2112; t += 128)
        cpa16(sb + OT_W + t * 16, wo3 + (size_t)t * 16);
    CP_COMMIT();

    // ---- layer 3: K=256 (16 ks), N=128 (2 slabs), + residual -> out ----
#pragma unroll 1
    for (int s = 0; s < 2; ++s) {
        CP_WAIT0();
        __syncthreads();
        if (s < 1) {
            uint32_t wb = OT_W + 50176u;
            for (int t = tid; t < 2112; t += 128)
                cpa16(sb + wb + t * 16, wo3 + (size_t)64 * 528 + t * 16);
            CP_COMMIT();
        }
        const uint32_t wbs = sb + OT_W + (uint32_t)((s & 1) * 50176) + (w * 16 + brow) * 528 + boff;
        const uint32_t Ab = sb + OT_A0 + arow * 528 + aoff;
        float c[2][4] = {};
#pragma unroll
        for (int ks = 0; ks < 16; ++ks) {
            uint32_t a[4], bb[4];
            ldm4(Ab + ks * 32, a);
            ldm4(wbs + ks * 32, bb);
            mma_f16(c[0], a, bb[0], bb[1]);
            mma_f16(c[1], a, bb[2], bb[3]);
        }
#pragma unroll
        for (int t = 0; t < 2; ++t) {
            int col = s * 64 + w * 16 + t * 8 + 2 * tg;
            float bc0 = bo3[col], bc1 = bo3[col + 1];
            float2 e0 = *(const float2*)(inputs + (size_t)(row0 + r0) * FF + col);
            float2 e1 = *(const float2*)(inputs + (size_t)(row0 + r1) * FF + col);
            *(float2*)(out + (size_t)(row0 + r0) * FF + col) =
                make_float2(e0.x + c[t][0] + bc0, e0.y + c[t][1] + bc1);
            *(float2*)(out + (size_t)(row0 + r1) * FF + col) =
                make_float2(e1.x + c[t][2] + bc0, e1.y + c[t][3] + bc1);
        }
    }
}

// =====================================================================
extern "C" void kernel_launch(void* const* d_in, const int* in_sizes, int n_in,
                              void* d_out, int out_size)
{
    const float* inputs   = (const float*)d_in[0];
    const float* rel_type = (const float*)d_in[1];
    const float* W1  = (const float*)d_in[4];
    const float* b1  = (const float*)d_in[5];
    const float* W2  = (const float*)d_in[6];
    const float* b2  = (const float*)d_in[7];
    const float* Wo1 = (const float*)d_in[8];
    const float* bo1 = (const float*)d_in[9];
    const float* Wo2 = (const float*)d_in[10];
    const float* bo2 = (const float*)d_in[11];
    const float* Wo3 = (const float*)d_in[12];
    const float* bo3 = (const float*)d_in[13];
    float* out = (float*)d_out;

    float *agg, *ns;
    unsigned char *w1r, *w1s, *w2i, *wo1i, *wo2i, *wo3i;
    uint32_t *xhi, *xlo;
    cudaGetSymbolAddress((void**)&agg, g_agg);
    cudaGetSymbolAddress((void**)&ns, g_ns);
    cudaGetSymbolAddress((void**)&w1r, g_w1r);
    cudaGetSymbolAddress((void**)&w1s, g_w1s);
    cudaGetSymbolAddress((void**)&w2i, g_w2img);
    cudaGetSymbolAddress((void**)&wo1i, g_wo1);
    cudaGetSymbolAddress((void**)&wo2i, g_wo2);
    cudaGetSymbolAddress((void**)&wo3i, g_wo3);
    cudaGetSymbolAddress((void**)&xhi, g_ximg_hi);
    cudaGetSymbolAddress((void**)&xlo, g_ximg_lo);

    cudaFuncSetAttribute(edge_kernel, cudaFuncAttributeMaxDynamicSharedMemorySize, SE_TOTAL);
    cudaFuncSetAttribute(ns_kernel, cudaFuncAttributeMaxDynamicSharedMemorySize, NS_TOTAL);
    cudaFuncSetAttribute(out_tc_kernel, cudaFuncAttributeMaxDynamicSharedMemorySize, OT_TOTAL);

    prep_x_kernel<<<BB * NN * 64 / 256, 256>>>(inputs, xhi, xlo);
    prep_w_kernel<<<dim3(4, 8, 4), 256>>>(W1, 0,   w1r, 272);
    prep_w_kernel<<<dim3(4, 8, 4), 256>>>(W1, 128, w1s, 272);
    prep_w2h_kernel<<<dim3(8, 8, 4), 256>>>(W2, w2i);
    prep_wo_kernel<<<dim3(12, 8), 256>>>(Wo1, wo1i, 256, 784);
    prep_wo_kernel<<<dim3(8, 8), 256>>>(Wo2, wo2i, 256, 528);
    prep_wo_kernel<<<dim3(8, 4), 256>>>(Wo3, wo3i, 128, 528);
    ns_kernel<<<dim3(KK, BB, 4), 256, NS_TOTAL>>>(xhi, xlo, w1r, w1s, b1, ns);
    edge_kernel<<<dim3(NN / 4, BB), 256, SE_TOTAL>>>(rel_type, w2i, ns, b2, agg);
    out_tc_kernel<<<BB * NN / 16, 128, OT_TOTAL>>>(inputs, agg, wo1i, wo2i, wo3i,
                                                   bo1, bo2, bo3, out);
}

// round 12
// speedup vs baseline: 3.9921x; 1.1821x over previous
#include <cuda_runtime.h>
#include <cuda_bf16.h>
#include <cuda_fp16.h>
#include <cstdint>

#define BB 32
#define NN 64
#define FF 128
#define KK 4
#define EE 4032

// ---------------- static device scratch (no allocations) ----------------
__device__ __align__(16) unsigned char g_w1r[KK * 2 * 256 * 272];   // W1 recv half (bf16 hi/lo)
__device__ __align__(16) unsigned char g_w1s[KK * 2 * 256 * 272];   // W1 send half (bf16 hi/lo)
__device__ __align__(16) unsigned char g_w2img[KK * 256 * 528];     // W2 fp16 HI only
__device__ __align__(16) unsigned char g_wo1[256 * 784];            // Wo1 fp16 image
__device__ __align__(16) unsigned char g_wo2[256 * 528];            // Wo2 fp16 image
__device__ __align__(16) unsigned char g_wo3[128 * 528];            // Wo3 fp16 image
__device__ __align__(16) uint32_t g_ximg_hi[BB * NN * 64];          // node feats bf16 pairs
__device__ __align__(16) uint32_t g_ximg_lo[BB * NN * 64];
__device__ __align__(16) float    g_hb[KK * BB * NN * 256];         // hbase fp32 (8 MB)
__device__ __align__(16) uint16_t g_simg[KK * BB * NN * 256];       // S fp16 image (4 MB)
__device__ float g_agg[BB * NN * 256];                              // 2 MB

// ---------------- helpers ----------------
__device__ __forceinline__ uint32_t smem_u32(const void* p) {
    uint32_t a;
    asm("{ .reg .u64 t; cvta.to.shared.u64 t, %1; cvt.u32.u64 %0, t; }" : "=r"(a) : "l"(p));
    return a;
}
__device__ __forceinline__ void split2(float2 v, uint32_t& hi, uint32_t& lo) {  // bf16
    __nv_bfloat162 h2 = __float22bfloat162_rn(v);
    float2 r = make_float2(v.x - __bfloat162float(h2.x), v.y - __bfloat162float(h2.y));
    __nv_bfloat162 l2 = __float22bfloat162_rn(r);
    hi = reinterpret_cast<uint32_t&>(h2);
    lo = reinterpret_cast<uint32_t&>(l2);
}
__device__ __forceinline__ uint32_t h2pack(float a, float b) {
    __half2 h = __float22half2_rn(make_float2(a, b));
    return reinterpret_cast<uint32_t&>(h);
}
__device__ __forceinline__ void ldm4(uint32_t addr, uint32_t r[4]) {
    asm volatile("ldmatrix.sync.aligned.m8n8.x4.shared.b16 {%0,%1,%2,%3}, [%4];"
                 : "=r"(r[0]), "=r"(r[1]), "=r"(r[2]), "=r"(r[3]) : "r"(addr));
}
__device__ __forceinline__ void mma_bf16(float* c, const uint32_t* a, uint32_t b0, uint32_t b1) {
    asm volatile(
        "mma.sync.aligned.m16n8k16.row.col.f32.bf16.bf16.f32 "
        "{%0,%1,%2,%3}, {%4,%5,%6,%7}, {%8,%9}, {%0,%1,%2,%3};"
        : "+f"(c[0]), "+f"(c[1]), "+f"(c[2]), "+f"(c[3])
        : "r"(a[0]), "r"(a[1]), "r"(a[2]), "r"(a[3]), "r"(b0), "r"(b1));
}
__device__ __forceinline__ void mma_f16(float* c, const uint32_t* a, uint32_t b0, uint32_t b1) {
    asm volatile(
        "mma.sync.aligned.m16n8k16.row.col.f32.f16.f16.f32 "
        "{%0,%1,%2,%3}, {%4,%5,%6,%7}, {%8,%9}, {%0,%1,%2,%3};"
        : "+f"(c[0]), "+f"(c[1]), "+f"(c[2]), "+f"(c[3])
        : "r"(a[0]), "r"(a[1]), "r"(a[2]), "r"(a[3]), "r"(b0), "r"(b1));
}
__device__ __forceinline__ void cpa16(uint32_t dst, const void* src) {
    asm volatile("cp.async.cg.shared.global [%0], [%1], 16;" :: "r"(dst), "l"(src));
}
#define CP_COMMIT() asm volatile("cp.async.commit_group;" ::: "memory")
#define CP_WAIT0()  asm volatile("cp.async.wait_group 0;" ::: "memory")
#define CP_WAIT1()  asm volatile("cp.async.wait_group 1;" ::: "memory")

// =====================================================================
// Prep kernels
// =====================================================================
__global__ void __launch_bounds__(256)
prep_w_kernel(const float* __restrict__ W, int koff, unsigned char* __restrict__ img, int rstride)
{
    __shared__ float ts[32][33];
    const int f0 = blockIdx.x * 32, nn0 = blockIdx.y * 32, kt = blockIdx.z;
    const int tid = threadIdx.x;
    const float* Wk = W + (size_t)kt * 65536;
#pragma unroll
    for (int p = 0; p < 4; ++p) {
        int fr = (tid >> 5) + p * 8, nl = tid & 31;
        ts[fr][nl] = Wk[(size_t)(koff + f0 + fr) * 256 + nn0 + nl];
    }
    __syncthreads();
#pragma unroll
    for (int p = 0; p < 2; ++p) {
        int idx = tid + p * 256;
        int nr = idx >> 4, wp = idx & 15;
        uint32_t hi, lo;
        split2(make_float2(ts[2 * wp][nr], ts[2 * wp + 1][nr]), hi, lo);
        size_t rb = (size_t)(nn0 + nr) * rstride + (f0 + 2 * wp) * 2;
        *(uint32_t*)(img + (size_t)(kt * 2 + 0) * 256 * rstride + rb) = hi;
        *(uint32_t*)(img + (size_t)(kt * 2 + 1) * 256 * rstride + rb) = lo;
    }
}

__global__ void __launch_bounds__(256)
prep_w2h_kernel(const float* __restrict__ W, unsigned char* __restrict__ img)
{
    __shared__ float ts[32][33];
    const int f0 = blockIdx.x * 32, nn0 = blockIdx.y * 32, kt = blockIdx.z;
    const int tid = threadIdx.x;
    const float* Wk = W + (size_t)kt * 65536;
#pragma unroll
    for (int p = 0; p < 4; ++p) {
        int fr = (tid >> 5) + p * 8, nl = tid & 31;
        ts[fr][nl] = Wk[(size_t)(f0 + fr) * 256 + nn0 + nl];
    }
    __syncthreads();
#pragma unroll
    for (int p = 0; p < 2; ++p) {
        int idx = tid + p * 256;
        int nr = idx >> 4, wp = idx & 15;
        *(uint32_t*)(img + (size_t)(kt * 256 + nn0 + nr) * 528 + (f0 + 2 * wp) * 2) =
            h2pack(ts[2 * wp][nr], ts[2 * wp + 1][nr]);
    }
}

__global__ void __launch_bounds__(256)
prep_wo_kernel(const float* __restrict__ W, unsigned char* __restrict__ img, int Ncols, int rstride)
{
    __shared__ float ts[32][33];
    const int f0 = blockIdx.x * 32, nn0 = blockIdx.y * 32;
    const int tid = threadIdx.x;
#pragma unroll
    for (int p = 0; p < 4; ++p) {
        int fr = (tid >> 5) + p * 8, nl = tid & 31;
        ts[fr][nl] = W[(size_t)(f0 + fr) * Ncols + nn0 + nl];
    }
    __syncthreads();
#pragma unroll
    for (int p = 0; p < 2; ++p) {
        int idx = tid + p * 256;
        int nr = idx >> 4, wp = idx & 15;
        *(uint32_t*)(img + (size_t)(nn0 + nr) * rstride + (f0 + 2 * wp) * 2) =
            h2pack(ts[2 * wp][nr], ts[2 * wp + 1][nr]);
    }
}

__global__ void __launch_bounds__(256)
prep_x_kernel(const float* __restrict__ inputs, uint32_t* __restrict__ xhi, uint32_t* __restrict__ xlo)
{
    int idx = blockIdx.x * 256 + threadIdx.x;
    float2 v = ((const float2*)inputs)[idx];
    uint32_t hi, lo;
    split2(v, hi, lo);
    xhi[idx] = hi;
    xlo[idx] = lo;
}

// =====================================================================
// ns_kernel: per (k,b,z) node GEMM [64x128]@[128x128] (3-split bf16).
// half 0 -> g_hb fp32 (x@W1_recv + b1); half 1 -> g_simg fp16 (x@W1_send).
// =====================================================================
#define NS_XHI 0
#define NS_XLO 17408
#define NS_W   34816
#define NS_B1  69632
#define NS_TOTAL 70656

__global__ void __launch_bounds__(256)
ns_kernel(const uint32_t* __restrict__ xhi, const uint32_t* __restrict__ xlo,
          const unsigned char* __restrict__ w1r, const unsigned char* __restrict__ w1s,
          const float* __restrict__ b1, float* __restrict__ hb, uint16_t* __restrict__ simg)
{
    extern __shared__ char smem[];
    const uint32_t sb = smem_u32(smem);
    const int tid = threadIdx.x, lane = tid & 31, w = tid >> 5;
    const int k = blockIdx.x, b = blockIdx.y;
    const int half = blockIdx.z >> 1, s0 = (blockIdx.z & 1) * 2;

    for (int t = tid; t < 1024; t += 256) {
        int row = t >> 4, sgi = t & 15;
        size_t so = (size_t)(b * 64 + row) * 64 + sgi * 4;
        cpa16(sb + NS_XHI + row * 272 + sgi * 16, xhi + so);
        cpa16(sb + NS_XLO + row * 272 + sgi * 16, xlo + so);
    }
    CP_COMMIT();
    if (tid < 64) ((float4*)(smem + NS_B1))[tid] = ((const float4*)(b1 + k * 256))[tid];

    const int g = lane >> 2, tg = lane & 3;
    const int arow = lane & 15;
    const uint32_t aoff = (uint32_t)((lane >> 4) << 4);
    const int brow = (lane & 7) + ((lane >> 4) << 3);
    const uint32_t boff = (uint32_t)((lane & 8) << 1);
    const int wm = w & 3, wn = w >> 2;
    const int m0 = wm * 16;
    const float* b1s = (const float*)(smem + NS_B1);
    const unsigned char* img = half ? w1s : w1r;
    float* outh = hb + ((size_t)k * BB + b) * 64 * 256;
    uint32_t* outs = (uint32_t*)simg + ((size_t)k * BB + b) * 64 * 128;

#pragma unroll 1
    for (int si = 0; si < 2; ++si) {
        int s = s0 + si;
        for (int t = tid; t < 2176; t += 256) {
            int im = t >= 1088;
            uint32_t off = (uint32_t)(t - im * 1088) * 16;
            cpa16(sb + NS_W + (im ? 17408 : 0) + off,
                  img + (size_t)((k * 2 + im) * 256 + s * 64) * 272 + off);
        }
        CP_COMMIT(); CP_WAIT0();
        __syncthreads();
        float c[4][4] = {};
#pragma unroll
        for (int sp = 0; sp < 3; ++sp) {
            uint32_t Ab = sb + (sp == 2 ? NS_XLO : NS_XHI) + (m0 + arow) * 272 + aoff;
            uint32_t Bb = sb + NS_W + (sp == 1 ? 17408u : 0u) + (wn * 32 + brow) * 272 + boff;
#pragma unroll
            for (int ks = 0; ks < 8; ++ks) {
                uint32_t a[4], b0[4], b1f[4];
                ldm4(Ab + ks * 32, a);
                ldm4(Bb + ks * 32, b0);
                ldm4(Bb + 16 * 272 + ks * 32, b1f);
                mma_bf16(c[0], a, b0[0], b0[1]);
                mma_bf16(c[1], a, b0[2], b0[3]);
                mma_bf16(c[2], a, b1f[0], b1f[1]);
                mma_bf16(c[3], a, b1f[2], b1f[3]);
            }
        }
        int r0 = m0 + g, r1 = r0 + 8;
        int cn = s * 64 + wn * 32;
        if (half == 0) {
#pragma unroll
            for (int t = 0; t < 4; ++t) {
                int col = cn + t * 8 + 2 * tg;
                outh[(size_t)r0 * 256 + col]     = c[t][0] + b1s[col];
                outh[(size_t)r0 * 256 + col + 1] = c[t][1] + b1s[col + 1];
                outh[(size_t)r1 * 256 + col]     = c[t][2] + b1s[col];
                outh[(size_t)r1 * 256 + col + 1] = c[t][3] + b1s[col + 1];
            }
        } else {
#pragma unroll
            for (int t = 0; t < 4; ++t) {
                int col = cn + t * 8 + 2 * tg;
                outs[(size_t)r0 * 128 + (col >> 1)] = h2pack(c[t][0], c[t][1]);
                outs[(size_t)r1 * 128 + (col >> 1)] = h2pack(c[t][2], c[t][3]);
            }
        }
        __syncthreads();
    }
}

// ---------------- SMEM map (bytes) for edge kernel ----------------
#define SE_S    0         // 64 x 528 (fp16) = 33792
#define SE_W2   33792     // 2 x 16896 -> 67584
#define SE_HBS  67584     // 2 x 256 f32 = 2048 -> 69632
#define SE_B2S  69632     // 1024 -> 70656
#define SE_RTS  70656     // 128 x 16 = 2048 -> 72704
#define SE_AGG  72704     // 8 x 256 f32 = 8192 -> 80896
#define SE_TOTAL 80896

// =====================================================================
// Edge kernel: block = (2 nodes, batch), 256 threads, 2 blocks/SM.
// M=128 edge rows, 16 rows/warp. H fragments fp16 in registers (64 regs).
// =====================================================================
__global__ void __launch_bounds__(256, 2)
edge_kernel(const float* __restrict__ rel_type,
            const unsigned char* __restrict__ w2img,
            const uint16_t* __restrict__ simg,
            const float* __restrict__ hb,
            const float* __restrict__ b2,
            float* __restrict__ agg)
{
    extern __shared__ char smem[];
    const uint32_t sb = smem_u32(smem);
    const int tid = threadIdx.x;
    const int lane = tid & 31, w = tid >> 5;
    const int n0 = blockIdx.x * 2, b = blockIdx.y;

    if (tid < 128) {   // rel_type tile [128 rows][4]
        int node = n0 + (tid >> 6), le = tid & 63;
        float4 v = make_float4(0.f, 0.f, 0.f, 0.f);
        if (le < 63) v = *(const float4*)(rel_type + ((size_t)b * EE + node * 63 + le) * KK);
        *(float4*)(smem + SE_RTS + tid * 16) = v;
    }
    for (int i = tid; i < 2048; i += 256) ((float*)(smem + SE_AGG))[i] = 0.f;

    const int g = lane >> 2, tg = lane & 3;
    const int brow = (lane & 7) + ((lane >> 4) << 3);
    const uint32_t boff = (uint32_t)((lane & 8) << 1);
    const int m0 = w * 16;
    const int nodeg = n0 + (w >> 2);
    const float* rts = (const float*)(smem + SE_RTS);
    const float* b2s = (const float*)(smem + SE_B2S);
    float* aggS = (float*)(smem + SE_AGG);

    const int rw0 = m0 + g, rw1 = rw0 + 8;
    const int le0 = rw0 & 63, le1 = rw1 & 63;
    const float msk0 = (le0 != 63) ? 1.f : 0.f;
    const float msk1 = (le1 != 63) ? 1.f : 0.f;
    const int j0 = (le0 != 63) ? (le0 + (le0 >= nodeg)) : 0;
    const int j1 = (le1 != 63) ? (le1 + (le1 >= nodeg)) : 0;

    uint32_t Ha[64];

#pragma unroll 1
    for (int k = 0; k < KK; ++k) {
        // S tile (fp16): 64 rows x 512 B
        {
            const unsigned char* sk = (const unsigned char*)simg +
                                      ((size_t)k * BB + b) * 64 * 512;
            for (int t = tid; t < 2048; t += 256) {
                int row = t >> 5, ch = t & 31;
                cpa16(sb + SE_S + row * 528 + ch * 16, sk + (size_t)row * 512 + ch * 16);
            }
            CP_COMMIT();
        }
        // W2 slab 0 prefetch
        for (int t = tid; t < 1056; t += 256)
            cpa16(sb + SE_W2 + t * 16, w2img + (size_t)(k * 256) * 528 + t * 16);
        CP_COMMIT();
        // hbase rows (2 nodes) + b2 via plain loads
        {
            const float* hbk = hb + (((size_t)k * BB + b) * 64 + n0) * 256;
            if (tid < 128) *(float4*)(smem + SE_HBS + tid * 16) = ((const float4*)hbk)[tid];
            else if (tid < 192)
                ((float4*)(smem + SE_B2S))[tid - 128] = ((const float4*)(b2 + k * 256))[tid - 128];
        }
        CP_WAIT1();        // S resident (W2 slab0 may still be in flight)
        __syncthreads();

        // ---- H fragments: relu(hbase + S), fp16 ----
        {
            const __half* S0 = (const __half*)(smem + SE_S) + j0 * 264;
            const __half* S1 = (const __half*)(smem + SE_S) + j1 * 264;
            const float* hbs = (const float*)(smem + SE_HBS) + (w >> 2) * 256;
#pragma unroll
            for (int ks = 0; ks < 16; ++ks) {
                int c = ks * 16 + 2 * tg;
                float2 h0 = *(const float2*)(hbs + c);
                float2 h8 = *(const float2*)(hbs + c + 8);
                __half2 a0 = *(const __half2*)(S0 + c);
                __half2 a8 = *(const __half2*)(S0 + c + 8);
                __half2 bq0 = *(const __half2*)(S1 + c);
                __half2 bq8 = *(const __half2*)(S1 + c + 8);
                Ha[ks*4+0] = h2pack(msk0 * fmaxf(h0.x + __low2float(a0), 0.f),
                                    msk0 * fmaxf(h0.y + __high2float(a0), 0.f));
                Ha[ks*4+1] = h2pack(msk1 * fmaxf(h0.x + __low2float(bq0), 0.f),
                                    msk1 * fmaxf(h0.y + __high2float(bq0), 0.f));
                Ha[ks*4+2] = h2pack(msk0 * fmaxf(h8.x + __low2float(a8), 0.f),
                                    msk0 * fmaxf(h8.y + __high2float(a8), 0.f));
                Ha[ks*4+3] = h2pack(msk1 * fmaxf(h8.x + __low2float(bq8), 0.f),
                                    msk1 * fmaxf(h8.y + __high2float(bq8), 0.f));
            }
        }

        const float wr0 = rts[rw0 * 4 + k], wr1 = rts[rw1 * 4 + k];
#pragma unroll 1
        for (int s = 0; s < 8; ++s) {
            CP_WAIT0();
            __syncthreads();
            if (s < 7) {
                uint32_t wb = SE_W2 + (uint32_t)(((s + 1) & 1) * 16896);
                for (int t = tid; t < 1056; t += 256)
                    cpa16(sb + wb + t * 16,
                          w2img + (size_t)(k * 256 + (s + 1) * 32) * 528 + t * 16);
                CP_COMMIT();
            }
            const uint32_t wbs = sb + SE_W2 + (uint32_t)((s & 1) * 16896) + brow * 528 + boff;
            float c[4][4] = {};
#pragma unroll
            for (int ks = 0; ks < 16; ++ks) {
                uint32_t b0[4], b1f[4];
                ldm4(wbs + ks * 32, b0);
                ldm4(wbs + 16 * 528 + ks * 32, b1f);
                const uint32_t* a = Ha + ks * 4;
                mma_f16(c[0], a, b0[0], b0[1]);
                mma_f16(c[1], a, b0[2], b0[3]);
                mma_f16(c[2], a, b1f[0], b1f[1]);
                mma_f16(c[3], a, b1f[2], b1f[3]);
            }
            float p0[4], p1[4];
#pragma unroll
            for (int t = 0; t < 4; ++t) {
                int col = s * 32 + t * 8 + 2 * tg;
                float bc0 = b2s[col], bc1 = b2s[col + 1];
                p0[t] = wr0 * fmaxf(c[t][0] + bc0, 0.f) + wr1 * fmaxf(c[t][2] + bc0, 0.f);
                p1[t] = wr0 * fmaxf(c[t][1] + bc1, 0.f) + wr1 * fmaxf(c[t][3] + bc1, 0.f);
            }
#pragma unroll
            for (int off = 4; off <= 16; off <<= 1)
#pragma unroll
                for (int t = 0; t < 4; ++t) {
                    p0[t] += __shfl_xor_sync(0xffffffff, p0[t], off);
                    p1[t] += __shfl_xor_sync(0xffffffff, p1[t], off);
                }
            if (g == 0) {
#pragma unroll
                for (int t = 0; t < 4; ++t) {
                    int col = s * 32 + t * 8 + 2 * tg;
                    aggS[w * 256 + col]     += p0[t];
                    aggS[w * 256 + col + 1] += p1[t];
                }
            }
        }
    }

    __syncthreads();
    // node ni (0..1) = warps 4ni .. 4ni+3
    for (int t = tid; t < 512; t += 256) {
        int ni = t >> 8, m = t & 255;
        agg[((size_t)b * NN + n0 + ni) * 256 + m] =
            aggS[(4 * ni + 0) * 256 + m] + aggS[(4 * ni + 1) * 256 + m] +
            aggS[(4 * ni + 2) * 256 + m] + aggS[(4 * ni + 3) * 256 + m];
    }
}

// =====================================================================
// Output MLP, tensor-core fp16: 16 rows/block, 128 threads, grid 128.
// =====================================================================
#define OT_A0 0
#define OT_A1 12544
#define OT_W  20992
#define OT_TOTAL 121344

__global__ void __launch_bounds__(128, 1)
out_tc_kernel(const float* __restrict__ inputs, const float* __restrict__ agg,
              const unsigned char* __restrict__ wo1, const unsigned char* __restrict__ wo2,
              const unsigned char* __restrict__ wo3,
              const float* __restrict__ bo1, const float* __restrict__ bo2,
              const float* __restrict__ bo3, float* __restrict__ out)
{
    extern __shared__ char smem[];
    const uint32_t sb = smem_u32(smem);
    const int tid = threadIdx.x, lane = tid & 31, w = tid >> 5;
    const int row0 = blockIdx.x * 16;

    const int g = lane >> 2, tg = lane & 3;
    const int arow = lane & 15;
    const uint32_t aoff = (uint32_t)((lane >> 4) << 4);
    const int brow = (lane & 7) + ((lane >> 4) << 3);
    const uint32_t boff = (uint32_t)((lane & 8) << 1);
    const int r0 = g, r1 = g + 8;

    for (int idx = tid; idx < 16 * 192; idx += 128) {
        int r = idx / 192, pc = idx % 192;
        float2 v;
        if (pc < 64) v = *(const float2*)(inputs + (size_t)(row0 + r) * FF + pc * 2);
        else         v = *(const float2*)(agg + (size_t)(row0 + r) * 256 + (pc - 64) * 2);
        *(uint32_t*)(smem + OT_A0 + r * 784 + pc * 4) = h2pack(v.x, v.y);
    }
    for (int t = tid; t < 3136; t += 128)
        cpa16(sb + OT_W + t * 16, wo1 + (size_t)t * 16);
    CP_COMMIT();
    __syncthreads();

#pragma unroll 1
    for (int s = 0; s < 4; ++s) {
        CP_WAIT0();
        __syncthreads();
        if (s < 3) {
            uint32_t wb = OT_W + (uint32_t)(((s + 1) & 1) * 50176);
            for (int t = tid; t < 3136; t += 128)
                cpa16(sb + wb + t * 16, wo1 + (size_t)((s + 1) * 64) * 784 + t * 16);
            CP_COMMIT();
        }
        const uint32_t wbs = sb + OT_W + (uint32_t)((s & 1) * 50176) + (w * 16 + brow) * 784 + boff;
        const uint32_t Ab = sb + OT_A0 + arow * 784 + aoff;
        float c[2][4] = {};
#pragma unroll
        for (int ks = 0; ks < 24; ++ks) {
            uint32_t a[4], bb[4];
            ldm4(Ab + ks * 32, a);
            ldm4(wbs + ks * 32, bb);
            mma_f16(c[0], a, bb[0], bb[1]);
            mma_f16(c[1], a, bb[2], bb[3]);
        }
#pragma unroll
        for (int t = 0; t < 2; ++t) {
            int col = s * 64 + w * 16 + t * 8 + 2 * tg;
            float bc0 = bo1[col], bc1 = bo1[col + 1];
            *(uint32_t*)(smem + OT_A1 + r0 * 528 + col * 2) =
                h2pack(fmaxf(c[t][0] + bc0, 0.f), fmaxf(c[t][1] + bc1, 0.f));
            *(uint32_t*)(smem + OT_A1 + r1 * 528 + col * 2) =
                h2pack(fmaxf(c[t][2] + bc0, 0.f), fmaxf(c[t][3] + bc1, 0.f));
        }
    }
    __syncthreads();
    for (int t = tid; t < 2112; t += 128)
        cpa16(sb + OT_W + t * 16, wo2 + (size_t)t * 16);
    CP_COMMIT();

#pragma unroll 1
    for (int s = 0; s < 4; ++s) {
        CP_WAIT0();
        __syncthreads();
        if (s < 3) {
            uint32_t wb = OT_W + (uint32_t)(((s + 1) & 1) * 50176);
            for (int t = tid; t < 2112; t += 128)
                cpa16(sb + wb + t * 16, wo2 + (size_t)((s + 1) * 64) * 528 + t * 16);
            CP_COMMIT();
        }
        const uint32_t wbs = sb + OT_W + (uint32_t)((s & 1) * 50176) + (w * 16 + brow) * 528 + boff;
        const uint32_t Ab = sb + OT_A1 + arow * 528 + aoff;
        float c[2][4] = {};
#pragma unroll
        for (int ks = 0; ks < 16; ++ks) {
            uint32_t a[4], bb[4];
            ldm4(Ab + ks * 32, a);
            ldm4(wbs + ks * 32, bb);
            mma_f16(c[0], a, bb[0], bb[1]);
            mma_f16(c[1], a, bb[2], bb[3]);
        }
#pragma unroll
        for (int t = 0; t < 2; ++t) {
            int col = s * 64 + w * 16 + t * 8 + 2 * tg;
            float bc0 = bo2[col], bc1 = bo2[col + 1];
            *(uint32_t*)(smem + OT_A0 + r0 * 528 + col * 2) =
                h2pack(fmaxf(c[t][0] + bc0, 0.f), fmaxf(c[t][1] + bc1, 0.f));
            *(uint32_t*)(smem + OT_A0 + r1 * 528 + col * 2) =
                h2pack(fmaxf(c[t][2] + bc0, 0.f), fmaxf(c[t][3] + bc1, 0.f));
        }
    }
    __syncthreads();
    for (int t = tid; t < 2112; t += 128)
        cpa16(sb + OT_W + t * 16, wo3 + (size_t)t * 16);
    CP_COMMIT();

#pragma unroll 1
    for (int s = 0; s < 2; ++s) {
        CP_WAIT0();
        __syncthreads();
        if (s < 1) {
            uint32_t wb = OT_W + 50176u;
            for (int t = tid; t < 2112; t += 128)
                cpa16(sb + wb + t * 16, wo3 + (size_t)64 * 528 + t * 16);
            CP_COMMIT();
        }
        const uint32_t wbs = sb + OT_W + (uint32_t)((s & 1) * 50176) + (w * 16 + brow) * 528 + boff;
        const uint32_t Ab = sb + OT_A0 + arow * 528 + aoff;
        float c[2][4] = {};
#pragma unroll
        for (int ks = 0; ks < 16; ++ks) {
            uint32_t a[4], bb[4];
            ldm4(Ab + ks * 32, a);
            ldm4(wbs + ks * 32, bb);
            mma_f16(c[0], a, bb[0], bb[1]);
            mma_f16(c[1], a, bb[2], bb[3]);
        }
#pragma unroll
        for (int t = 0; t < 2; ++t) {
            int col = s * 64 + w * 16 + t * 8 + 2 * tg;
            float bc0 = bo3[col], bc1 = bo3[col + 1];
            float2 e0 = *(const float2*)(inputs + (size_t)(row0 + r0) * FF + col);
            float2 e1 = *(const float2*)(inputs + (size_t)(row0 + r1) * FF + col);
            *(float2*)(out + (size_t)(row0 + r0) * FF + col) =
                make_float2(e0.x + c[t][0] + bc0, e0.y + c[t][1] + bc1);
            *(float2*)(out + (size_t)(row0 + r1) * FF + col) =
                make_float2(e1.x + c[t][2] + bc0, e1.y + c[t][3] + bc1);
        }
    }
}

// =====================================================================
extern "C" void kernel_launch(void* const* d_in, const int* in_sizes, int n_in,
                              void* d_out, int out_size)
{
    const float* inputs   = (const float*)d_in[0];
    const float* rel_type = (const float*)d_in[1];
    const float* W1  = (const float*)d_in[4];
    const float* b1  = (const float*)d_in[5];
    const float* W2  = (const float*)d_in[6];
    const float* b2  = (const float*)d_in[7];
    const float* Wo1 = (const float*)d_in[8];
    const float* bo1 = (const float*)d_in[9];
    const float* Wo2 = (const float*)d_in[10];
    const float* bo2 = (const float*)d_in[11];
    const float* Wo3 = (const float*)d_in[12];
    const float* bo3 = (const float*)d_in[13];
    float* out = (float*)d_out;

    float *agg, *hbp;
    uint16_t* simg;
    unsigned char *w1r, *w1s, *w2i, *wo1i, *wo2i, *wo3i;
    uint32_t *xhi, *xlo;
    cudaGetSymbolAddress((void**)&agg, g_agg);
    cudaGetSymbolAddress((void**)&hbp, g_hb);
    cudaGetSymbolAddress((void**)&simg, g_simg);
    cudaGetSymbolAddress((void**)&w1r, g_w1r);
    cudaGetSymbolAddress((void**)&w1s, g_w1s);
    cudaGetSymbolAddress((void**)&w2i, g_w2img);
    cudaGetSymbolAddress((void**)&wo1i, g_wo1);
    cudaGetSymbolAddress((void**)&wo2i, g_wo2);
    cudaGetSymbolAddress((void**)&wo3i, g_wo3);
    cudaGetSymbolAddress((void**)&xhi, g_ximg_hi);
    cudaGetSymbolAddress((void**)&xlo, g_ximg_lo);

    cudaFuncSetAttribute(edge_kernel, cudaFuncAttributeMaxDynamicSharedMemorySize, SE_TOTAL);
    cudaFuncSetAttribute(ns_kernel, cudaFuncAttributeMaxDynamicSharedMemorySize, NS_TOTAL);
    cudaFuncSetAttribute(out_tc_kernel, cudaFuncAttributeMaxDynamicSharedMemorySize, OT_TOTAL);

    prep_x_kernel<<<BB * NN * 64 / 256, 256>>>(inputs, xhi, xlo);
    prep_w_kernel<<<dim3(4, 8, 4), 256>>>(W1, 0,   w1r, 272);
    prep_w_kernel<<<dim3(4, 8, 4), 256>>>(W1, 128, w1s, 272);
    prep_w2h_kernel<<<dim3(8, 8, 4), 256>>>(W2, w2i);
    prep_wo_kernel<<<dim3(12, 8), 256>>>(Wo1, wo1i, 256, 784);
    prep_wo_kernel<<<dim3(8, 8), 256>>>(Wo2, wo2i, 256, 528);
    prep_wo_kernel<<<dim3(8, 4), 256>>>(Wo3, wo3i, 128, 528);
    ns_kernel<<<dim3(KK, BB, 4), 256, NS_TOTAL>>>(xhi, xlo, w1r, w1s, b1, hbp, simg);
    edge_kernel<<<dim3(NN / 2, BB), 256, SE_TOTAL>>>(rel_type, w2i, simg, hbp, b2, agg);
    out_tc_kernel<<<BB * NN / 16, 128, OT_TOTAL>>>(inputs, agg, wo1i, wo2i, wo3i,
                                                   bo1, bo2, bo3, out);
}

// round 13
// speedup vs baseline: 4.0965x; 1.0262x over previous
#include <cuda_runtime.h>
#include <cuda_bf16.h>
#include <cuda_fp16.h>
#include <cstdint>

#define BB 32
#define NN 64
#define FF 128
#define KK 4
#define EE 4032

// ---------------- static device scratch (no allocations) ----------------
__device__ __align__(16) unsigned char g_w1r[KK * 2 * 256 * 272];   // W1 recv half (bf16 hi/lo)
__device__ __align__(16) unsigned char g_w1s[KK * 2 * 256 * 272];   // W1 send half (bf16 hi/lo)
__device__ __align__(16) unsigned char g_w2img[KK * 256 * 528];     // W2 fp16 HI only
__device__ __align__(16) unsigned char g_wo1[256 * 784];            // Wo1 fp16 image
__device__ __align__(16) unsigned char g_wo2[256 * 528];            // Wo2 fp16 image
__device__ __align__(16) unsigned char g_wo3[128 * 528];            // Wo3 fp16 image
__device__ __align__(16) uint32_t g_ximg_hi[BB * NN * 64];          // node feats bf16 pairs
__device__ __align__(16) uint32_t g_ximg_lo[BB * NN * 64];
__device__ __align__(16) float    g_hb[KK * BB * NN * 256];         // hbase fp32 (8 MB)
__device__ __align__(16) uint16_t g_simg[KK * BB * NN * 256];       // S fp16 image (4 MB)
__device__ float g_agg[BB * NN * 256];                              // 2 MB

// ---------------- helpers ----------------
__device__ __forceinline__ uint32_t smem_u32(const void* p) {
    uint32_t a;
    asm("{ .reg .u64 t; cvta.to.shared.u64 t, %1; cvt.u32.u64 %0, t; }" : "=r"(a) : "l"(p));
    return a;
}
__device__ __forceinline__ void split2(float2 v, uint32_t& hi, uint32_t& lo) {  // bf16
    __nv_bfloat162 h2 = __float22bfloat162_rn(v);
    float2 r = make_float2(v.x - __bfloat162float(h2.x), v.y - __bfloat162float(h2.y));
    __nv_bfloat162 l2 = __float22bfloat162_rn(r);
    hi = reinterpret_cast<uint32_t&>(h2);
    lo = reinterpret_cast<uint32_t&>(l2);
}
__device__ __forceinline__ uint32_t h2pack(float a, float b) {
    __half2 h = __float22half2_rn(make_float2(a, b));
    return reinterpret_cast<uint32_t&>(h);
}
__device__ __forceinline__ void ldm4(uint32_t addr, uint32_t r[4]) {
    asm volatile("ldmatrix.sync.aligned.m8n8.x4.shared.b16 {%0,%1,%2,%3}, [%4];"
                 : "=r"(r[0]), "=r"(r[1]), "=r"(r[2]), "=r"(r[3]) : "r"(addr));
}
__device__ __forceinline__ void mma_bf16(float* c, const uint32_t* a, uint32_t b0, uint32_t b1) {
    asm volatile(
        "mma.sync.aligned.m16n8k16.row.col.f32.bf16.bf16.f32 "
        "{%0,%1,%2,%3}, {%4,%5,%6,%7}, {%8,%9}, {%0,%1,%2,%3};"
        : "+f"(c[0]), "+f"(c[1]), "+f"(c[2]), "+f"(c[3])
        : "r"(a[0]), "r"(a[1]), "r"(a[2]), "r"(a[3]), "r"(b0), "r"(b1));
}
__device__ __forceinline__ void mma_f16(float* c, const uint32_t* a, uint32_t b0, uint32_t b1) {
    asm volatile(
        "mma.sync.aligned.m16n8k16.row.col.f32.f16.f16.f32 "
        "{%0,%1,%2,%3}, {%4,%5,%6,%7}, {%8,%9}, {%0,%1,%2,%3};"
        : "+f"(c[0]), "+f"(c[1]), "+f"(c[2]), "+f"(c[3])
        : "r"(a[0]), "r"(a[1]), "r"(a[2]), "r"(a[3]), "r"(b0), "r"(b1));
}
__device__ __forceinline__ void cpa16(uint32_t dst, const void* src) {
    asm volatile("cp.async.cg.shared.global [%0], [%1], 16;" :: "r"(dst), "l"(src));
}
#define CP_COMMIT() asm volatile("cp.async.commit_group;" ::: "memory")
#define CP_WAIT0()  asm volatile("cp.async.wait_group 0;" ::: "memory")
#define CP_WAIT1()  asm volatile("cp.async.wait_group 1;" ::: "memory")

// =====================================================================
// prep_all_kernel: all weight/input image preps fused into one launch.
// Block ranges:
//  [0,512)      prep_x       (inputs -> bf16 hi/lo pairs)
//  [512,640)    W1 recv half -> g_w1r  (bf16 hi/lo, stride 272)
//  [640,768)    W1 send half -> g_w1s
//  [768,1024)   W2           -> g_w2img (fp16 hi, stride 528)
//  [1024,1120)  Wo1          -> g_wo1   (fp16, stride 784)
//  [1120,1184)  Wo2          -> g_wo2   (fp16, stride 528)
//  [1184,1216)  Wo3          -> g_wo3   (fp16, stride 528)
// =====================================================================
__device__ __forceinline__ void prep_w_body(const float* Wk, int koff, int f0, int nn0,
                                            int kt, unsigned char* img, int rstride,
                                            float ts[32][33], int tid)
{
#pragma unroll
    for (int p = 0; p < 4; ++p) {
        int fr = (tid >> 5) + p * 8, nl = tid & 31;
        ts[fr][nl] = Wk[(size_t)(koff + f0 + fr) * 256 + nn0 + nl];
    }
    __syncthreads();
#pragma unroll
    for (int p = 0; p < 2; ++p) {
        int idx = tid + p * 256;
        int nr = idx >> 4, wp = idx & 15;
        uint32_t hi, lo;
        split2(make_float2(ts[2 * wp][nr], ts[2 * wp + 1][nr]), hi, lo);
        size_t rb = (size_t)(nn0 + nr) * rstride + (f0 + 2 * wp) * 2;
        *(uint32_t*)(img + (size_t)(kt * 2 + 0) * 256 * rstride + rb) = hi;
        *(uint32_t*)(img + (size_t)(kt * 2 + 1) * 256 * rstride + rb) = lo;
    }
}
__device__ __forceinline__ void prep_h_body(const float* W, int Ncols, int f0, int nn0,
                                            unsigned char* img, int rstride,
                                            float ts[32][33], int tid)
{
#pragma unroll
    for (int p = 0; p < 4; ++p) {
        int fr = (tid >> 5) + p * 8, nl = tid & 31;
        ts[fr][nl] = W[(size_t)(f0 + fr) * Ncols + nn0 + nl];
    }
    __syncthreads();
#pragma unroll
    for (int p = 0; p < 2; ++p) {
        int idx = tid + p * 256;
        int nr = idx >> 4, wp = idx & 15;
        *(uint32_t*)(img + (size_t)(nn0 + nr) * rstride + (f0 + 2 * wp) * 2) =
            h2pack(ts[2 * wp][nr], ts[2 * wp + 1][nr]);
    }
}

__global__ void __launch_bounds__(256)
prep_all_kernel(const float* __restrict__ inputs,
                const float* __restrict__ W1, const float* __restrict__ W2,
                const float* __restrict__ Wo1, const float* __restrict__ Wo2,
                const float* __restrict__ Wo3,
                uint32_t* __restrict__ xhi, uint32_t* __restrict__ xlo,
                unsigned char* __restrict__ w1r, unsigned char* __restrict__ w1s,
                unsigned char* __restrict__ w2i,
                unsigned char* __restrict__ wo1i, unsigned char* __restrict__ wo2i,
                unsigned char* __restrict__ wo3i)
{
    __shared__ float ts[32][33];
    const int bid = blockIdx.x, tid = threadIdx.x;

    if (bid < 512) {                       // prep_x
        int idx = bid * 256 + tid;
        float2 v = ((const float2*)inputs)[idx];
        uint32_t hi, lo;
        split2(v, hi, lo);
        xhi[idx] = hi;
        xlo[idx] = lo;
    } else if (bid < 640) {                // W1 recv
        int b2 = bid - 512;
        prep_w_body(W1 + (size_t)(b2 >> 5) * 65536, 0, (b2 & 3) * 32,
                    ((b2 >> 2) & 7) * 32, b2 >> 5, w1r, 272, ts, tid);
    } else if (bid < 768) {                // W1 send
        int b2 = bid - 640;
        prep_w_body(W1 + (size_t)(b2 >> 5) * 65536, 128, (b2 & 3) * 32,
                    ((b2 >> 2) & 7) * 32, b2 >> 5, w1s, 272, ts, tid);
    } else if (bid < 1024) {               // W2 (fp16 hi, per k-type)
        int b3 = bid - 768;
        int f0 = (b3 & 7) * 32, nn0 = ((b3 >> 3) & 7) * 32, kt = b3 >> 6;
        prep_h_body(W2 + (size_t)kt * 65536, 256, f0, nn0,
                    w2i + (size_t)kt * 256 * 528, 528, ts, tid);
    } else if (bid < 1120) {               // Wo1
        int b4 = bid - 1024;
        prep_h_body(Wo1, 256, (b4 % 12) * 32, (b4 / 12) * 32, wo1i, 784, ts, tid);
    } else if (bid < 1184) {               // Wo2
        int b5 = bid - 1120;
        prep_h_body(Wo2, 256, (b5 & 7) * 32, (b5 >> 3) * 32, wo2i, 528, ts, tid);
    } else {                               // Wo3
        int b6 = bid - 1184;
        prep_h_body(Wo3, 128, (b6 & 7) * 32, (b6 >> 3) * 32, wo3i, 528, ts, tid);
    }
}

// =====================================================================
// ns_kernel: per (k,b,z) node GEMM [64x128]@[128x128] (3-split bf16).
// half 0 -> g_hb fp32 (x@W1_recv + b1); half 1 -> g_simg fp16 (x@W1_send).
// =====================================================================
#define NS_XHI 0
#define NS_XLO 17408
#define NS_W   34816
#define NS_B1  69632
#define NS_TOTAL 70656

__global__ void __launch_bounds__(256)
ns_kernel(const uint32_t* __restrict__ xhi, const uint32_t* __restrict__ xlo,
          const unsigned char* __restrict__ w1r, const unsigned char* __restrict__ w1s,
          const float* __restrict__ b1, float* __restrict__ hb, uint16_t* __restrict__ simg)
{
    extern __shared__ char smem[];
    const uint32_t sb = smem_u32(smem);
    const int tid = threadIdx.x, lane = tid & 31, w = tid >> 5;
    const int k = blockIdx.x, b = blockIdx.y;
    const int half = blockIdx.z >> 1, s0 = (blockIdx.z & 1) * 2;

    for (int t = tid; t < 1024; t += 256) {
        int row = t >> 4, sgi = t & 15;
        size_t so = (size_t)(b * 64 + row) * 64 + sgi * 4;
        cpa16(sb + NS_XHI + row * 272 + sgi * 16, xhi + so);
        cpa16(sb + NS_XLO + row * 272 + sgi * 16, xlo + so);
    }
    CP_COMMIT();
    if (tid < 64) ((float4*)(smem + NS_B1))[tid] = ((const float4*)(b1 + k * 256))[tid];

    const int g = lane >> 2, tg = lane & 3;
    const int arow = lane & 15;
    const uint32_t aoff = (uint32_t)((lane >> 4) << 4);
    const int brow = (lane & 7) + ((lane >> 4) << 3);
    const uint32_t boff = (uint32_t)((lane & 8) << 1);
    const int wm = w & 3, wn = w >> 2;
    const int m0 = wm * 16;
    const float* b1s = (const float*)(smem + NS_B1);
    const unsigned char* img = half ? w1s : w1r;
    float* outh = hb + ((size_t)k * BB + b) * 64 * 256;
    uint32_t* outs = (uint32_t*)simg + ((size_t)k * BB + b) * 64 * 128;

#pragma unroll 1
    for (int si = 0; si < 2; ++si) {
        int s = s0 + si;
        for (int t = tid; t < 2176; t += 256) {
            int im = t >= 1088;
            uint32_t off = (uint32_t)(t - im * 1088) * 16;
            cpa16(sb + NS_W + (im ? 17408 : 0) + off,
                  img + (size_t)((k * 2 + im) * 256 + s * 64) * 272 + off);
        }
        CP_COMMIT(); CP_WAIT0();
        __syncthreads();
        float c[4][4] = {};
#pragma unroll
        for (int sp = 0; sp < 3; ++sp) {
            uint32_t Ab = sb + (sp == 2 ? NS_XLO : NS_XHI) + (m0 + arow) * 272 + aoff;
            uint32_t Bb = sb + NS_W + (sp == 1 ? 17408u : 0u) + (wn * 32 + brow) * 272 + boff;
#pragma unroll
            for (int ks = 0; ks < 8; ++ks) {
                uint32_t a[4], b0[4], b1f[4];
                ldm4(Ab + ks * 32, a);
                ldm4(Bb + ks * 32, b0);
                ldm4(Bb + 16 * 272 + ks * 32, b1f);
                mma_bf16(c[0], a, b0[0], b0[1]);
                mma_bf16(c[1], a, b0[2], b0[3]);
                mma_bf16(c[2], a, b1f[0], b1f[1]);
                mma_bf16(c[3], a, b1f[2], b1f[3]);
            }
        }
        int r0 = m0 + g, r1 = r0 + 8;
        int cn = s * 64 + wn * 32;
        if (half == 0) {
#pragma unroll
            for (int t = 0; t < 4; ++t) {
                int col = cn + t * 8 + 2 * tg;
                outh[(size_t)r0 * 256 + col]     = c[t][0] + b1s[col];
                outh[(size_t)r0 * 256 + col + 1] = c[t][1] + b1s[col + 1];
                outh[(size_t)r1 * 256 + col]     = c[t][2] + b1s[col];
                outh[(size_t)r1 * 256 + col + 1] = c[t][3] + b1s[col + 1];
            }
        } else {
#pragma unroll
            for (int t = 0; t < 4; ++t) {
                int col = cn + t * 8 + 2 * tg;
                outs[(size_t)r0 * 128 + (col >> 1)] = h2pack(c[t][0], c[t][1]);
                outs[(size_t)r1 * 128 + (col >> 1)] = h2pack(c[t][2], c[t][3]);
            }
        }
        __syncthreads();
    }
}

// ---------------- SMEM map (bytes) for edge kernel ----------------
#define SE_S    0         // 64 x 528 (fp16) = 33792
#define SE_W2   33792     // 2 x 16896 -> 67584
#define SE_HBS  67584     // 2 x 256 f32 = 2048 -> 69632
#define SE_B2S  69632     // 1024 -> 70656
#define SE_RTS  70656     // 128 x 16 = 2048 -> 72704
#define SE_AGG  72704     // 8 x 256 f32 = 8192 -> 80896
#define SE_TOTAL 80896

// =====================================================================
// Edge kernel: block = (2 nodes, batch), 256 threads, 2 blocks/SM.
// =====================================================================
__global__ void __launch_bounds__(256, 2)
edge_kernel(const float* __restrict__ rel_type,
            const unsigned char* __restrict__ w2img,
            const uint16_t* __restrict__ simg,
            const float* __restrict__ hb,
            const float* __restrict__ b2,
            float* __restrict__ agg)
{
    extern __shared__ char smem[];
    const uint32_t sb = smem_u32(smem);
    const int tid = threadIdx.x;
    const int lane = tid & 31, w = tid >> 5;
    const int n0 = blockIdx.x * 2, b = blockIdx.y;

    if (tid < 128) {
        int node = n0 + (tid >> 6), le = tid & 63;
        float4 v = make_float4(0.f, 0.f, 0.f, 0.f);
        if (le < 63) v = *(const float4*)(rel_type + ((size_t)b * EE + node * 63 + le) * KK);
        *(float4*)(smem + SE_RTS + tid * 16) = v;
    }
    for (int i = tid; i < 2048; i += 256) ((float*)(smem + SE_AGG))[i] = 0.f;

    const int g = lane >> 2, tg = lane & 3;
    const int brow = (lane & 7) + ((lane >> 4) << 3);
    const uint32_t boff = (uint32_t)((lane & 8) << 1);
    const int m0 = w * 16;
    const int nodeg = n0 + (w >> 2);
    const float* rts = (const float*)(smem + SE_RTS);
    const float* b2s = (const float*)(smem + SE_B2S);
    float* aggS = (float*)(smem + SE_AGG);

    const int rw0 = m0 + g, rw1 = rw0 + 8;
    const int le0 = rw0 & 63, le1 = rw1 & 63;
    const float msk0 = (le0 != 63) ? 1.f : 0.f;
    const float msk1 = (le1 != 63) ? 1.f : 0.f;
    const int j0 = (le0 != 63) ? (le0 + (le0 >= nodeg)) : 0;
    const int j1 = (le1 != 63) ? (le1 + (le1 >= nodeg)) : 0;

    uint32_t Ha[64];

#pragma unroll 1
    for (int k = 0; k < KK; ++k) {
        {
            const unsigned char* sk = (const unsigned char*)simg +
                                      ((size_t)k * BB + b) * 64 * 512;
            for (int t = tid; t < 2048; t += 256) {
                int row = t >> 5, ch = t & 31;
                cpa16(sb + SE_S + row * 528 + ch * 16, sk + (size_t)row * 512 + ch * 16);
            }
            CP_COMMIT();
        }
        for (int t = tid; t < 1056; t += 256)
            cpa16(sb + SE_W2 + t * 16, w2img + (size_t)(k * 256) * 528 + t * 16);
        CP_COMMIT();
        {
            const float* hbk = hb + (((size_t)k * BB + b) * 64 + n0) * 256;
            if (tid < 128) *(float4*)(smem + SE_HBS + tid * 16) = ((const float4*)hbk)[tid];
            else if (tid < 192)
                ((float4*)(smem + SE_B2S))[tid - 128] = ((const float4*)(b2 + k * 256))[tid - 128];
        }
        CP_WAIT1();
        __syncthreads();

        {
            const __half* S0 = (const __half*)(smem + SE_S) + j0 * 264;
            const __half* S1 = (const __half*)(smem + SE_S) + j1 * 264;
            const float* hbs = (const float*)(smem + SE_HBS) + (w >> 2) * 256;
#pragma unroll
            for (int ks = 0; ks < 16; ++ks) {
                int c = ks * 16 + 2 * tg;
                float2 h0 = *(const float2*)(hbs + c);
                float2 h8 = *(const float2*)(hbs + c + 8);
                __half2 a0 = *(const __half2*)(S0 + c);
                __half2 a8 = *(const __half2*)(S0 + c + 8);
                __half2 bq0 = *(const __half2*)(S1 + c);
                __half2 bq8 = *(const __half2*)(S1 + c + 8);
                Ha[ks*4+0] = h2pack(msk0 * fmaxf(h0.x + __low2float(a0), 0.f),
                                    msk0 * fmaxf(h0.y + __high2float(a0), 0.f));
                Ha[ks*4+1] = h2pack(msk1 * fmaxf(h0.x + __low2float(bq0), 0.f),
                                    msk1 * fmaxf(h0.y + __high2float(bq0), 0.f));
                Ha[ks*4+2] = h2pack(msk0 * fmaxf(h8.x + __low2float(a8), 0.f),
                                    msk0 * fmaxf(h8.y + __high2float(a8), 0.f));
                Ha[ks*4+3] = h2pack(msk1 * fmaxf(h8.x + __low2float(bq8), 0.f),
                                    msk1 * fmaxf(h8.y + __high2float(bq8), 0.f));
            }
        }

        const float wr0 = rts[rw0 * 4 + k], wr1 = rts[rw1 * 4 + k];
#pragma unroll 1
        for (int s = 0; s < 8; ++s) {
            CP_WAIT0();
            __syncthreads();
            if (s < 7) {
                uint32_t wb = SE_W2 + (uint32_t)(((s + 1) & 1) * 16896);
                for (int t = tid; t < 1056; t += 256)
                    cpa16(sb + wb + t * 16,
                          w2img + (size_t)(k * 256 + (s + 1) * 32) * 528 + t * 16);
                CP_COMMIT();
            }
            const uint32_t wbs = sb + SE_W2 + (uint32_t)((s & 1) * 16896) + brow * 528 + boff;
            float c[4][4] = {};
#pragma unroll
            for (int ks = 0; ks < 16; ++ks) {
                uint32_t b0[4], b1f[4];
                ldm4(wbs + ks * 32, b0);
                ldm4(wbs + 16 * 528 + ks * 32, b1f);
                const uint32_t* a = Ha + ks * 4;
                mma_f16(c[0], a, b0[0], b0[1]);
                mma_f16(c[1], a, b0[2], b0[3]);
                mma_f16(c[2], a, b1f[0], b1f[1]);
                mma_f16(c[3], a, b1f[2], b1f[3]);
            }
            float p0[4], p1[4];
#pragma unroll
            for (int t = 0; t < 4; ++t) {
                int col = s * 32 + t * 8 + 2 * tg;
                float bc0 = b2s[col], bc1 = b2s[col + 1];
                p0[t] = wr0 * fmaxf(c[t][0] + bc0, 0.f) + wr1 * fmaxf(c[t][2] + bc0, 0.f);
                p1[t] = wr0 * fmaxf(c[t][1] + bc1, 0.f) + wr1 * fmaxf(c[t][3] + bc1, 0.f);
            }
#pragma unroll
            for (int off = 4; off <= 16; off <<= 1)
#pragma unroll
                for (int t = 0; t < 4; ++t) {
                    p0[t] += __shfl_xor_sync(0xffffffff, p0[t], off);
                    p1[t] += __shfl_xor_sync(0xffffffff, p1[t], off);
                }
            if (g == 0) {
#pragma unroll
                for (int t = 0; t < 4; ++t) {
                    int col = s * 32 + t * 8 + 2 * tg;
                    aggS[w * 256 + col]     += p0[t];
                    aggS[w * 256 + col + 1] += p1[t];
                }
            }
        }
    }

    __syncthreads();
    for (int t = tid; t < 512; t += 256) {
        int ni = t >> 8, m = t & 255;
        agg[((size_t)b * NN + n0 + ni) * 256 + m] =
            aggS[(4 * ni + 0) * 256 + m] + aggS[(4 * ni + 1) * 256 + m] +
            aggS[(4 * ni + 2) * 256 + m] + aggS[(4 * ni + 3) * 256 + m];
    }
}

// =====================================================================
// Output MLP, tensor-core fp16: 16 rows/block, 128 threads, grid 128.
// =====================================================================
#define OT_A0 0
#define OT_A1 12544
#define OT_W  20992
#define OT_TOTAL 121344

__global__ void __launch_bounds__(128, 1)
out_tc_kernel(const float* __restrict__ inputs, const float* __restrict__ agg,
              const unsigned char* __restrict__ wo1, const unsigned char* __restrict__ wo2,
              const unsigned char* __restrict__ wo3,
              const float* __restrict__ bo1, const float* __restrict__ bo2,
              const float* __restrict__ bo3, float* __restrict__ out)
{
    extern __shared__ char smem[];
    const uint32_t sb = smem_u32(smem);
    const int tid = threadIdx.x, lane = tid & 31, w = tid >> 5;
    const int row0 = blockIdx.x * 16;

    const int g = lane >> 2, tg = lane & 3;
    const int arow = lane & 15;
    const uint32_t aoff = (uint32_t)((lane >> 4) << 4);
    const int brow = (lane & 7) + ((lane >> 4) << 3);
    const uint32_t boff = (uint32_t)((lane & 8) << 1);
    const int r0 = g, r1 = g + 8;

    for (int idx = tid; idx < 16 * 192; idx += 128) {
        int r = idx / 192, pc = idx % 192;
        float2 v;
        if (pc < 64) v = *(const float2*)(inputs + (size_t)(row0 + r) * FF + pc * 2);
        else         v = *(const float2*)(agg + (size_t)(row0 + r) * 256 + (pc - 64) * 2);
        *(uint32_t*)(smem + OT_A0 + r * 784 + pc * 4) = h2pack(v.x, v.y);
    }
    for (int t = tid; t < 3136; t += 128)
        cpa16(sb + OT_W + t * 16, wo1 + (size_t)t * 16);
    CP_COMMIT();
    __syncthreads();

#pragma unroll 1
    for (int s = 0; s < 4; ++s) {
        CP_WAIT0();
        __syncthreads();
        if (s < 3) {
            uint32_t wb = OT_W + (uint32_t)(((s + 1) & 1) * 50176);
            for (int t = tid; t < 3136; t += 128)
                cpa16(sb + wb + t * 16, wo1 + (size_t)((s + 1) * 64) * 784 + t * 16);
            CP_COMMIT();
        }
        const uint32_t wbs = sb + OT_W + (uint32_t)((s & 1) * 50176) + (w * 16 + brow) * 784 + boff;
        const uint32_t Ab = sb + OT_A0 + arow * 784 + aoff;
        float c[2][4] = {};
#pragma unroll
        for (int ks = 0; ks < 24; ++ks) {
            uint32_t a[4], bb[4];
            ldm4(Ab + ks * 32, a);
            ldm4(wbs + ks * 32, bb);
            mma_f16(c[0], a, bb[0], bb[1]);
            mma_f16(c[1], a, bb[2], bb[3]);
        }
#pragma unroll
        for (int t = 0; t < 2; ++t) {
            int col = s * 64 + w * 16 + t * 8 + 2 * tg;
            float bc0 = bo1[col], bc1 = bo1[col + 1];
            *(uint32_t*)(smem + OT_A1 + r0 * 528 + col * 2) =
                h2pack(fmaxf(c[t][0] + bc0, 0.f), fmaxf(c[t][1] + bc1, 0.f));
            *(uint32_t*)(smem + OT_A1 + r1 * 528 + col * 2) =
                h2pack(fmaxf(c[t][2] + bc0, 0.f), fmaxf(c[t][3] + bc1, 0.f));
        }
    }
    __syncthreads();
    for (int t = tid; t < 2112; t += 128)
        cpa16(sb + OT_W + t * 16, wo2 + (size_t)t * 16);
    CP_COMMIT();

#pragma unroll 1
    for (int s = 0; s < 4; ++s) {
        CP_WAIT0();
        __syncthreads();
        if (s < 3) {
            uint32_t wb = OT_W + (uint32_t)(((s + 1) & 1) * 50176);
            for (int t = tid; t < 2112; t += 128)
                cpa16(sb + wb + t * 16, wo2 + (size_t)((s + 1) * 64) * 528 + t * 16);
            CP_COMMIT();
        }
        const uint32_t wbs = sb + OT_W + (uint32_t)((s & 1) * 50176) + (w * 16 + brow) * 528 + boff;
        const uint32_t Ab = sb + OT_A1 + arow * 528 + aoff;
        float c[2][4] = {};
#pragma unroll
        for (int ks = 0; ks < 16; ++ks) {
            uint32_t a[4], bb[4];
            ldm4(Ab + ks * 32, a);
            ldm4(wbs + ks * 32, bb);
            mma_f16(c[0], a, bb[0], bb[1]);
            mma_f16(c[1], a, bb[2], bb[3]);
        }
#pragma unroll
        for (int t = 0; t < 2; ++t) {
            int col = s * 64 + w * 16 + t * 8 + 2 * tg;
            float bc0 = bo2[col], bc1 = bo2[col + 1];
            *(uint32_t*)(smem + OT_A0 + r0 * 528 + col * 2) =
                h2pack(fmaxf(c[t][0] + bc0, 0.f), fmaxf(c[t][1] + bc1, 0.f));
            *(uint32_t*)(smem + OT_A0 + r1 * 528 + col * 2) =
                h2pack(fmaxf(c[t][2] + bc0, 0.f), fmaxf(c[t][3] + bc1, 0.f));
        }
    }
    __syncthreads();
    for (int t = tid; t < 2112; t += 128)
        cpa16(sb + OT_W + t * 16, wo3 + (size_t)t * 16);
    CP_COMMIT();

#pragma unroll 1
    for (int s = 0; s < 2; ++s) {
        CP_WAIT0();
        __syncthreads();
        if (s < 1) {
            uint32_t wb = OT_W + 50176u;
            for (int t = tid; t < 2112; t += 128)
                cpa16(sb + wb + t * 16, wo3 + (size_t)64 * 528 + t * 16);
            CP_COMMIT();
        }
        const uint32_t wbs = sb + OT_W + (uint32_t)((s & 1) * 50176) + (w * 16 + brow) * 528 + boff;
        const uint32_t Ab = sb + OT_A0 + arow * 528 + aoff;
        float c[2][4] = {};
#pragma unroll
        for (int ks = 0; ks < 16; ++ks) {
            uint32_t a[4], bb[4];
            ldm4(Ab + ks * 32, a);
            ldm4(wbs + ks * 32, bb);
            mma_f16(c[0], a, bb[0], bb[1]);
            mma_f16(c[1], a, bb[2], bb[3]);
        }
#pragma unroll
        for (int t = 0; t < 2; ++t) {
            int col = s * 64 + w * 16 + t * 8 + 2 * tg;
            float bc0 = bo3[col], bc1 = bo3[col + 1];
            float2 e0 = *(const float2*)(inputs + (size_t)(row0 + r0) * FF + col);
            float2 e1 = *(const float2*)(inputs + (size_t)(row0 + r1) * FF + col);
            *(float2*)(out + (size_t)(row0 + r0) * FF + col) =
                make_float2(e0.x + c[t][0] + bc0, e0.y + c[t][1] + bc1);
            *(float2*)(out + (size_t)(row0 + r1) * FF + col) =
                make_float2(e1.x + c[t][2] + bc0, e1.y + c[t][3] + bc1);
        }
    }
}

// =====================================================================
extern "C" void kernel_launch(void* const* d_in, const int* in_sizes, int n_in,
                              void* d_out, int out_size)
{
    const float* inputs   = (const float*)d_in[0];
    const float* rel_type = (const float*)d_in[1];
    const float* W1  = (const float*)d_in[4];
    const float* b1  = (const float*)d_in[5];
    const float* W2  = (const float*)d_in[6];
    const float* b2  = (const float*)d_in[7];
    const float* Wo1 = (const float*)d_in[8];
    const float* bo1 = (const float*)d_in[9];
    const float* Wo2 = (const float*)d_in[10];
    const float* bo2 = (const float*)d_in[11];
    const float* Wo3 = (const float*)d_in[12];
    const float* bo3 = (const float*)d_in[13];
    float* out = (float*)d_out;

    float *agg, *hbp;
    uint16_t* simg;
    unsigned char *w1r, *w1s, *w2i, *wo1i, *wo2i, *wo3i;
    uint32_t *xhi, *xlo;
    cudaGetSymbolAddress((void**)&agg, g_agg);
    cudaGetSymbolAddress((void**)&hbp, g_hb);
    cudaGetSymbolAddress((void**)&simg, g_simg);
    cudaGetSymbolAddress((void**)&w1r, g_w1r);
    cudaGetSymbolAddress((void**)&w1s, g_w1s);
    cudaGetSymbolAddress((void**)&w2i, g_w2img);
    cudaGetSymbolAddress((void**)&wo1i, g_wo1);
    cudaGetSymbolAddress((void**)&wo2i, g_wo2);
    cudaGetSymbolAddress((void**)&wo3i, g_wo3);
    cudaGetSymbolAddress((void**)&xhi, g_ximg_hi);
    cudaGetSymbolAddress((void**)&xlo, g_ximg_lo);

    cudaFuncSetAttribute(edge_kernel, cudaFuncAttributeMaxDynamicSharedMemorySize, SE_TOTAL);
    cudaFuncSetAttribute(ns_kernel, cudaFuncAttributeMaxDynamicSharedMemorySize, NS_TOTAL);
    cudaFuncSetAttribute(out_tc_kernel, cudaFuncAttributeMaxDynamicSharedMemorySize, OT_TOTAL);

    prep_all_kernel<<<1216, 256>>>(inputs, W1, W2, Wo1, Wo2, Wo3,
                                   xhi, xlo, w1r, w1s, w2i, wo1i, wo2i, wo3i);
    ns_kernel<<<dim3(KK, BB, 4), 256, NS_TOTAL>>>(xhi, xlo, w1r, w1s, b1, hbp, simg);
    edge_kernel<<<dim3(NN / 2, BB), 256, SE_TOTAL>>>(rel_type, w2i, simg, hbp, b2, agg);
    out_tc_kernel<<<BB * NN / 16, 128, OT_TOTAL>>>(inputs, agg, wo1i, wo2i, wo3i,
                                                   bo1, bo2, bo3, out);
}

// round 14
// speedup vs baseline: 4.1588x; 1.0152x over previous
#include <cuda_runtime.h>
#include <cuda_bf16.h>
#include <cuda_fp16.h>
#include <cstdint>

#define BB 32
#define NN 64
#define FF 128
#define KK 4
#define EE 4032

// ---------------- static device scratch (no allocations) ----------------
__device__ __align__(16) unsigned char g_w1r[KK * 2 * 256 * 272];
__device__ __align__(16) unsigned char g_w1s[KK * 2 * 256 * 272];
__device__ __align__(16) unsigned char g_w2img[KK * 256 * 528];
__device__ __align__(16) unsigned char g_wo1[256 * 784];
__device__ __align__(16) unsigned char g_wo2[256 * 528];
__device__ __align__(16) unsigned char g_wo3[128 * 528];
__device__ __align__(16) uint32_t g_ximg_hi[BB * NN * 64];
__device__ __align__(16) uint32_t g_ximg_lo[BB * NN * 64];
__device__ __align__(16) float    g_hb[KK * BB * NN * 256];
__device__ __align__(16) uint16_t g_simg[KK * BB * NN * 256];
__device__ float g_agg[BB * NN * 256];

// ---------------- helpers ----------------
__device__ __forceinline__ uint32_t smem_u32(const void* p) {
    uint32_t a;
    asm("{ .reg .u64 t; cvta.to.shared.u64 t, %1; cvt.u32.u64 %0, t; }" : "=r"(a) : "l"(p));
    return a;
}
__device__ __forceinline__ void split2(float2 v, uint32_t& hi, uint32_t& lo) {  // bf16
    __nv_bfloat162 h2 = __float22bfloat162_rn(v);
    float2 r = make_float2(v.x - __bfloat162float(h2.x), v.y - __bfloat162float(h2.y));
    __nv_bfloat162 l2 = __float22bfloat162_rn(r);
    hi = reinterpret_cast<uint32_t&>(h2);
    lo = reinterpret_cast<uint32_t&>(l2);
}
__device__ __forceinline__ uint32_t h2pack(float a, float b) {
    __half2 h = __float22half2_rn(make_float2(a, b));
    return reinterpret_cast<uint32_t&>(h);
}
__device__ __forceinline__ void ldm4(uint32_t addr, uint32_t r[4]) {
    asm volatile("ldmatrix.sync.aligned.m8n8.x4.shared.b16 {%0,%1,%2,%3}, [%4];"
                 : "=r"(r[0]), "=r"(r[1]), "=r"(r[2]), "=r"(r[3]) : "r"(addr));
}
__device__ __forceinline__ void mma_bf16(float* c, const uint32_t* a, uint32_t b0, uint32_t b1) {
    asm volatile(
        "mma.sync.aligned.m16n8k16.row.col.f32.bf16.bf16.f32 "
        "{%0,%1,%2,%3}, {%4,%5,%6,%7}, {%8,%9}, {%0,%1,%2,%3};"
        : "+f"(c[0]), "+f"(c[1]), "+f"(c[2]), "+f"(c[3])
        : "r"(a[0]), "r"(a[1]), "r"(a[2]), "r"(a[3]), "r"(b0), "r"(b1));
}
__device__ __forceinline__ void mma_f16(float* c, const uint32_t* a, uint32_t b0, uint32_t b1) {
    asm volatile(
        "mma.sync.aligned.m16n8k16.row.col.f32.f16.f16.f32 "
        "{%0,%1,%2,%3}, {%4,%5,%6,%7}, {%8,%9}, {%0,%1,%2,%3};"
        : "+f"(c[0]), "+f"(c[1]), "+f"(c[2]), "+f"(c[3])
        : "r"(a[0]), "r"(a[1]), "r"(a[2]), "r"(a[3]), "r"(b0), "r"(b1));
}
__device__ __forceinline__ void cpa16(uint32_t dst, const void* src) {
    asm volatile("cp.async.cg.shared.global [%0], [%1], 16;" :: "r"(dst), "l"(src));
}
#define CP_COMMIT() asm volatile("cp.async.commit_group;" ::: "memory")
#define CP_WAIT0()  asm volatile("cp.async.wait_group 0;" ::: "memory")

// =====================================================================
// prep_all_kernel (unchanged from R13)
// =====================================================================
__device__ __forceinline__ void prep_w_body(const float* Wk, int koff, int f0, int nn0,
                                            int kt, unsigned char* img, int rstride,
                                            float ts[32][33], int tid)
{
#pragma unroll
    for (int p = 0; p < 4; ++p) {
        int fr = (tid >> 5) + p * 8, nl = tid & 31;
        ts[fr][nl] = Wk[(size_t)(koff + f0 + fr) * 256 + nn0 + nl];
    }
    __syncthreads();
#pragma unroll
    for (int p = 0; p < 2; ++p) {
        int idx = tid + p * 256;
        int nr = idx >> 4, wp = idx & 15;
        uint32_t hi, lo;
        split2(make_float2(ts[2 * wp][nr], ts[2 * wp + 1][nr]), hi, lo);
        size_t rb = (size_t)(nn0 + nr) * rstride + (f0 + 2 * wp) * 2;
        *(uint32_t*)(img + (size_t)(kt * 2 + 0) * 256 * rstride + rb) = hi;
        *(uint32_t*)(img + (size_t)(kt * 2 + 1) * 256 * rstride + rb) = lo;
    }
}
__device__ __forceinline__ void prep_h_body(const float* W, int Ncols, int f0, int nn0,
                                            unsigned char* img, int rstride,
                                            float ts[32][33], int tid)
{
#pragma unroll
    for (int p = 0; p < 4; ++p) {
        int fr = (tid >> 5) + p * 8, nl = tid & 31;
        ts[fr][nl] = W[(size_t)(f0 + fr) * Ncols + nn0 + nl];
    }
    __syncthreads();
#pragma unroll
    for (int p = 0; p < 2; ++p) {
        int idx = tid + p * 256;
        int nr = idx >> 4, wp = idx & 15;
        *(uint32_t*)(img + (size_t)(nn0 + nr) * rstride + (f0 + 2 * wp) * 2) =
            h2pack(ts[2 * wp][nr], ts[2 * wp + 1][nr]);
    }
}

__global__ void __launch_bounds__(256)
prep_all_kernel(const float* __restrict__ inputs,
                const float* __restrict__ W1, const float* __restrict__ W2,
                const float* __restrict__ Wo1, const float* __restrict__ Wo2,
                const float* __restrict__ Wo3,
                uint32_t* __restrict__ xhi, uint32_t* __restrict__ xlo,
                unsigned char* __restrict__ w1r, unsigned char* __restrict__ w1s,
                unsigned char* __restrict__ w2i,
                unsigned char* __restrict__ wo1i, unsigned char* __restrict__ wo2i,
                unsigned char* __restrict__ wo3i)
{
    __shared__ float ts[32][33];
    const int bid = blockIdx.x, tid = threadIdx.x;

    if (bid < 512) {
        int idx = bid * 256 + tid;
        float2 v = ((const float2*)inputs)[idx];
        uint32_t hi, lo;
        split2(v, hi, lo);
        xhi[idx] = hi;
        xlo[idx] = lo;
    } else if (bid < 640) {
        int b2 = bid - 512;
        prep_w_body(W1 + (size_t)(b2 >> 5) * 65536, 0, (b2 & 3) * 32,
                    ((b2 >> 2) & 7) * 32, b2 >> 5, w1r, 272, ts, tid);
    } else if (bid < 768) {
        int b2 = bid - 640;
        prep_w_body(W1 + (size_t)(b2 >> 5) * 65536, 128, (b2 & 3) * 32,
                    ((b2 >> 2) & 7) * 32, b2 >> 5, w1s, 272, ts, tid);
    } else if (bid < 1024) {
        int b3 = bid - 768;
        int f0 = (b3 & 7) * 32, nn0 = ((b3 >> 3) & 7) * 32, kt = b3 >> 6;
        prep_h_body(W2 + (size_t)kt * 65536, 256, f0, nn0,
                    w2i + (size_t)kt * 256 * 528, 528, ts, tid);
    } else if (bid < 1120) {
        int b4 = bid - 1024;
        prep_h_body(Wo1, 256, (b4 % 12) * 32, (b4 / 12) * 32, wo1i, 784, ts, tid);
    } else if (bid < 1184) {
        int b5 = bid - 1120;
        prep_h_body(Wo2, 256, (b5 & 7) * 32, (b5 >> 3) * 32, wo2i, 528, ts, tid);
    } else {
        int b6 = bid - 1184;
        prep_h_body(Wo3, 128, (b6 & 7) * 32, (b6 >> 3) * 32, wo3i, 528, ts, tid);
    }
}

// =====================================================================
// ns_kernel (unchanged from R13)
// =====================================================================
#define NS_XHI 0
#define NS_XLO 17408
#define NS_W   34816
#define NS_B1  69632
#define NS_TOTAL 70656

__global__ void __launch_bounds__(256)
ns_kernel(const uint32_t* __restrict__ xhi, const uint32_t* __restrict__ xlo,
          const unsigned char* __restrict__ w1r, const unsigned char* __restrict__ w1s,
          const float* __restrict__ b1, float* __restrict__ hb, uint16_t* __restrict__ simg)
{
    extern __shared__ char smem[];
    const uint32_t sb = smem_u32(smem);
    const int tid = threadIdx.x, lane = tid & 31, w = tid >> 5;
    const int k = blockIdx.x, b = blockIdx.y;
    const int half = blockIdx.z >> 1, s0 = (blockIdx.z & 1) * 2;

    for (int t = tid; t < 1024; t += 256) {
        int row = t >> 4, sgi = t & 15;
        size_t so = (size_t)(b * 64 + row) * 64 + sgi * 4;
        cpa16(sb + NS_XHI + row * 272 + sgi * 16, xhi + so);
        cpa16(sb + NS_XLO + row * 272 + sgi * 16, xlo + so);
    }
    CP_COMMIT();
    if (tid < 64) ((float4*)(smem + NS_B1))[tid] = ((const float4*)(b1 + k * 256))[tid];

    const int g = lane >> 2, tg = lane & 3;
    const int arow = lane & 15;
    const uint32_t aoff = (uint32_t)((lane >> 4) << 4);
    const int brow = (lane & 7) + ((lane >> 4) << 3);
    const uint32_t boff = (uint32_t)((lane & 8) << 1);
    const int wm = w & 3, wn = w >> 2;
    const int m0 = wm * 16;
    const float* b1s = (const float*)(smem + NS_B1);
    const unsigned char* img = half ? w1s : w1r;
    float* outh = hb + ((size_t)k * BB + b) * 64 * 256;
    uint32_t* outs = (uint32_t*)simg + ((size_t)k * BB + b) * 64 * 128;

#pragma unroll 1
    for (int si = 0; si < 2; ++si) {
        int s = s0 + si;
        for (int t = tid; t < 2176; t += 256) {
            int im = t >= 1088;
            uint32_t off = (uint32_t)(t - im * 1088) * 16;
            cpa16(sb + NS_W + (im ? 17408 : 0) + off,
                  img + (size_t)((k * 2 + im) * 256 + s * 64) * 272 + off);
        }
        CP_COMMIT(); CP_WAIT0();
        __syncthreads();
        float c[4][4] = {};
#pragma unroll
        for (int sp = 0; sp < 3; ++sp) {
            uint32_t Ab = sb + (sp == 2 ? NS_XLO : NS_XHI) + (m0 + arow) * 272 + aoff;
            uint32_t Bb = sb + NS_W + (sp == 1 ? 17408u : 0u) + (wn * 32 + brow) * 272 + boff;
#pragma unroll
            for (int ks = 0; ks < 8; ++ks) {
                uint32_t a[4], b0[4], b1f[4];
                ldm4(Ab + ks * 32, a);
                ldm4(Bb + ks * 32, b0);
                ldm4(Bb + 16 * 272 + ks * 32, b1f);
                mma_bf16(c[0], a, b0[0], b0[1]);
                mma_bf16(c[1], a, b0[2], b0[3]);
                mma_bf16(c[2], a, b1f[0], b1f[1]);
                mma_bf16(c[3], a, b1f[2], b1f[3]);
            }
        }
        int r0 = m0 + g, r1 = r0 + 8;
        int cn = s * 64 + wn * 32;
        if (half == 0) {
#pragma unroll
            for (int t = 0; t < 4; ++t) {
                int col = cn + t * 8 + 2 * tg;
                outh[(size_t)r0 * 256 + col]     = c[t][0] + b1s[col];
                outh[(size_t)r0 * 256 + col + 1] = c[t][1] + b1s[col + 1];
                outh[(size_t)r1 * 256 + col]     = c[t][2] + b1s[col];
                outh[(size_t)r1 * 256 + col + 1] = c[t][3] + b1s[col + 1];
            }
        } else {
#pragma unroll
            for (int t = 0; t < 4; ++t) {
                int col = cn + t * 8 + 2 * tg;
                outs[(size_t)r0 * 128 + (col >> 1)] = h2pack(c[t][0], c[t][1]);
                outs[(size_t)r1 * 128 + (col >> 1)] = h2pack(c[t][2], c[t][3]);
            }
        }
        __syncthreads();
    }
}

// ---------------- SMEM map (bytes) for edge kernel ----------------
#define SE_S    0         // 64 x 528 (fp16) = 33792 (single buffer)
#define SE_W2   33792     // 2 x 33792 (64-col slabs) -> 101376
#define SE_HBS  101376    // 2048 -> 103424
#define SE_B2S  103424    // 1024 -> 104448
#define SE_RTS  104448    // 2048 -> 106496
#define SE_AGG  106496    // 8192 -> 114688
#define SE_TOTAL 114688

// =====================================================================
// Edge kernel: block = (2 nodes, batch), 256 threads, 2 blocks/SM.
// W2 slabs of 64 cols (4 barrier rounds per k), computed as 2x32-col passes.
// S single-buffered; S(k+1) rides the s==2 prefetch group.
// =====================================================================
__global__ void __launch_bounds__(256, 2)
edge_kernel(const float* __restrict__ rel_type,
            const unsigned char* __restrict__ w2img,
            const uint16_t* __restrict__ simg,
            const float* __restrict__ hb,
            const float* __restrict__ b2,
            float* __restrict__ agg)
{
    extern __shared__ char smem[];
    const uint32_t sb = smem_u32(smem);
    const int tid = threadIdx.x;
    const int lane = tid & 31, w = tid >> 5;
    const int n0 = blockIdx.x * 2, b = blockIdx.y;

    // prologue group: S(k=0) + W2 slab 0 (64 cols)
    {
        const unsigned char* sk = (const unsigned char*)simg + (size_t)b * 64 * 512;
        for (int t = tid; t < 2048; t += 256) {
            int row = t >> 5, ch = t & 31;
            cpa16(sb + SE_S + row * 528 + ch * 16, sk + (size_t)row * 512 + ch * 16);
        }
        for (int t = tid; t < 2112; t += 256)
            cpa16(sb + SE_W2 + t * 16, w2img + (size_t)t * 16);
        CP_COMMIT();
    }

    if (tid < 128) {
        int node = n0 + (tid >> 6), le = tid & 63;
        float4 v = make_float4(0.f, 0.f, 0.f, 0.f);
        if (le < 63) v = *(const float4*)(rel_type + ((size_t)b * EE + node * 63 + le) * KK);
        *(float4*)(smem + SE_RTS + tid * 16) = v;
    }
    for (int i = tid; i < 2048; i += 256) ((float*)(smem + SE_AGG))[i] = 0.f;

    const int g = lane >> 2, tg = lane & 3;
    const int brow = (lane & 7) + ((lane >> 4) << 3);
    const uint32_t boff = (uint32_t)((lane & 8) << 1);
    const int m0 = w * 16;
    const int nodeg = n0 + (w >> 2);
    const float* rts = (const float*)(smem + SE_RTS);
    const float* b2s = (const float*)(smem + SE_B2S);
    float* aggS = (float*)(smem + SE_AGG);

    const int rw0 = m0 + g, rw1 = rw0 + 8;
    const int le0 = rw0 & 63, le1 = rw1 & 63;
    const float msk0 = (le0 != 63) ? 1.f : 0.f;
    const float msk1 = (le1 != 63) ? 1.f : 0.f;
    const int j0 = (le0 != 63) ? (le0 + (le0 >= nodeg)) : 0;
    const int j1 = (le1 != 63) ? (le1 + (le1 >= nodeg)) : 0;

    uint32_t Ha[64];

#pragma unroll 1
    for (int k = 0; k < KK; ++k) {
        // hbase rows (2 nodes) + b2 via plain loads
        {
            const float* hbk = hb + (((size_t)k * BB + b) * 64 + n0) * 256;
            if (tid < 128) *(float4*)(smem + SE_HBS + tid * 16) = ((const float4*)hbk)[tid];
            else if (tid < 192)
                ((float4*)(smem + SE_B2S))[tid - 128] = ((const float4*)(b2 + k * 256))[tid - 128];
        }
        if (k == 0) CP_WAIT0();   // S(0)+slab0; for k>0 S(k) already waited at prior s==3
        __syncthreads();

        // ---- H fragments: relu(hbase + S), fp16 ----
        {
            const __half* S0 = (const __half*)(smem + SE_S) + j0 * 264;
            const __half* S1 = (const __half*)(smem + SE_S) + j1 * 264;
            const float* hbs = (const float*)(smem + SE_HBS) + (w >> 2) * 256;
#pragma unroll
            for (int ks = 0; ks < 16; ++ks) {
                int c = ks * 16 + 2 * tg;
                float2 h0 = *(const float2*)(hbs + c);
                float2 h8 = *(const float2*)(hbs + c + 8);
                __half2 a0 = *(const __half2*)(S0 + c);
                __half2 a8 = *(const __half2*)(S0 + c + 8);
                __half2 bq0 = *(const __half2*)(S1 + c);
                __half2 bq8 = *(const __half2*)(S1 + c + 8);
                Ha[ks*4+0] = h2pack(msk0 * fmaxf(h0.x + __low2float(a0), 0.f),
                                    msk0 * fmaxf(h0.y + __high2float(a0), 0.f));
                Ha[ks*4+1] = h2pack(msk1 * fmaxf(h0.x + __low2float(bq0), 0.f),
                                    msk1 * fmaxf(h0.y + __high2float(bq0), 0.f));
                Ha[ks*4+2] = h2pack(msk0 * fmaxf(h8.x + __low2float(a8), 0.f),
                                    msk0 * fmaxf(h8.y + __high2float(a8), 0.f));
                Ha[ks*4+3] = h2pack(msk1 * fmaxf(h8.x + __low2float(bq8), 0.f),
                                    msk1 * fmaxf(h8.y + __high2float(bq8), 0.f));
            }
        }

        const float wr0 = rts[rw0 * 4 + k], wr1 = rts[rw1 * 4 + k];
#pragma unroll 1
        for (int s = 0; s < 4; ++s) {
            const int gs = k * 4 + s;
            CP_WAIT0();        // slab gs (and, at s==3, S(k+1)) resident
            __syncthreads();   // all warps done with the other buffer
            if (gs < 15) {
                const int nk = (gs + 1) >> 2, nslab = (gs + 1) & 3;
                uint32_t wb = SE_W2 + (uint32_t)(((gs + 1) & 1) * 33792);
                for (int t = tid; t < 2112; t += 256)
                    cpa16(sb + wb + t * 16,
                          w2img + (size_t)(nk * 256 + nslab * 64) * 528 + t * 16);
                if (s == 2 && k < 3) {   // S(k+1) rides in this group
                    const unsigned char* sk = (const unsigned char*)simg +
                                              ((size_t)(k + 1) * BB + b) * 64 * 512;
                    for (int t = tid; t < 2048; t += 256) {
                        int row = t >> 5, ch = t & 31;
                        cpa16(sb + SE_S + row * 528 + ch * 16,
                              sk + (size_t)row * 512 + ch * 16);
                    }
                }
                CP_COMMIT();
            }
            const uint32_t wbase = sb + SE_W2 + (uint32_t)((s & 1) * 33792);
#pragma unroll
            for (int h = 0; h < 2; ++h) {
                const uint32_t wbs = wbase + (h * 32 + brow) * 528 + boff;
                float c[4][4] = {};
#pragma unroll
                for (int ks = 0; ks < 16; ++ks) {
                    uint32_t b0[4], b1f[4];
                    ldm4(wbs + ks * 32, b0);
                    ldm4(wbs + 16 * 528 + ks * 32, b1f);
                    const uint32_t* a = Ha + ks * 4;
                    mma_f16(c[0], a, b0[0], b0[1]);
                    mma_f16(c[1], a, b0[2], b0[3]);
                    mma_f16(c[2], a, b1f[0], b1f[1]);
                    mma_f16(c[3], a, b1f[2], b1f[3]);
                }
                float p0[4], p1[4];
#pragma unroll
                for (int t = 0; t < 4; ++t) {
                    int col = s * 64 + h * 32 + t * 8 + 2 * tg;
                    float bc0 = b2s[col], bc1 = b2s[col + 1];
                    p0[t] = wr0 * fmaxf(c[t][0] + bc0, 0.f) + wr1 * fmaxf(c[t][2] + bc0, 0.f);
                    p1[t] = wr0 * fmaxf(c[t][1] + bc1, 0.f) + wr1 * fmaxf(c[t][3] + bc1, 0.f);
                }
#pragma unroll
                for (int off = 4; off <= 16; off <<= 1)
#pragma unroll
                    for (int t = 0; t < 4; ++t) {
                        p0[t] += __shfl_xor_sync(0xffffffff, p0[t], off);
                        p1[t] += __shfl_xor_sync(0xffffffff, p1[t], off);
                    }
                if (g == 0) {
#pragma unroll
                    for (int t = 0; t < 4; ++t) {
                        int col = s * 64 + h * 32 + t * 8 + 2 * tg;
                        aggS[w * 256 + col]     += p0[t];
                        aggS[w * 256 + col + 1] += p1[t];
                    }
                }
            }
        }
    }

    __syncthreads();
    for (int t = tid; t < 512; t += 256) {
        int ni = t >> 8, m = t & 255;
        agg[((size_t)b * NN + n0 + ni) * 256 + m] =
            aggS[(4 * ni + 0) * 256 + m] + aggS[(4 * ni + 1) * 256 + m] +
            aggS[(4 * ni + 2) * 256 + m] + aggS[(4 * ni + 3) * 256 + m];
    }
}

// =====================================================================
// Output MLP, tensor-core fp16: 16 rows/block, 128 threads, grid 128.
// Single W buffer -> 71168 B SMEM -> 3 blocks/SM.
// =====================================================================
#define OT_A0 0          // 16 x 784 = 12544
#define OT_A1 12544      // 16 x 528 = 8448 -> 20992
#define OT_W  20992      // 50176 -> 71168
#define OT_TOTAL 71168

__global__ void __launch_bounds__(128, 3)
out_tc_kernel(const float* __restrict__ inputs, const float* __restrict__ agg,
              const unsigned char* __restrict__ wo1, const unsigned char* __restrict__ wo2,
              const unsigned char* __restrict__ wo3,
              const float* __restrict__ bo1, const float* __restrict__ bo2,
              const float* __restrict__ bo3, float* __restrict__ out)
{
    extern __shared__ char smem[];
    const uint32_t sb = smem_u32(smem);
    const int tid = threadIdx.x, lane = tid & 31, w = tid >> 5;
    const int row0 = blockIdx.x * 16;

    const int g = lane >> 2, tg = lane & 3;
    const int arow = lane & 15;
    const uint32_t aoff = (uint32_t)((lane >> 4) << 4);
    const int brow = (lane & 7) + ((lane >> 4) << 3);
    const uint32_t boff = (uint32_t)((lane & 8) << 1);
    const int r0 = g, r1 = g + 8;

    for (int idx = tid; idx < 16 * 192; idx += 128) {
        int r = idx / 192, pc = idx % 192;
        float2 v;
        if (pc < 64) v = *(const float2*)(inputs + (size_t)(row0 + r) * FF + pc * 2);
        else         v = *(const float2*)(agg + (size_t)(row0 + r) * 256 + (pc - 64) * 2);
        *(uint32_t*)(smem + OT_A0 + r * 784 + pc * 4) = h2pack(v.x, v.y);
    }

    // ---- layer 1: K=384 (24 ks), N=256 (4 slabs of 64), relu -> A1 ----
#pragma unroll 1
    for (int s = 0; s < 4; ++s) {
        __syncthreads();   // prior slab reads done (and A0 writes on s==0)
        for (int t = tid; t < 3136; t += 128)
            cpa16(sb + OT_W + t * 16, wo1 + (size_t)(s * 64) * 784 + t * 16);
        CP_COMMIT(); CP_WAIT0();
        __syncthreads();
        const uint32_t wbs = sb + OT_W + (w * 16 + brow) * 784 + boff;
        const uint32_t Ab = sb + OT_A0 + arow * 784 + aoff;
        float c[2][4] = {};
#pragma unroll
        for (int ks = 0; ks < 24; ++ks) {
            uint32_t a[4], bb[4];
            ldm4(Ab + ks * 32, a);
            ldm4(wbs + ks * 32, bb);
            mma_f16(c[0], a, bb[0], bb[1]);
            mma_f16(c[1], a, bb[2], bb[3]);
        }
#pragma unroll
        for (int t = 0; t < 2; ++t) {
            int col = s * 64 + w * 16 + t * 8 + 2 * tg;
            float bc0 = bo1[col], bc1 = bo1[col + 1];
            *(uint32_t*)(smem + OT_A1 + r0 * 528 + col * 2) =
                h2pack(fmaxf(c[t][0] + bc0, 0.f), fmaxf(c[t][1] + bc1, 0.f));
            *(uint32_t*)(smem + OT_A1 + r1 * 528 + col * 2) =
                h2pack(fmaxf(c[t][2] + bc0, 0.f), fmaxf(c[t][3] + bc1, 0.f));
        }
    }

    // ---- layer 2: K=256 (16 ks), N=256, relu -> A0 (stride 528) ----
#pragma unroll 1
    for (int s = 0; s < 4; ++s) {
        __syncthreads();
        for (int t = tid; t < 2112; t += 128)
            cpa16(sb + OT_W + t * 16, wo2 + (size_t)(s * 64) * 528 + t * 16);
        CP_COMMIT(); CP_WAIT0();
        __syncthreads();
        const uint32_t wbs = sb + OT_W + (w * 16 + brow) * 528 + boff;
        const uint32_t Ab = sb + OT_A1 + arow * 528 + aoff;
        float c[2][4] = {};
#pragma unroll
        for (int ks = 0; ks < 16; ++ks) {
            uint32_t a[4], bb[4];
            ldm4(Ab + ks * 32, a);
            ldm4(wbs + ks * 32, bb);
            mma_f16(c[0], a, bb[0], bb[1]);
            mma_f16(c[1], a, bb[2], bb[3]);
        }
#pragma unroll
        for (int t = 0; t < 2; ++t) {
            int col = s * 64 + w * 16 + t * 8 + 2 * tg;
            float bc0 = bo2[col], bc1 = bo2[col + 1];
            *(uint32_t*)(smem + OT_A0 + r0 * 528 + col * 2) =
                h2pack(fmaxf(c[t][0] + bc0, 0.f), fmaxf(c[t][1] + bc1, 0.f));
            *(uint32_t*)(smem + OT_A0 + r1 * 528 + col * 2) =
                h2pack(fmaxf(c[t][2] + bc0, 0.f), fmaxf(c[t][3] + bc1, 0.f));
        }
    }

    // ---- layer 3: K=256 (16 ks), N=128 (2 slabs), + residual -> out ----
#pragma unroll 1
    for (int s = 0; s < 2; ++s) {
        __syncthreads();
        for (int t = tid; t < 2112; t += 128)
            cpa16(sb + OT_W + t * 16, wo3 + (size_t)(s * 64) * 528 + t * 16);
        CP_COMMIT(); CP_WAIT0();
        __syncthreads();
        const uint32_t wbs = sb + OT_W + (w * 16 + brow) * 528 + boff;
        const uint32_t Ab = sb + OT_A0 + arow * 528 + aoff;
        float c[2][4] = {};
#pragma unroll
        for (int ks = 0; ks < 16; ++ks) {
            uint32_t a[4], bb[4];
            ldm4(Ab + ks * 32, a);
            ldm4(wbs + ks * 32, bb);
            mma_f16(c[0], a, bb[0], bb[1]);
            mma_f16(c[1], a, bb[2], bb[3]);
        }
#pragma unroll
        for (int t = 0; t < 2; ++t) {
            int col = s * 64 + w * 16 + t * 8 + 2 * tg;
            float bc0 = bo3[col], bc1 = bo3[col + 1];
            float2 e0 = *(const float2*)(inputs + (size_t)(row0 + r0) * FF + col);
            float2 e1 = *(const float2*)(inputs + (size_t)(row0 + r1) * FF + col);
            *(float2*)(out + (size_t)(row0 + r0) * FF + col) =
                make_float2(e0.x + c[t][0] + bc0, e0.y + c[t][1] + bc1);
            *(float2*)(out + (size_t)(row0 + r1) * FF + col) =
                make_float2(e1.x + c[t][2] + bc0, e1.y + c[t][3] + bc1);
        }
    }
}

// =====================================================================
extern "C" void kernel_launch(void* const* d_in, const int* in_sizes, int n_in,
                              void* d_out, int out_size)
{
    const float* inputs   = (const float*)d_in[0];
    const float* rel_type = (const float*)d_in[1];
    const float* W1  = (const float*)d_in[4];
    const float* b1  = (const float*)d_in[5];
    const float* W2  = (const float*)d_in[6];
    const float* b2  = (const float*)d_in[7];
    const float* Wo1 = (const float*)d_in[8];
    const float* bo1 = (const float*)d_in[9];
    const float* Wo2 = (const float*)d_in[10];
    const float* bo2 = (const float*)d_in[11];
    const float* Wo3 = (const float*)d_in[12];
    const float* bo3 = (const float*)d_in[13];
    float* out = (float*)d_out;

    float *agg, *hbp;
    uint16_t* simg;
    unsigned char *w1r, *w1s, *w2i, *wo1i, *wo2i, *wo3i;
    uint32_t *xhi, *xlo;
    cudaGetSymbolAddress((void**)&agg, g_agg);
    cudaGetSymbolAddress((void**)&hbp, g_hb);
    cudaGetSymbolAddress((void**)&simg, g_simg);
    cudaGetSymbolAddress((void**)&w1r, g_w1r);
    cudaGetSymbolAddress((void**)&w1s, g_w1s);
    cudaGetSymbolAddress((void**)&w2i, g_w2img);
    cudaGetSymbolAddress((void**)&wo1i, g_wo1);
    cudaGetSymbolAddress((void**)&wo2i, g_wo2);
    cudaGetSymbolAddress((void**)&wo3i, g_wo3);
    cudaGetSymbolAddress((void**)&xhi, g_ximg_hi);
    cudaGetSymbolAddress((void**)&xlo, g_ximg_lo);

    cudaFuncSetAttribute(edge_kernel, cudaFuncAttributeMaxDynamicSharedMemorySize, SE_TOTAL);
    cudaFuncSetAttribute(ns_kernel, cudaFuncAttributeMaxDynamicSharedMemorySize, NS_TOTAL);
    cudaFuncSetAttribute(out_tc_kernel, cudaFuncAttributeMaxDynamicSharedMemorySize, OT_TOTAL);

    prep_all_kernel<<<1216, 256>>>(inputs, W1, W2, Wo1, Wo2, Wo3,
                                   xhi, xlo, w1r, w1s, w2i, wo1i, wo2i, wo3i);
    ns_kernel<<<dim3(KK, BB, 4), 256, NS_TOTAL>>>(xhi, xlo, w1r, w1s, b1, hbp, simg);
    edge_kernel<<<dim3(NN / 2, BB), 256, SE_TOTAL>>>(rel_type, w2i, simg, hbp, b2, agg);
    out_tc_kernel<<<BB * NN / 16, 128, OT_TOTAL>>>(inputs, agg, wo1i, wo2i, wo3i,
                                                   bo1, bo2, bo3, out);
}

// round 15
// speedup vs baseline: 4.1918x; 1.0079x over previous
#include <cuda_runtime.h>
#include <cuda_bf16.h>
#include <cuda_fp16.h>
#include <cstdint>

#define BB 32
#define NN 64
#define FF 128
#define KK 4
#define EE 4032

// ---------------- static device scratch (no allocations) ----------------
__device__ __align__(16) unsigned char g_w1r[KK * 2 * 256 * 272];
__device__ __align__(16) unsigned char g_w1s[KK * 2 * 256 * 272];
__device__ __align__(16) unsigned char g_w2img[KK * 256 * 528];
__device__ __align__(16) unsigned char g_wo1[256 * 784];
__device__ __align__(16) unsigned char g_wo2[256 * 528];
__device__ __align__(16) unsigned char g_wo3[128 * 528];
__device__ __align__(16) uint32_t g_ximg_hi[BB * NN * 64];
__device__ __align__(16) uint32_t g_ximg_lo[BB * NN * 64];
__device__ __align__(16) float    g_hb[KK * BB * NN * 256];
__device__ __align__(16) uint16_t g_simg[KK * BB * NN * 256];
__device__ float g_agg[2 * BB * NN * 256];   // two k-partials (4 MB)

// ---------------- helpers ----------------
__device__ __forceinline__ uint32_t smem_u32(const void* p) {
    uint32_t a;
    asm("{ .reg .u64 t; cvta.to.shared.u64 t, %1; cvt.u32.u64 %0, t; }" : "=r"(a) : "l"(p));
    return a;
}
__device__ __forceinline__ void split2(float2 v, uint32_t& hi, uint32_t& lo) {  // bf16
    __nv_bfloat162 h2 = __float22bfloat162_rn(v);
    float2 r = make_float2(v.x - __bfloat162float(h2.x), v.y - __bfloat162float(h2.y));
    __nv_bfloat162 l2 = __float22bfloat162_rn(r);
    hi = reinterpret_cast<uint32_t&>(h2);
    lo = reinterpret_cast<uint32_t&>(l2);
}
__device__ __forceinline__ uint32_t h2pack(float a, float b) {
    __half2 h = __float22half2_rn(make_float2(a, b));
    return reinterpret_cast<uint32_t&>(h);
}
__device__ __forceinline__ void ldm4(uint32_t addr, uint32_t r[4]) {
    asm volatile("ldmatrix.sync.aligned.m8n8.x4.shared.b16 {%0,%1,%2,%3}, [%4];"
                 : "=r"(r[0]), "=r"(r[1]), "=r"(r[2]), "=r"(r[3]) : "r"(addr));
}
__device__ __forceinline__ void mma_bf16(float* c, const uint32_t* a, uint32_t b0, uint32_t b1) {
    asm volatile(
        "mma.sync.aligned.m16n8k16.row.col.f32.bf16.bf16.f32 "
        "{%0,%1,%2,%3}, {%4,%5,%6,%7}, {%8,%9}, {%0,%1,%2,%3};"
        : "+f"(c[0]), "+f"(c[1]), "+f"(c[2]), "+f"(c[3])
        : "r"(a[0]), "r"(a[1]), "r"(a[2]), "r"(a[3]), "r"(b0), "r"(b1));
}
__device__ __forceinline__ void mma_f16(float* c, const uint32_t* a, uint32_t b0, uint32_t b1) {
    asm volatile(
        "mma.sync.aligned.m16n8k16.row.col.f32.f16.f16.f32 "
        "{%0,%1,%2,%3}, {%4,%5,%6,%7}, {%8,%9}, {%0,%1,%2,%3};"
        : "+f"(c[0]), "+f"(c[1]), "+f"(c[2]), "+f"(c[3])
        : "r"(a[0]), "r"(a[1]), "r"(a[2]), "r"(a[3]), "r"(b0), "r"(b1));
}
__device__ __forceinline__ void cpa16(uint32_t dst, const void* src) {
    asm volatile("cp.async.cg.shared.global [%0], [%1], 16;" :: "r"(dst), "l"(src));
}
#define CP_COMMIT() asm volatile("cp.async.commit_group;" ::: "memory")
#define CP_WAIT0()  asm volatile("cp.async.wait_group 0;" ::: "memory")
#define CP_WAIT1()  asm volatile("cp.async.wait_group 1;" ::: "memory")

// =====================================================================
// prep_all_kernel (unchanged)
// =====================================================================
__device__ __forceinline__ void prep_w_body(const float* Wk, int koff, int f0, int nn0,
                                            int kt, unsigned char* img, int rstride,
                                            float ts[32][33], int tid)
{
#pragma unroll
    for (int p = 0; p < 4; ++p) {
        int fr = (tid >> 5) + p * 8, nl = tid & 31;
        ts[fr][nl] = Wk[(size_t)(koff + f0 + fr) * 256 + nn0 + nl];
    }
    __syncthreads();
#pragma unroll
    for (int p = 0; p < 2; ++p) {
        int idx = tid + p * 256;
        int nr = idx >> 4, wp = idx & 15;
        uint32_t hi, lo;
        split2(make_float2(ts[2 * wp][nr], ts[2 * wp + 1][nr]), hi, lo);
        size_t rb = (size_t)(nn0 + nr) * rstride + (f0 + 2 * wp) * 2;
        *(uint32_t*)(img + (size_t)(kt * 2 + 0) * 256 * rstride + rb) = hi;
        *(uint32_t*)(img + (size_t)(kt * 2 + 1) * 256 * rstride + rb) = lo;
    }
}
__device__ __forceinline__ void prep_h_body(const float* W, int Ncols, int f0, int nn0,
                                            unsigned char* img, int rstride,
                                            float ts[32][33], int tid)
{
#pragma unroll
    for (int p = 0; p < 4; ++p) {
        int fr = (tid >> 5) + p * 8, nl = tid & 31;
        ts[fr][nl] = W[(size_t)(f0 + fr) * Ncols + nn0 + nl];
    }
    __syncthreads();
#pragma unroll
    for (int p = 0; p < 2; ++p) {
        int idx = tid + p * 256;
        int nr = idx >> 4, wp = idx & 15;
        *(uint32_t*)(img + (size_t)(nn0 + nr) * rstride + (f0 + 2 * wp) * 2) =
            h2pack(ts[2 * wp][nr], ts[2 * wp + 1][nr]);
    }
}

__global__ void __launch_bounds__(256)
prep_all_kernel(const float* __restrict__ inputs,
                const float* __restrict__ W1, const float* __restrict__ W2,
                const float* __restrict__ Wo1, const float* __restrict__ Wo2,
                const float* __restrict__ Wo3,
                uint32_t* __restrict__ xhi, uint32_t* __restrict__ xlo,
                unsigned char* __restrict__ w1r, unsigned char* __restrict__ w1s,
                unsigned char* __restrict__ w2i,
                unsigned char* __restrict__ wo1i, unsigned char* __restrict__ wo2i,
                unsigned char* __restrict__ wo3i)
{
    __shared__ float ts[32][33];
    const int bid = blockIdx.x, tid = threadIdx.x;

    if (bid < 512) {
        int idx = bid * 256 + tid;
        float2 v = ((const float2*)inputs)[idx];
        uint32_t hi, lo;
        split2(v, hi, lo);
        xhi[idx] = hi;
        xlo[idx] = lo;
    } else if (bid < 640) {
        int b2 = bid - 512;
        prep_w_body(W1 + (size_t)(b2 >> 5) * 65536, 0, (b2 & 3) * 32,
                    ((b2 >> 2) & 7) * 32, b2 >> 5, w1r, 272, ts, tid);
    } else if (bid < 768) {
        int b2 = bid - 640;
        prep_w_body(W1 + (size_t)(b2 >> 5) * 65536, 128, (b2 & 3) * 32,
                    ((b2 >> 2) & 7) * 32, b2 >> 5, w1s, 272, ts, tid);
    } else if (bid < 1024) {
        int b3 = bid - 768;
        int f0 = (b3 & 7) * 32, nn0 = ((b3 >> 3) & 7) * 32, kt = b3 >> 6;
        prep_h_body(W2 + (size_t)kt * 65536, 256, f0, nn0,
                    w2i + (size_t)kt * 256 * 528, 528, ts, tid);
    } else if (bid < 1120) {
        int b4 = bid - 1024;
        prep_h_body(Wo1, 256, (b4 % 12) * 32, (b4 / 12) * 32, wo1i, 784, ts, tid);
    } else if (bid < 1184) {
        int b5 = bid - 1120;
        prep_h_body(Wo2, 256, (b5 & 7) * 32, (b5 >> 3) * 32, wo2i, 528, ts, tid);
    } else {
        int b6 = bid - 1184;
        prep_h_body(Wo3, 128, (b6 & 7) * 32, (b6 >> 3) * 32, wo3i, 528, ts, tid);
    }
}

// =====================================================================
// ns_kernel (unchanged)
// =====================================================================
#define NS_XHI 0
#define NS_XLO 17408
#define NS_W   34816
#define NS_B1  69632
#define NS_TOTAL 70656

__global__ void __launch_bounds__(256)
ns_kernel(const uint32_t* __restrict__ xhi, const uint32_t* __restrict__ xlo,
          const unsigned char* __restrict__ w1r, const unsigned char* __restrict__ w1s,
          const float* __restrict__ b1, float* __restrict__ hb, uint16_t* __restrict__ simg)
{
    extern __shared__ char smem[];
    const uint32_t sb = smem_u32(smem);
    const int tid = threadIdx.x, lane = tid & 31, w = tid >> 5;
    const int k = blockIdx.x, b = blockIdx.y;
    const int half = blockIdx.z >> 1, s0 = (blockIdx.z & 1) * 2;

    for (int t = tid; t < 1024; t += 256) {
        int row = t >> 4, sgi = t & 15;
        size_t so = (size_t)(b * 64 + row) * 64 + sgi * 4;
        cpa16(sb + NS_XHI + row * 272 + sgi * 16, xhi + so);
        cpa16(sb + NS_XLO + row * 272 + sgi * 16, xlo + so);
    }
    CP_COMMIT();
    if (tid < 64) ((float4*)(smem + NS_B1))[tid] = ((const float4*)(b1 + k * 256))[tid];

    const int g = lane >> 2, tg = lane & 3;
    const int arow = lane & 15;
    const uint32_t aoff = (uint32_t)((lane >> 4) << 4);
    const int brow = (lane & 7) + ((lane >> 4) << 3);
    const uint32_t boff = (uint32_t)((lane & 8) << 1);
    const int wm = w & 3, wn = w >> 2;
    const int m0 = wm * 16;
    const float* b1s = (const float*)(smem + NS_B1);
    const unsigned char* img = half ? w1s : w1r;
    float* outh = hb + ((size_t)k * BB + b) * 64 * 256;
    uint32_t* outs = (uint32_t*)simg + ((size_t)k * BB + b) * 64 * 128;

#pragma unroll 1
    for (int si = 0; si < 2; ++si) {
        int s = s0 + si;
        for (int t = tid; t < 2176; t += 256) {
            int im = t >= 1088;
            uint32_t off = (uint32_t)(t - im * 1088) * 16;
            cpa16(sb + NS_W + (im ? 17408 : 0) + off,
                  img + (size_t)((k * 2 + im) * 256 + s * 64) * 272 + off);
        }
        CP_COMMIT(); CP_WAIT0();
        __syncthreads();
        float c[4][4] = {};
#pragma unroll
        for (int sp = 0; sp < 3; ++sp) {
            uint32_t Ab = sb + (sp == 2 ? NS_XLO : NS_XHI) + (m0 + arow) * 272 + aoff;
            uint32_t Bb = sb + NS_W + (sp == 1 ? 17408u : 0u) + (wn * 32 + brow) * 272 + boff;
#pragma unroll
            for (int ks = 0; ks < 8; ++ks) {
                uint32_t a[4], b0[4], b1f[4];
                ldm4(Ab + ks * 32, a);
                ldm4(Bb + ks * 32, b0);
                ldm4(Bb + 16 * 272 + ks * 32, b1f);
                mma_bf16(c[0], a, b0[0], b0[1]);
                mma_bf16(c[1], a, b0[2], b0[3]);
                mma_bf16(c[2], a, b1f[0], b1f[1]);
                mma_bf16(c[3], a, b1f[2], b1f[3]);
            }
        }
        int r0 = m0 + g, r1 = r0 + 8;
        int cn = s * 64 + wn * 32;
        if (half == 0) {
#pragma unroll
            for (int t = 0; t < 4; ++t) {
                int col = cn + t * 8 + 2 * tg;
                outh[(size_t)r0 * 256 + col]     = c[t][0] + b1s[col];
                outh[(size_t)r0 * 256 + col + 1] = c[t][1] + b1s[col + 1];
                outh[(size_t)r1 * 256 + col]     = c[t][2] + b1s[col];
                outh[(size_t)r1 * 256 + col + 1] = c[t][3] + b1s[col + 1];
            }
        } else {
#pragma unroll
            for (int t = 0; t < 4; ++t) {
                int col = cn + t * 8 + 2 * tg;
                outs[(size_t)r0 * 128 + (col >> 1)] = h2pack(c[t][0], c[t][1]);
                outs[(size_t)r1 * 128 + (col >> 1)] = h2pack(c[t][2], c[t][3]);
            }
        }
        __syncthreads();
    }
}

// ---------------- SMEM map (bytes) for edge kernel ----------------
#define SE_S    0         // 64 x 528 (fp16) = 33792 (single buffer)
#define SE_W2   33792     // 2 x 33792 (64-col slabs) -> 101376
#define SE_HBS  101376    // 2048 -> 103424
#define SE_B2S  103424    // 1024 -> 104448
#define SE_RTS  104448    // 2048 -> 106496
#define SE_AGG  106496    // 8192 -> 114688
#define SE_TOTAL 114688

// =====================================================================
// Edge kernel: block = (2 nodes, batch, k-pair), 256 threads, 2 blocks/SM.
// Each block processes k in {2z, 2z+1}; agg written to per-z partial buffer.
// =====================================================================
__global__ void __launch_bounds__(256, 2)
edge_kernel(const float* __restrict__ rel_type,
            const unsigned char* __restrict__ w2img,
            const uint16_t* __restrict__ simg,
            const float* __restrict__ hb,
            const float* __restrict__ b2,
            float* __restrict__ agg)
{
    extern __shared__ char smem[];
    const uint32_t sb = smem_u32(smem);
    const int tid = threadIdx.x;
    const int lane = tid & 31, w = tid >> 5;
    const int n0 = blockIdx.x * 2, b = blockIdx.y;
    const int kbase = blockIdx.z * 2;

    // prologue group: S(kbase) + W2(kbase, slab0)
    {
        const unsigned char* sk = (const unsigned char*)simg +
                                  ((size_t)kbase * BB + b) * 64 * 512;
        for (int t = tid; t < 2048; t += 256) {
            int row = t >> 5, ch = t & 31;
            cpa16(sb + SE_S + row * 528 + ch * 16, sk + (size_t)row * 512 + ch * 16);
        }
        for (int t = tid; t < 2112; t += 256)
            cpa16(sb + SE_W2 + t * 16, w2img + (size_t)(kbase * 256) * 528 + t * 16);
        CP_COMMIT();
    }

    if (tid < 128) {
        int node = n0 + (tid >> 6), le = tid & 63;
        float4 v = make_float4(0.f, 0.f, 0.f, 0.f);
        if (le < 63) v = *(const float4*)(rel_type + ((size_t)b * EE + node * 63 + le) * KK);
        *(float4*)(smem + SE_RTS + tid * 16) = v;
    }
    for (int i = tid; i < 2048; i += 256) ((float*)(smem + SE_AGG))[i] = 0.f;

    const int g = lane >> 2, tg = lane & 3;
    const int brow = (lane & 7) + ((lane >> 4) << 3);
    const uint32_t boff = (uint32_t)((lane & 8) << 1);
    const int m0 = w * 16;
    const int nodeg = n0 + (w >> 2);
    const float* rts = (const float*)(smem + SE_RTS);
    const float* b2s = (const float*)(smem + SE_B2S);
    float* aggS = (float*)(smem + SE_AGG);

    const int rw0 = m0 + g, rw1 = rw0 + 8;
    const int le0 = rw0 & 63, le1 = rw1 & 63;
    const float msk0 = (le0 != 63) ? 1.f : 0.f;
    const float msk1 = (le1 != 63) ? 1.f : 0.f;
    const int j0 = (le0 != 63) ? (le0 + (le0 >= nodeg)) : 0;
    const int j1 = (le1 != 63) ? (le1 + (le1 >= nodeg)) : 0;

    uint32_t Ha[64];

#pragma unroll 1
    for (int ki = 0; ki < 2; ++ki) {
        const int k = kbase + ki;
        {
            const float* hbk = hb + (((size_t)k * BB + b) * 64 + n0) * 256;
            if (tid < 128) *(float4*)(smem + SE_HBS + tid * 16) = ((const float4*)hbk)[tid];
            else if (tid < 192)
                ((float4*)(smem + SE_B2S))[tid - 128] = ((const float4*)(b2 + k * 256))[tid - 128];
        }
        if (ki == 0) CP_WAIT0();   // S(kbase)+slab0; S(kbase+1) waited at prior s==3
        __syncthreads();

        // ---- H fragments: relu(hbase + S), fp16 ----
        {
            const __half* S0 = (const __half*)(smem + SE_S) + j0 * 264;
            const __half* S1 = (const __half*)(smem + SE_S) + j1 * 264;
            const float* hbs = (const float*)(smem + SE_HBS) + (w >> 2) * 256;
#pragma unroll
            for (int ks = 0; ks < 16; ++ks) {
                int c = ks * 16 + 2 * tg;
                float2 h0 = *(const float2*)(hbs + c);
                float2 h8 = *(const float2*)(hbs + c + 8);
                __half2 a0 = *(const __half2*)(S0 + c);
                __half2 a8 = *(const __half2*)(S0 + c + 8);
                __half2 bq0 = *(const __half2*)(S1 + c);
                __half2 bq8 = *(const __half2*)(S1 + c + 8);
                Ha[ks*4+0] = h2pack(msk0 * fmaxf(h0.x + __low2float(a0), 0.f),
                                    msk0 * fmaxf(h0.y + __high2float(a0), 0.f));
                Ha[ks*4+1] = h2pack(msk1 * fmaxf(h0.x + __low2float(bq0), 0.f),
                                    msk1 * fmaxf(h0.y + __high2float(bq0), 0.f));
                Ha[ks*4+2] = h2pack(msk0 * fmaxf(h8.x + __low2float(a8), 0.f),
                                    msk0 * fmaxf(h8.y + __high2float(a8), 0.f));
                Ha[ks*4+3] = h2pack(msk1 * fmaxf(h8.x + __low2float(bq8), 0.f),
                                    msk1 * fmaxf(h8.y + __high2float(bq8), 0.f));
            }
        }

        const float wr0 = rts[rw0 * 4 + k], wr1 = rts[rw1 * 4 + k];
#pragma unroll 1
        for (int s = 0; s < 4; ++s) {
            const int gs = ki * 4 + s;
            CP_WAIT0();        // slab gs (and, at s==3, S(k+1)) resident
            __syncthreads();
            if (gs < 7) {
                const int nk = kbase + ((gs + 1) >> 2), nslab = (gs + 1) & 3;
                uint32_t wb = SE_W2 + (uint32_t)(((gs + 1) & 1) * 33792);
                for (int t = tid; t < 2112; t += 256)
                    cpa16(sb + wb + t * 16,
                          w2img + (size_t)(nk * 256 + nslab * 64) * 528 + t * 16);
                if (s == 2 && ki == 0) {   // S(kbase+1) rides in this group
                    const unsigned char* sk = (const unsigned char*)simg +
                                              ((size_t)(k + 1) * BB + b) * 64 * 512;
                    for (int t = tid; t < 2048; t += 256) {
                        int row = t >> 5, ch = t & 31;
                        cpa16(sb + SE_S + row * 528 + ch * 16,
                              sk + (size_t)row * 512 + ch * 16);
                    }
                }
                CP_COMMIT();
            }
            const uint32_t wbase = sb + SE_W2 + (uint32_t)((s & 1) * 33792);
#pragma unroll
            for (int h = 0; h < 2; ++h) {
                const uint32_t wbs = wbase + (h * 32 + brow) * 528 + boff;
                float c[4][4] = {};
#pragma unroll
                for (int ks = 0; ks < 16; ++ks) {
                    uint32_t b0[4], b1f[4];
                    ldm4(wbs + ks * 32, b0);
                    ldm4(wbs + 16 * 528 + ks * 32, b1f);
                    const uint32_t* a = Ha + ks * 4;
                    mma_f16(c[0], a, b0[0], b0[1]);
                    mma_f16(c[1], a, b0[2], b0[3]);
                    mma_f16(c[2], a, b1f[0], b1f[1]);
                    mma_f16(c[3], a, b1f[2], b1f[3]);
                }
                float p0[4], p1[4];
#pragma unroll
                for (int t = 0; t < 4; ++t) {
                    int col = s * 64 + h * 32 + t * 8 + 2 * tg;
                    float bc0 = b2s[col], bc1 = b2s[col + 1];
                    p0[t] = wr0 * fmaxf(c[t][0] + bc0, 0.f) + wr1 * fmaxf(c[t][2] + bc0, 0.f);
                    p1[t] = wr0 * fmaxf(c[t][1] + bc1, 0.f) + wr1 * fmaxf(c[t][3] + bc1, 0.f);
                }
#pragma unroll
                for (int off = 4; off <= 16; off <<= 1)
#pragma unroll
                    for (int t = 0; t < 4; ++t) {
                        p0[t] += __shfl_xor_sync(0xffffffff, p0[t], off);
                        p1[t] += __shfl_xor_sync(0xffffffff, p1[t], off);
                    }
                if (g == 0) {
#pragma unroll
                    for (int t = 0; t < 4; ++t) {
                        int col = s * 64 + h * 32 + t * 8 + 2 * tg;
                        aggS[w * 256 + col]     += p0[t];
                        aggS[w * 256 + col + 1] += p1[t];
                    }
                }
            }
        }
    }

    __syncthreads();
    {
        float* aggz = agg + (size_t)blockIdx.z * BB * NN * 256;
        for (int t = tid; t < 512; t += 256) {
            int ni = t >> 8, m = t & 255;
            aggz[((size_t)b * NN + n0 + ni) * 256 + m] =
                aggS[(4 * ni + 0) * 256 + m] + aggS[(4 * ni + 1) * 256 + m] +
                aggS[(4 * ni + 2) * 256 + m] + aggS[(4 * ni + 3) * 256 + m];
        }
    }
}

// =====================================================================
// Output MLP, tensor-core fp16: 16 rows/block, grid 128, double-buffered W
// (R13 configuration — measured 16.6 us). Sums the two agg partials on load.
// =====================================================================
#define OT_A0 0
#define OT_A1 12544
#define OT_W  20992
#define OT_TOTAL 121344

__global__ void __launch_bounds__(128, 1)
out_tc_kernel(const float* __restrict__ inputs, const float* __restrict__ agg,
              const unsigned char* __restrict__ wo1, const unsigned char* __restrict__ wo2,
              const unsigned char* __restrict__ wo3,
              const float* __restrict__ bo1, const float* __restrict__ bo2,
              const float* __restrict__ bo3, float* __restrict__ out)
{
    extern __shared__ char smem[];
    const uint32_t sb = smem_u32(smem);
    const int tid = threadIdx.x, lane = tid & 31, w = tid >> 5;
    const int row0 = blockIdx.x * 16;

    const int g = lane >> 2, tg = lane & 3;
    const int arow = lane & 15;
    const uint32_t aoff = (uint32_t)((lane >> 4) << 4);
    const int brow = (lane & 7) + ((lane >> 4) << 3);
    const uint32_t boff = (uint32_t)((lane & 8) << 1);
    const int r0 = g, r1 = g + 8;

    const float* agg1 = agg + (size_t)BB * NN * 256;
    for (int idx = tid; idx < 16 * 192; idx += 128) {
        int r = idx / 192, pc = idx % 192;
        float2 v;
        if (pc < 64) {
            v = *(const float2*)(inputs + (size_t)(row0 + r) * FF + pc * 2);
        } else {
            size_t o = (size_t)(row0 + r) * 256 + (pc - 64) * 2;
            float2 v0 = *(const float2*)(agg + o);
            float2 v1 = *(const float2*)(agg1 + o);
            v = make_float2(v0.x + v1.x, v0.y + v1.y);
        }
        *(uint32_t*)(smem + OT_A0 + r * 784 + pc * 4) = h2pack(v.x, v.y);
    }
    for (int t = tid; t < 3136; t += 128)
        cpa16(sb + OT_W + t * 16, wo1 + (size_t)t * 16);
    CP_COMMIT();
    __syncthreads();

    // ---- layer 1: K=384, N=256 (4 slabs), relu -> A1 ----
#pragma unroll 1
    for (int s = 0; s < 4; ++s) {
        CP_WAIT0();
        __syncthreads();
        if (s < 3) {
            uint32_t wb = OT_W + (uint32_t)(((s + 1) & 1) * 50176);
            for (int t = tid; t < 3136; t += 128)
                cpa16(sb + wb + t * 16, wo1 + (size_t)((s + 1) * 64) * 784 + t * 16);
            CP_COMMIT();
        }
        const uint32_t wbs = sb + OT_W + (uint32_t)((s & 1) * 50176) + (w * 16 + brow) * 784 + boff;
        const uint32_t Ab = sb + OT_A0 + arow * 784 + aoff;
        float c[2][4] = {};
#pragma unroll
        for (int ks = 0; ks < 24; ++ks) {
            uint32_t a[4], bb[4];
            ldm4(Ab + ks * 32, a);
            ldm4(wbs + ks * 32, bb);
            mma_f16(c[0], a, bb[0], bb[1]);
            mma_f16(c[1], a, bb[2], bb[3]);
        }
#pragma unroll
        for (int t = 0; t < 2; ++t) {
            int col = s * 64 + w * 16 + t * 8 + 2 * tg;
            float bc0 = bo1[col], bc1 = bo1[col + 1];
            *(uint32_t*)(smem + OT_A1 + r0 * 528 + col * 2) =
                h2pack(fmaxf(c[t][0] + bc0, 0.f), fmaxf(c[t][1] + bc1, 0.f));
            *(uint32_t*)(smem + OT_A1 + r1 * 528 + col * 2) =
                h2pack(fmaxf(c[t][2] + bc0, 0.f), fmaxf(c[t][3] + bc1, 0.f));
        }
    }
    __syncthreads();
    for (int t = tid; t < 2112; t += 128)
        cpa16(sb + OT_W + t * 16, wo2 + (size_t)t * 16);
    CP_COMMIT();

    // ---- layer 2: K=256, N=256, relu -> A0 (stride 528) ----
#pragma unroll 1
    for (int s = 0; s < 4; ++s) {
        CP_WAIT0();
        __syncthreads();
        if (s < 3) {
            uint32_t wb = OT_W + (uint32_t)(((s + 1) & 1) * 50176);
            for (int t = tid; t < 2112; t += 128)
                cpa16(sb + wb + t * 16, wo2 + (size_t)((s + 1) * 64) * 528 + t * 16);
            CP_COMMIT();
        }
        const uint32_t wbs = sb + OT_W + (uint32_t)((s & 1) * 50176) + (w * 16 + brow) * 528 + boff;
        const uint32_t Ab = sb + OT_A1 + arow * 528 + aoff;
        float c[2][4] = {};
#pragma unroll
        for (int ks = 0; ks < 16; ++ks) {
            uint32_t a[4], bb[4];
            ldm4(Ab + ks * 32, a);
            ldm4(wbs + ks * 32, bb);
            mma_f16(c[0], a, bb[0], bb[1]);
            mma_f16(c[1], a, bb[2], bb[3]);
        }
#pragma unroll
        for (int t = 0; t < 2; ++t) {
            int col = s * 64 + w * 16 + t * 8 + 2 * tg;
            float bc0 = bo2[col], bc1 = bo2[col + 1];
            *(uint32_t*)(smem + OT_A0 + r0 * 528 + col * 2) =
                h2pack(fmaxf(c[t][0] + bc0, 0.f), fmaxf(c[t][1] + bc1, 0.f));
            *(uint32_t*)(smem + OT_A0 + r1 * 528 + col * 2) =
                h2pack(fmaxf(c[t][2] + bc0, 0.f), fmaxf(c[t][3] + bc1, 0.f));
        }
    }
    __syncthreads();
    for (int t = tid; t < 2112; t += 128)
        cpa16(sb + OT_W + t * 16, wo3 + (size_t)t * 16);
    CP_COMMIT();

    // ---- layer 3: K=256, N=128 (2 slabs), + residual -> out ----
#pragma unroll 1
    for (int s = 0; s < 2; ++s) {
        CP_WAIT0();
        __syncthreads();
        if (s < 1) {
            uint32_t wb = OT_W + 50176u;
            for (int t = tid; t < 2112; t += 128)
                cpa16(sb + wb + t * 16, wo3 + (size_t)64 * 528 + t * 16);
            CP_COMMIT();
        }
        const uint32_t wbs = sb + OT_W + (uint32_t)((s & 1) * 50176) + (w * 16 + brow) * 528 + boff;
        const uint32_t Ab = sb + OT_A0 + arow * 528 + aoff;
        float c[2][4] = {};
#pragma unroll
        for (int ks = 0; ks < 16; ++ks) {
            uint32_t a[4], bb[4];
            ldm4(Ab + ks * 32, a);
            ldm4(wbs + ks * 32, bb);
            mma_f16(c[0], a, bb[0], bb[1]);
            mma_f16(c[1], a, bb[2], bb[3]);
        }
#pragma unroll
        for (int t = 0; t < 2; ++t) {
            int col = s * 64 + w * 16 + t * 8 + 2 * tg;
            float bc0 = bo3[col], bc1 = bo3[col + 1];
            float2 e0 = *(const float2*)(inputs + (size_t)(row0 + r0) * FF + col);
            float2 e1 = *(const float2*)(inputs + (size_t)(row0 + r1) * FF + col);
            *(float2*)(out + (size_t)(row0 + r0) * FF + col) =
                make_float2(e0.x + c[t][0] + bc0, e0.y + c[t][1] + bc1);
            *(float2*)(out + (size_t)(row0 + r1) * FF + col) =
                make_float2(e1.x + c[t][2] + bc0, e1.y + c[t][3] + bc1);
        }
    }
}

// =====================================================================
extern "C" void kernel_launch(void* const* d_in, const int* in_sizes, int n_in,
                              void* d_out, int out_size)
{
    const float* inputs   = (const float*)d_in[0];
    const float* rel_type = (const float*)d_in[1];
    const float* W1  = (const float*)d_in[4];
    const float* b1  = (const float*)d_in[5];
    const float* W2  = (const float*)d_in[6];
    const float* b2  = (const float*)d_in[7];
    const float* Wo1 = (const float*)d_in[8];
    const float* bo1 = (const float*)d_in[9];
    const float* Wo2 = (const float*)d_in[10];
    const float* bo2 = (const float*)d_in[11];
    const float* Wo3 = (const float*)d_in[12];
    const float* bo3 = (const float*)d_in[13];
    float* out = (float*)d_out;

    float *agg, *hbp;
    uint16_t* simg;
    unsigned char *w1r, *w1s, *w2i, *wo1i, *wo2i, *wo3i;
    uint32_t *xhi, *xlo;
    cudaGetSymbolAddress((void**)&agg, g_agg);
    cudaGetSymbolAddress((void**)&hbp, g_hb);
    cudaGetSymbolAddress((void**)&simg, g_simg);
    cudaGetSymbolAddress((void**)&w1r, g_w1r);
    cudaGetSymbolAddress((void**)&w1s, g_w1s);
    cudaGetSymbolAddress((void**)&w2i, g_w2img);
    cudaGetSymbolAddress((void**)&wo1i, g_wo1);
    cudaGetSymbolAddress((void**)&wo2i, g_wo2);
    cudaGetSymbolAddress((void**)&wo3i, g_wo3);
    cudaGetSymbolAddress((void**)&xhi, g_ximg_hi);
    cudaGetSymbolAddress((void**)&xlo, g_ximg_lo);

    cudaFuncSetAttribute(edge_kernel, cudaFuncAttributeMaxDynamicSharedMemorySize, SE_TOTAL);
    cudaFuncSetAttribute(ns_kernel, cudaFuncAttributeMaxDynamicSharedMemorySize, NS_TOTAL);
    cudaFuncSetAttribute(out_tc_kernel, cudaFuncAttributeMaxDynamicSharedMemorySize, OT_TOTAL);

    prep_all_kernel<<<1216, 256>>>(inputs, W1, W2, Wo1, Wo2, Wo3,
                                   xhi, xlo, w1r, w1s, w2i, wo1i, wo2i, wo3i);
    ns_kernel<<<dim3(KK, BB, 4), 256, NS_TOTAL>>>(xhi, xlo, w1r, w1s, b1, hbp, simg);
    edge_kernel<<<dim3(NN / 2, BB, 2), 256, SE_TOTAL>>>(rel_type, w2i, simg, hbp, b2, agg);
    out_tc_kernel<<<BB * NN / 16, 128, OT_TOTAL>>>(inputs, agg, wo1i, wo2i, wo3i,
                                                   bo1, bo2, bo3, out);
}